// round 7
// baseline (speedup 1.0000x reference)
#include <cuda_runtime.h>
#include <cuda_bf16.h>
#include <cstdint>

#define B      32
#define QLEN   32
#define DLEN   1024
#define EMB    300
#define CDIM   128
#define MD     (B*DLEN)   // 32768 doc rows
#define MQ     (B*QLEN)   // 1024 query rows

// Row layout: [0,32768) doc, [32768,32896) zero pad, [32896,33920) query, [33920,33924) pad
#define QROW0   32896
#define NROWS   33924
#define KPAD    320        // K padded (300 -> 320) = 10 chunks of 32 f32
#define NCAT    768        // 6 tap-groups x 128 channels
#define MTILES  264        // 256 doc tiles + 8 query tiles

// ---------------- device scratch (zero-initialized globals) ----------------
__device__ float g_Ehi[(size_t)NROWS * KPAD];     // tf32-rounded hi part (stored as f32)
__device__ float g_Elo[(size_t)NROWS * KPAD];     // tf32 residual
__device__ float g_Whi[NCAT * KPAD];
__device__ float g_Wlo[NCAT * KPAD];
__device__ float g_P[(size_t)NROWS * NCAT];       // partial conv outputs (pad rows stay 0)
__device__ float g_DENC[3ull * MD * CDIM];
__device__ float g_QENC[3ull * MQ * CDIM];
__device__ float g_LOGITS[B * 189];

__device__ __forceinline__ uint32_t smem_u32(const void* p) {
    uint32_t a;
    asm("{ .reg .u64 t; cvta.to.shared.u64 t, %1; cvt.u32.u64 %0, t; }" : "=r"(a) : "l"(p));
    return a;
}
__device__ __forceinline__ float f2tf32(float x) {
    uint32_t r;
    asm("cvt.rna.tf32.f32 %0, %1;" : "=r"(r) : "f"(x));
    return __uint_as_float(r);
}
__device__ __forceinline__ void ldmx4(uint32_t* r, uint32_t addr) {
    asm volatile("ldmatrix.sync.aligned.m8n8.x4.shared.b16 {%0,%1,%2,%3}, [%4];"
                 : "=r"(r[0]), "=r"(r[1]), "=r"(r[2]), "=r"(r[3]) : "r"(addr));
}
__device__ __forceinline__ void mma_tf32(float* c, const uint32_t* a, const uint32_t* b) {
    asm volatile("mma.sync.aligned.m16n8k8.row.col.f32.tf32.tf32.f32 "
                 "{%0,%1,%2,%3}, {%4,%5,%6,%7}, {%8,%9}, {%0,%1,%2,%3};"
                 : "+f"(c[0]), "+f"(c[1]), "+f"(c[2]), "+f"(c[3])
                 : "r"(a[0]), "r"(a[1]), "r"(a[2]), "r"(a[3]), "r"(b[0]), "r"(b[1]));
}
__device__ __forceinline__ void cp16(uint32_t dst, const void* src) {
    asm volatile("cp.async.cg.shared.global [%0], [%1], 16;" :: "r"(dst), "l"(src));
}
__device__ __forceinline__ void cp_commit() {
    asm volatile("cp.async.commit_group;" ::: "memory");
}
template <int N>
__device__ __forceinline__ void cp_wait() {
    asm volatile("cp.async.wait_group %0;" :: "n"(N) : "memory");
}

// ---------------- 1) gather embeddings -> padded tf32 hi/lo ----------------
__global__ void gather_kernel(const int* __restrict__ qids, const int* __restrict__ dids,
                              const float* __restrict__ emb) {
    int w = (blockIdx.x * blockDim.x + threadIdx.x) >> 5;
    int lane = threadIdx.x & 31;
    if (w >= MD + MQ) return;
    int id, drow;
    if (w < MD) { id = dids[w]; drow = w; }
    else        { id = qids[w - MD]; drow = QROW0 + (w - MD); }
    const float* src = emb + (size_t)id * EMB;
    float* dh = g_Ehi + (size_t)drow * KPAD;
    float* dl = g_Elo + (size_t)drow * KPAD;
    #pragma unroll
    for (int i = 0; i < 10; i++) {
        int c = lane + i * 32;
        float x = (c < EMB) ? src[c] : 0.f;
        float h = f2tf32(x);
        dh[c] = h;
        dl[c] = f2tf32(x - h);
    }
}

// ---------------- 2) Wcat (768 x 320) tf32 hi/lo ----------------
// group g: 0=(k1,t0) 1=(k2,t0) 2=(k2,t1) 3=(k3,t0) 4=(k3,t1) 5=(k3,t2)
__global__ void wcat_kernel(const float* __restrict__ w1, const float* __restrict__ w2,
                            const float* __restrict__ w3) {
    int idx = blockIdx.x * blockDim.x + threadIdx.x;
    if (idx >= NCAT * KPAD) return;
    int j = idx / KPAD, e = idx % KPAD;
    int g = j >> 7, c = j & 127;
    float v = 0.f;
    if (e < EMB) {
        if (g == 0)      v = w1[c * EMB + e];
        else if (g == 1) v = w2[(c * EMB + e) * 2 + 0];
        else if (g == 2) v = w2[(c * EMB + e) * 2 + 1];
        else             v = w3[(c * EMB + e) * 3 + (g - 3)];
    }
    float h = f2tf32(v);
    g_Whi[idx] = h;
    g_Wlo[idx] = f2tf32(v - h);
}

// ---------------- 3) TF32-split MMA GEMM: P[128 x 256] per CTA ----------------
// grid (3, 264): x = N pass (256 cols), y = M tile. 8 warps, warp tile 64x64.
// smem stage: [Ah 128x32][Al 128x32][Bh 256x32][Bl 256x32], f32, row stride 36 (144 B).
#define STRIDE_B  144
#define A_TILE_B  (128 * STRIDE_B)                 // 18432
#define B_TILE_B  (256 * STRIDE_B)                 // 36864
#define STAGE_B   (2 * A_TILE_B + 2 * B_TILE_B)    // 110592
#define SMEM_DYN  (2 * STAGE_B)                    // 221184

__global__ void __launch_bounds__(256, 1) conv_tf32_kernel() {
    extern __shared__ char sm[];
    const int mt = blockIdx.y, pass = blockIdx.x;
    const int mbase = (mt < 256) ? mt * 128 : QROW0 + (mt - 256) * 128;
    const int jbase = pass * 256;
    const int tid = threadIdx.x, wid = tid >> 5, lane = tid & 31;
    const int wm = wid & 1, wn = wid >> 1;     // warp tile: rows wm*64, cols wn*64

    const uint32_t smb = smem_u32(sm);

    // cp.async source bases
    const float* Ah_src = g_Ehi + (size_t)mbase * KPAD;
    const float* Al_src = g_Elo + (size_t)mbase * KPAD;
    const float* Bh_src = g_Whi + (size_t)jbase * KPAD;
    const float* Bl_src = g_Wlo + (size_t)jbase * KPAD;

    auto load_stage = [&](int s, int kc) {
        const uint32_t st = smb + s * STAGE_B;
        const int kof = kc * 32;
        // A tiles: 128 rows x 32 f32 -> 1024 16B chunks each (4 per thread)
        #pragma unroll
        for (int i = 0; i < 4; i++) {
            int q = tid + i * 256;
            int r = q >> 3, c = q & 7;
            uint32_t doff = (uint32_t)r * STRIDE_B + c * 16;
            const float* sa = Ah_src + (size_t)r * KPAD + kof + c * 4;
            const float* sl = Al_src + (size_t)r * KPAD + kof + c * 4;
            cp16(st + doff, sa);
            cp16(st + A_TILE_B + doff, sl);
        }
        // B tiles: 256 rows x 32 f32 -> 2048 chunks each (8 per thread)
        #pragma unroll
        for (int i = 0; i < 8; i++) {
            int q = tid + i * 256;
            int r = q >> 3, c = q & 7;
            uint32_t doff = (uint32_t)r * STRIDE_B + c * 16;
            const float* sh = Bh_src + (size_t)r * KPAD + kof + c * 4;
            const float* sl = Bl_src + (size_t)r * KPAD + kof + c * 4;
            cp16(st + 2 * A_TILE_B + doff, sh);
            cp16(st + 2 * A_TILE_B + B_TILE_B + doff, sl);
        }
        cp_commit();
    };

    float acc[4][8][4];
    #pragma unroll
    for (int i = 0; i < 4; i++)
        #pragma unroll
        for (int j = 0; j < 8; j++)
            #pragma unroll
            for (int k = 0; k < 4; k++) acc[i][j][k] = 0.f;

    // ldmatrix lane address components (fp32-as-b16 pairs trick)
    const int lg = lane >> 3, lj = lane & 7;
    const uint32_t a_off = (uint32_t)(lj + 8 * (lg & 1)) * STRIDE_B + (uint32_t)(lg >> 1) * 16;
    const uint32_t b_off = (uint32_t)(lj + 8 * (lg >> 1)) * STRIDE_B + (uint32_t)(lg & 1) * 16;

    load_stage(0, 0);

    for (int kc = 0; kc < 10; kc++) {
        const int s = kc & 1;
        if (kc + 1 < 10) {
            load_stage(s ^ 1, kc + 1);
            cp_wait<1>();
        } else {
            cp_wait<0>();
        }
        __syncthreads();

        const uint32_t Ah = smb + s * STAGE_B;
        const uint32_t Al = Ah + A_TILE_B;
        const uint32_t Bh = Ah + 2 * A_TILE_B;
        const uint32_t Bl = Bh + B_TILE_B;

        #pragma unroll
        for (int ks = 0; ks < 4; ks++) {
            const uint32_t kb = ks * 32;       // 8 f32 per k-step
            uint32_t bh[8][2], bl[8][2];
            #pragma unroll
            for (int h = 0; h < 4; h++) {
                uint32_t off = (uint32_t)(wn * 64 + h * 16) * STRIDE_B + kb + b_off;
                uint32_t r[4];
                ldmx4(r, Bh + off);
                bh[h * 2 + 0][0] = r[0]; bh[h * 2 + 0][1] = r[1];
                bh[h * 2 + 1][0] = r[2]; bh[h * 2 + 1][1] = r[3];
                ldmx4(r, Bl + off);
                bl[h * 2 + 0][0] = r[0]; bl[h * 2 + 0][1] = r[1];
                bl[h * 2 + 1][0] = r[2]; bl[h * 2 + 1][1] = r[3];
            }
            #pragma unroll
            for (int mf = 0; mf < 4; mf++) {
                uint32_t off = (uint32_t)(wm * 64 + mf * 16) * STRIDE_B + kb + a_off;
                uint32_t ah[4], al[4];
                ldmx4(ah, Ah + off);
                ldmx4(al, Al + off);
                #pragma unroll
                for (int nf = 0; nf < 8; nf++) {
                    mma_tf32(acc[mf][nf], ah, bh[nf]);
                    mma_tf32(acc[mf][nf], al, bh[nf]);
                    mma_tf32(acc[mf][nf], ah, bl[nf]);
                }
            }
        }
        __syncthreads();
    }

    // epilogue
    const int r0 = lane >> 2, c0 = (lane & 3) * 2;
    #pragma unroll
    for (int mf = 0; mf < 4; mf++) {
        int row = mbase + wm * 64 + mf * 16 + r0;
        #pragma unroll
        for (int nf = 0; nf < 8; nf++) {
            int col = jbase + wn * 64 + nf * 8 + c0;
            float* p = g_P + (size_t)row * NCAT + col;
            *(float2*)p                      = make_float2(acc[mf][nf][0], acc[mf][nf][1]);
            *(float2*)(p + (size_t)8 * NCAT) = make_float2(acc[mf][nf][2], acc[mf][nf][3]);
        }
    }
}

// ---------------- 4) combine taps + bias + relu + L2 normalize + mask ----------------
__global__ void combine_kernel(const float* __restrict__ b1, const float* __restrict__ b2,
                               const float* __restrict__ b3,
                               const float* __restrict__ qmask, const float* __restrict__ dmask) {
    int w = (blockIdx.x * blockDim.x + threadIdx.x) >> 5;
    int lane = threadIdx.x & 31;
    if (w >= (MD + MQ) * 3) return;
    int kidx = w % 3;
    int row  = w / 3;
    int prow; float* out; float mk;
    if (row < MD) { prow = row; out = g_DENC + ((size_t)kidx * MD + row) * CDIM; mk = dmask[row]; }
    else {
        int q = row - MD;
        prow = QROW0 + q;
        out = g_QENC + ((size_t)kidx * MQ + q) * CDIM;
        mk = qmask[q];
    }
    const float* bias = (kidx == 0) ? b1 : (kidx == 1 ? b2 : b3);
    const float* P0 = g_P + (size_t)prow * NCAT;
    int c = lane * 4;
    float4 v;
    if (kidx == 0) {
        v = *(const float4*)(P0 + c);
    } else if (kidx == 1) {
        float4 a = *(const float4*)(P0 + 128 + c);
        float4 b = *(const float4*)(P0 + NCAT + 256 + c);
        v = make_float4(a.x + b.x, a.y + b.y, a.z + b.z, a.w + b.w);
    } else {
        float4 a = *(const float4*)(P0 + 384 + c);
        float4 b = *(const float4*)(P0 + NCAT + 512 + c);
        float4 d = *(const float4*)(P0 + 2 * NCAT + 640 + c);
        v = make_float4(a.x + b.x + d.x, a.y + b.y + d.y, a.z + b.z + d.z, a.w + b.w + d.w);
    }
    float4 bv = *(const float4*)(bias + c);
    v.x = fmaxf(v.x + bv.x, 0.f);  v.y = fmaxf(v.y + bv.y, 0.f);
    v.z = fmaxf(v.z + bv.z, 0.f);  v.w = fmaxf(v.w + bv.w, 0.f);
    float ss = v.x * v.x + v.y * v.y + v.z * v.z + v.w * v.w;
    #pragma unroll
    for (int off = 16; off > 0; off >>= 1)
        ss += __shfl_xor_sync(0xffffffffu, ss, off);
    float sc = mk / (sqrtf(ss) + 1e-13f);
    v.x *= sc; v.y *= sc; v.z *= sc; v.w *= sc;
    *(float4*)(out + c) = v;
}

// ---------------- 5) matcher: sim GEMM + Gaussian-bin pooling ----------------
__device__ __forceinline__ void accum_bins(float* h, float s, float sel) {
    float d1 = s - 1.0f;
    if (fabsf(d1) < 0.012f)                       // else term < 5e-32, invisible vs 1e-10 clamp
        h[0] += sel * __expf(-500000.f * d1 * d1);
    float d0 = s - 0.95f;
    float g = sel * __expf(-50.f * d0 * d0);
    float t = __expf(-10.f * d0) * 0.60653065971f;
    #pragma unroll
    for (int j = 1; j <= 20; j++) {
        h[j] += g;
        g *= t;
        t *= 0.36787944117f;
    }
}

__global__ __launch_bounds__(256) void matcher_kernel(const float* __restrict__ qmasks) {
    const int b    = blockIdx.x;
    const int pair = blockIdx.y;
    const int qk   = pair / 3, dk = pair % 3;
    const float* Q = g_QENC + ((size_t)qk * MQ + b * QLEN) * CDIM;
    const float* D = g_DENC + ((size_t)dk * MD + b * DLEN) * CDIM;
    const int qlen_v = QLEN - qk;
    const int dlen_v = DLEN - dk;

    __shared__ float Qs[128][36];
    __shared__ float Ds[128][65];
    __shared__ float warp_out[8][21];

    const int tid = threadIdx.x;
    const int tq  = tid >> 5;
    const int td  = tid & 31;

    for (int i = tid; i < 32 * 32; i += 256) {
        int q = i >> 5, c4 = i & 31;
        float4 v = *(const float4*)(Q + (size_t)q * CDIM + c4 * 4);
        Qs[c4 * 4 + 0][q] = v.x;  Qs[c4 * 4 + 1][q] = v.y;
        Qs[c4 * 4 + 2][q] = v.z;  Qs[c4 * 4 + 3][q] = v.w;
    }

    float hist[4][21];
    #pragma unroll
    for (int qi = 0; qi < 4; qi++)
        #pragma unroll
        for (int j = 0; j < 21; j++) hist[qi][j] = 0.f;

    for (int dt = 0; dt < DLEN / 64; dt++) {
        __syncthreads();
        for (int i = tid; i < 64 * 32; i += 256) {
            int r = i >> 5, c4 = i & 31;
            float4 v = *(const float4*)(D + (size_t)(dt * 64 + r) * CDIM + c4 * 4);
            Ds[c4 * 4 + 0][r] = v.x;  Ds[c4 * 4 + 1][r] = v.y;
            Ds[c4 * 4 + 2][r] = v.z;  Ds[c4 * 4 + 3][r] = v.w;
        }
        __syncthreads();

        float s0[4] = {0.f, 0.f, 0.f, 0.f};
        float s1[4] = {0.f, 0.f, 0.f, 0.f};
        #pragma unroll 8
        for (int kk = 0; kk < 128; kk++) {
            float a0 = Ds[kk][td];
            float a1 = Ds[kk][td + 32];
            float4 bq = *(const float4*)&Qs[kk][tq * 4];
            s0[0] = fmaf(a0, bq.x, s0[0]);  s0[1] = fmaf(a0, bq.y, s0[1]);
            s0[2] = fmaf(a0, bq.z, s0[2]);  s0[3] = fmaf(a0, bq.w, s0[3]);
            s1[0] = fmaf(a1, bq.x, s1[0]);  s1[1] = fmaf(a1, bq.y, s1[1]);
            s1[2] = fmaf(a1, bq.z, s1[2]);  s1[3] = fmaf(a1, bq.w, s1[3]);
        }
        float sel0 = (dt * 64 + td      < dlen_v) ? 1.f : 0.f;
        float sel1 = (dt * 64 + td + 32 < dlen_v) ? 1.f : 0.f;
        #pragma unroll
        for (int qi = 0; qi < 4; qi++) {
            accum_bins(hist[qi], s0[qi], sel0);
            accum_bins(hist[qi], s1[qi], sel1);
        }
    }

    #pragma unroll
    for (int qi = 0; qi < 4; qi++)
        #pragma unroll
        for (int j = 0; j < 21; j++) {
            float v = hist[qi][j];
            #pragma unroll
            for (int off = 16; off > 0; off >>= 1)
                v += __shfl_down_sync(0xffffffffu, v, off);
            hist[qi][j] = v;
        }

    if (td == 0) {
        float part[21];
        #pragma unroll
        for (int j = 0; j < 21; j++) part[j] = 0.f;
        #pragma unroll
        for (int qi = 0; qi < 4; qi++) {
            int qrow = tq * 4 + qi;
            float w = (qrow < qlen_v) ? qmasks[b * QLEN + qrow] : 0.f;
            #pragma unroll
            for (int j = 0; j < 21; j++)
                part[j] += __logf(fmaxf(hist[qi][j], 1e-10f)) * 0.01f * w;
        }
        #pragma unroll
        for (int j = 0; j < 21; j++) warp_out[tq][j] = part[j];
    }
    __syncthreads();
    if (tid < 21) {
        float s = 0.f;
        #pragma unroll
        for (int w = 0; w < 8; w++) s += warp_out[w][tid];
        g_LOGITS[b * 189 + pair * 21 + tid] = s;
    }
}

// ---------------- 6) dense score + output ----------------
__global__ void score_kernel(const float* __restrict__ dw, const float* __restrict__ db,
                             float* __restrict__ out, int out_size) {
    __shared__ float red[256];
    int b = blockIdx.x, tid = threadIdx.x;
    float v = (tid < 189) ? g_LOGITS[b * 189 + tid] * dw[tid] : 0.f;
    red[tid] = v;
    __syncthreads();
    for (int s = 128; s > 0; s >>= 1) {
        if (tid < s) red[tid] += red[tid + s];
        __syncthreads();
    }
    float score = red[0] + db[0];
    if (out_size >= B + B * 189) {
        if (tid == 0) out[b] = score;
        if (tid < 189) out[B + b * 189 + tid] = g_LOGITS[b * 189 + tid];
    } else if (out_size == B * 189) {
        if (tid < 189) out[b * 189 + tid] = g_LOGITS[b * 189 + tid];
    } else {
        if (tid == 0 && b < out_size) out[b] = score;
    }
}

// ---------------- launch ----------------
extern "C" void kernel_launch(void* const* d_in, const int* in_sizes, int n_in,
                              void* d_out, int out_size) {
    const int*   qids   = (const int*)d_in[0];
    const float* qmask  = (const float*)d_in[1];
    const int*   dids   = (const int*)d_in[2];
    const float* dmask  = (const float*)d_in[3];
    const float* emb    = (const float*)d_in[4];
    const float* w1     = (const float*)d_in[5];
    const float* b1     = (const float*)d_in[6];
    const float* w2     = (const float*)d_in[7];
    const float* b2     = (const float*)d_in[8];
    const float* w3     = (const float*)d_in[9];
    const float* b3     = (const float*)d_in[10];
    const float* dw     = (const float*)d_in[11];
    const float* db     = (const float*)d_in[12];
    float* out = (float*)d_out;

    cudaFuncSetAttribute(conv_tf32_kernel, cudaFuncAttributeMaxDynamicSharedMemorySize, SMEM_DYN);

    gather_kernel<<<((MD + MQ) * 32 + 255) / 256, 256>>>(qids, dids, emb);
    wcat_kernel<<<(NCAT * KPAD + 255) / 256, 256>>>(w1, w2, w3);
    conv_tf32_kernel<<<dim3(3, MTILES), 256, SMEM_DYN>>>();
    combine_kernel<<<((MD + MQ) * 3 * 32 + 255) / 256, 256>>>(b1, b2, b3, qmask, dmask);
    matcher_kernel<<<dim3(B, 9), 256>>>(qmask);
    score_kernel<<<B, 256>>>(dw, db, out, out_size);
}

// round 8
// speedup vs baseline: 1.1229x; 1.1229x over previous
#include <cuda_runtime.h>
#include <cuda_bf16.h>
#include <cstdint>

#define B      32
#define QLEN   32
#define DLEN   1024
#define EMB    300
#define CDIM   128
#define MD     (B*DLEN)   // 32768 doc rows
#define MQ     (B*QLEN)   // 1024 query rows

// Row layout: [0,32768) doc, [32768,32896) zero pad, [32896,33920) query, [33920,33924) pad
#define QROW0   32896
#define NROWS   33924
#define KPAD    320        // K padded (300 -> 320) = 10 chunks of 32 f32
#define KC2     640        // corr K (two halves of 320)
#define NCAT    768        // 6 tap-groups x 128 channels
#define MTILES  264        // 256 doc tiles + 8 query tiles

// ---------------- device scratch (zero-initialized globals) ----------------
__device__ float         g_Ehi[(size_t)NROWS * KPAD];   // tf32-rounded hi (stored f32)
__device__ __nv_bfloat16 g_Ecorr[(size_t)NROWS * KC2];  // [Elo16 | Ehi16]
__device__ float         g_Whi[NCAT * KPAD];
__device__ __nv_bfloat16 g_Wcorr[NCAT * KC2];           // [Whi16 | Wlo16]
__device__ float g_P[(size_t)NROWS * NCAT];             // partial conv outputs
__device__ float g_DENC[3ull * MD * CDIM];
__device__ float g_QENC[3ull * MQ * CDIM];
__device__ float g_LOGITS[B * 189];

__device__ __forceinline__ uint32_t smem_u32(const void* p) {
    uint32_t a;
    asm("{ .reg .u64 t; cvta.to.shared.u64 t, %1; cvt.u32.u64 %0, t; }" : "=r"(a) : "l"(p));
    return a;
}
__device__ __forceinline__ float f2tf32(float x) {
    uint32_t r;
    asm("cvt.rna.tf32.f32 %0, %1;" : "=r"(r) : "f"(x));
    return __uint_as_float(r);
}
__device__ __forceinline__ void ldmx4(uint32_t* r, uint32_t addr) {
    asm volatile("ldmatrix.sync.aligned.m8n8.x4.shared.b16 {%0,%1,%2,%3}, [%4];"
                 : "=r"(r[0]), "=r"(r[1]), "=r"(r[2]), "=r"(r[3]) : "r"(addr));
}
__device__ __forceinline__ void mma_tf32(float* c, const uint32_t* a, const uint32_t* b) {
    asm volatile("mma.sync.aligned.m16n8k8.row.col.f32.tf32.tf32.f32 "
                 "{%0,%1,%2,%3}, {%4,%5,%6,%7}, {%8,%9}, {%0,%1,%2,%3};"
                 : "+f"(c[0]), "+f"(c[1]), "+f"(c[2]), "+f"(c[3])
                 : "r"(a[0]), "r"(a[1]), "r"(a[2]), "r"(a[3]), "r"(b[0]), "r"(b[1]));
}
__device__ __forceinline__ void mma_bf16(float* c, const uint32_t* a, const uint32_t* b) {
    asm volatile("mma.sync.aligned.m16n8k16.row.col.f32.bf16.bf16.f32 "
                 "{%0,%1,%2,%3}, {%4,%5,%6,%7}, {%8,%9}, {%0,%1,%2,%3};"
                 : "+f"(c[0]), "+f"(c[1]), "+f"(c[2]), "+f"(c[3])
                 : "r"(a[0]), "r"(a[1]), "r"(a[2]), "r"(a[3]), "r"(b[0]), "r"(b[1]));
}
__device__ __forceinline__ void cp16(uint32_t dst, const void* src) {
    asm volatile("cp.async.cg.shared.global [%0], [%1], 16;" :: "r"(dst), "l"(src));
}
__device__ __forceinline__ void cp_commit() {
    asm volatile("cp.async.commit_group;" ::: "memory");
}
template <int N>
__device__ __forceinline__ void cp_wait() {
    asm volatile("cp.async.wait_group %0;" :: "n"(N) : "memory");
}

// ---------------- 1) gather embeddings -> Ehi f32 + Ecorr bf16 ----------------
__global__ void gather_kernel(const int* __restrict__ qids, const int* __restrict__ dids,
                              const float* __restrict__ emb) {
    int w = (blockIdx.x * blockDim.x + threadIdx.x) >> 5;
    int lane = threadIdx.x & 31;
    if (w >= MD + MQ) return;
    int id, drow;
    if (w < MD) { id = dids[w]; drow = w; }
    else        { id = qids[w - MD]; drow = QROW0 + (w - MD); }
    const float* src = emb + (size_t)id * EMB;
    float* dh = g_Ehi + (size_t)drow * KPAD;
    __nv_bfloat16* dc = g_Ecorr + (size_t)drow * KC2;
    #pragma unroll
    for (int i = 0; i < 10; i++) {
        int c = lane + i * 32;
        float x = (c < EMB) ? src[c] : 0.f;
        float h = f2tf32(x);
        float l = x - h;                           // exact in f32
        dh[c] = h;
        dc[c]        = __float2bfloat16(l);        // Elo16
        dc[c + KPAD] = __float2bfloat16(h);        // Ehi16
    }
}

// ---------------- 2) Wcat: Whi f32 + Wcorr bf16 ----------------
// group g: 0=(k1,t0) 1=(k2,t0) 2=(k2,t1) 3=(k3,t0) 4=(k3,t1) 5=(k3,t2)
__global__ void wcat_kernel(const float* __restrict__ w1, const float* __restrict__ w2,
                            const float* __restrict__ w3) {
    int idx = blockIdx.x * blockDim.x + threadIdx.x;
    if (idx >= NCAT * KPAD) return;
    int j = idx / KPAD, e = idx % KPAD;
    int g = j >> 7, c = j & 127;
    float v = 0.f;
    if (e < EMB) {
        if (g == 0)      v = w1[c * EMB + e];
        else if (g == 1) v = w2[(c * EMB + e) * 2 + 0];
        else if (g == 2) v = w2[(c * EMB + e) * 2 + 1];
        else             v = w3[(c * EMB + e) * 3 + (g - 3)];
    }
    float h = f2tf32(v);
    float l = v - h;
    g_Whi[idx] = h;
    g_Wcorr[(size_t)j * KC2 + e]        = __float2bfloat16(h);   // Whi16
    g_Wcorr[(size_t)j * KC2 + e + KPAD] = __float2bfloat16(l);   // Wlo16
}

// ---------------- 3) mixed tf32/bf16 split GEMM: P[128 x 256] per CTA ----------------
// grid (3, 264). 8 warps, warp tile 64x64.
// stage: [Ahi f32 128x32][Acorr bf16 128x64][Bhi f32 256x32][Bcorr bf16 256x64]
// all tiles row stride 144 B.
#define STRIDE_B  144
#define A_TILE_B  (128 * STRIDE_B)                 // 18432
#define B_TILE_B  (256 * STRIDE_B)                 // 36864
#define STAGE_B   (2 * A_TILE_B + 2 * B_TILE_B)    // 110592
#define SMEM_DYN  (2 * STAGE_B)                    // 221184

__global__ void __launch_bounds__(256, 1) conv_mix_kernel() {
    extern __shared__ char sm[];
    const int mt = blockIdx.y, pass = blockIdx.x;
    const int mbase = (mt < 256) ? mt * 128 : QROW0 + (mt - 256) * 128;
    const int jbase = pass * 256;
    const int tid = threadIdx.x, wid = tid >> 5, lane = tid & 31;
    const int wm = wid & 1, wn = wid >> 1;     // warp tile: rows wm*64, cols wn*64

    const uint32_t smb = smem_u32(sm);

    const float*         Ah_src = g_Ehi   + (size_t)mbase * KPAD;
    const __nv_bfloat16* Ac_src = g_Ecorr + (size_t)mbase * KC2;
    const float*         Bh_src = g_Whi   + (size_t)jbase * KPAD;
    const __nv_bfloat16* Bc_src = g_Wcorr + (size_t)jbase * KC2;

    auto load_stage = [&](int s, int kc) {
        const uint32_t st = smb + s * STAGE_B;
        const int kof = kc * 32;
        // A-hi: 128 x 32 f32 -> 1024 16B chunks (4/thread)
        #pragma unroll
        for (int i = 0; i < 4; i++) {
            int q = tid + i * 256;
            int r = q >> 3, c = q & 7;
            uint32_t doff = (uint32_t)r * STRIDE_B + c * 16;
            cp16(st + doff, Ah_src + (size_t)r * KPAD + kof + c * 4);
            // A-corr: 128 x 64 bf16; cols [0,32)=Elo chunk, [32,64)=Ehi chunk
            int cc = (c < 4) ? (kof + c * 8) : (KPAD + kof + (c - 4) * 8);
            cp16(st + A_TILE_B + doff, Ac_src + (size_t)r * KC2 + cc);
        }
        // B tiles: 256 rows (8/thread)
        #pragma unroll
        for (int i = 0; i < 8; i++) {
            int q = tid + i * 256;
            int r = q >> 3, c = q & 7;
            uint32_t doff = (uint32_t)r * STRIDE_B + c * 16;
            cp16(st + 2 * A_TILE_B + doff, Bh_src + (size_t)r * KPAD + kof + c * 4);
            int cc = (c < 4) ? (kof + c * 8) : (KPAD + kof + (c - 4) * 8);
            cp16(st + 2 * A_TILE_B + B_TILE_B + doff, Bc_src + (size_t)r * KC2 + cc);
        }
        cp_commit();
    };

    float acc[4][8][4];
    #pragma unroll
    for (int i = 0; i < 4; i++)
        #pragma unroll
        for (int j = 0; j < 8; j++)
            #pragma unroll
            for (int k = 0; k < 4; k++) acc[i][j][k] = 0.f;

    // fragment lane addressing (identical byte pattern for tf32-k8 and bf16-k16)
    const int lg = lane >> 3, lj = lane & 7;
    const uint32_t a_off = (uint32_t)(lj + 8 * (lg & 1)) * STRIDE_B + (uint32_t)(lg >> 1) * 16;
    const uint32_t b_off = (uint32_t)(lj + 8 * (lg >> 1)) * STRIDE_B + (uint32_t)(lg & 1) * 16;

    load_stage(0, 0);

    for (int kc = 0; kc < 10; kc++) {
        const int s = kc & 1;
        if (kc + 1 < 10) {
            load_stage(s ^ 1, kc + 1);
            cp_wait<1>();
        } else {
            cp_wait<0>();
        }
        __syncthreads();

        const uint32_t Ahi = smb + s * STAGE_B;
        const uint32_t Aco = Ahi + A_TILE_B;
        const uint32_t Bhi = Ahi + 2 * A_TILE_B;
        const uint32_t Bco = Bhi + B_TILE_B;

        #pragma unroll
        for (int ks = 0; ks < 4; ks++) {
            const uint32_t kb = ks * 32;       // 8 f32 or 16 bf16 per step
            // ---- main term (tf32 k8) ----
            {
                uint32_t bh[8][2];
                #pragma unroll
                for (int h = 0; h < 4; h++) {
                    uint32_t off = (uint32_t)(wn * 64 + h * 16) * STRIDE_B + kb + b_off;
                    uint32_t r[4];
                    ldmx4(r, Bhi + off);
                    bh[h * 2 + 0][0] = r[0]; bh[h * 2 + 0][1] = r[1];
                    bh[h * 2 + 1][0] = r[2]; bh[h * 2 + 1][1] = r[3];
                }
                #pragma unroll
                for (int mf = 0; mf < 4; mf++) {
                    uint32_t ah[4];
                    ldmx4(ah, Ahi + (uint32_t)(wm * 64 + mf * 16) * STRIDE_B + kb + a_off);
                    #pragma unroll
                    for (int nf = 0; nf < 8; nf++) mma_tf32(acc[mf][nf], ah, bh[nf]);
                }
            }
            // ---- correction term (bf16 k16) ----
            {
                uint32_t bc[8][2];
                #pragma unroll
                for (int h = 0; h < 4; h++) {
                    uint32_t off = (uint32_t)(wn * 64 + h * 16) * STRIDE_B + kb + b_off;
                    uint32_t r[4];
                    ldmx4(r, Bco + off);
                    bc[h * 2 + 0][0] = r[0]; bc[h * 2 + 0][1] = r[1];
                    bc[h * 2 + 1][0] = r[2]; bc[h * 2 + 1][1] = r[3];
                }
                #pragma unroll
                for (int mf = 0; mf < 4; mf++) {
                    uint32_t ac[4];
                    ldmx4(ac, Aco + (uint32_t)(wm * 64 + mf * 16) * STRIDE_B + kb + a_off);
                    #pragma unroll
                    for (int nf = 0; nf < 8; nf++) mma_bf16(acc[mf][nf], ac, bc[nf]);
                }
            }
        }
        __syncthreads();
    }

    // epilogue
    const int r0 = lane >> 2, c0 = (lane & 3) * 2;
    #pragma unroll
    for (int mf = 0; mf < 4; mf++) {
        int row = mbase + wm * 64 + mf * 16 + r0;
        #pragma unroll
        for (int nf = 0; nf < 8; nf++) {
            int col = jbase + wn * 64 + nf * 8 + c0;
            float* p = g_P + (size_t)row * NCAT + col;
            *(float2*)p                      = make_float2(acc[mf][nf][0], acc[mf][nf][1]);
            *(float2*)(p + (size_t)8 * NCAT) = make_float2(acc[mf][nf][2], acc[mf][nf][3]);
        }
    }
}

// ---------------- 4) combine taps + bias + relu + L2 normalize + mask ----------------
__global__ void combine_kernel(const float* __restrict__ b1, const float* __restrict__ b2,
                               const float* __restrict__ b3,
                               const float* __restrict__ qmask, const float* __restrict__ dmask) {
    int w = (blockIdx.x * blockDim.x + threadIdx.x) >> 5;
    int lane = threadIdx.x & 31;
    if (w >= (MD + MQ) * 3) return;
    int kidx = w % 3;
    int row  = w / 3;
    int prow; float* out; float mk;
    if (row < MD) { prow = row; out = g_DENC + ((size_t)kidx * MD + row) * CDIM; mk = dmask[row]; }
    else {
        int q = row - MD;
        prow = QROW0 + q;
        out = g_QENC + ((size_t)kidx * MQ + q) * CDIM;
        mk = qmask[q];
    }
    const float* bias = (kidx == 0) ? b1 : (kidx == 1 ? b2 : b3);
    const float* P0 = g_P + (size_t)prow * NCAT;
    int c = lane * 4;
    float4 v;
    if (kidx == 0) {
        v = *(const float4*)(P0 + c);
    } else if (kidx == 1) {
        float4 a = *(const float4*)(P0 + 128 + c);
        float4 b = *(const float4*)(P0 + NCAT + 256 + c);
        v = make_float4(a.x + b.x, a.y + b.y, a.z + b.z, a.w + b.w);
    } else {
        float4 a = *(const float4*)(P0 + 384 + c);
        float4 b = *(const float4*)(P0 + NCAT + 512 + c);
        float4 d = *(const float4*)(P0 + 2 * NCAT + 640 + c);
        v = make_float4(a.x + b.x + d.x, a.y + b.y + d.y, a.z + b.z + d.z, a.w + b.w + d.w);
    }
    float4 bv = *(const float4*)(bias + c);
    v.x = fmaxf(v.x + bv.x, 0.f);  v.y = fmaxf(v.y + bv.y, 0.f);
    v.z = fmaxf(v.z + bv.z, 0.f);  v.w = fmaxf(v.w + bv.w, 0.f);
    float ss = v.x * v.x + v.y * v.y + v.z * v.z + v.w * v.w;
    #pragma unroll
    for (int off = 16; off > 0; off >>= 1)
        ss += __shfl_xor_sync(0xffffffffu, ss, off);
    float sc = mk / (sqrtf(ss) + 1e-13f);
    v.x *= sc; v.y *= sc; v.z *= sc; v.w *= sc;
    *(float4*)(out + c) = v;
}

// ---------------- 5) matcher: sim GEMM + Gaussian-bin pooling ----------------
__device__ __forceinline__ void accum_bins(float* h, float s, float sel) {
    float d1 = s - 1.0f;
    if (fabsf(d1) < 0.012f)
        h[0] += sel * __expf(-500000.f * d1 * d1);
    float d0 = s - 0.95f;
    float g = sel * __expf(-50.f * d0 * d0);
    float t = __expf(-10.f * d0) * 0.60653065971f;
    #pragma unroll
    for (int j = 1; j <= 20; j++) {
        h[j] += g;
        g *= t;
        t *= 0.36787944117f;
    }
}

__global__ __launch_bounds__(256) void matcher_kernel(const float* __restrict__ qmasks) {
    const int b    = blockIdx.x;
    const int pair = blockIdx.y;
    const int qk   = pair / 3, dk = pair % 3;
    const float* Q = g_QENC + ((size_t)qk * MQ + b * QLEN) * CDIM;
    const float* D = g_DENC + ((size_t)dk * MD + b * DLEN) * CDIM;
    const int qlen_v = QLEN - qk;
    const int dlen_v = DLEN - dk;

    __shared__ float Qs[128][36];
    __shared__ float Ds[128][65];
    __shared__ float warp_out[8][21];

    const int tid = threadIdx.x;
    const int tq  = tid >> 5;
    const int td  = tid & 31;

    for (int i = tid; i < 32 * 32; i += 256) {
        int q = i >> 5, c4 = i & 31;
        float4 v = *(const float4*)(Q + (size_t)q * CDIM + c4 * 4);
        Qs[c4 * 4 + 0][q] = v.x;  Qs[c4 * 4 + 1][q] = v.y;
        Qs[c4 * 4 + 2][q] = v.z;  Qs[c4 * 4 + 3][q] = v.w;
    }

    float hist[4][21];
    #pragma unroll
    for (int qi = 0; qi < 4; qi++)
        #pragma unroll
        for (int j = 0; j < 21; j++) hist[qi][j] = 0.f;

    for (int dt = 0; dt < DLEN / 64; dt++) {
        __syncthreads();
        for (int i = tid; i < 64 * 32; i += 256) {
            int r = i >> 5, c4 = i & 31;
            float4 v = *(const float4*)(D + (size_t)(dt * 64 + r) * CDIM + c4 * 4);
            Ds[c4 * 4 + 0][r] = v.x;  Ds[c4 * 4 + 1][r] = v.y;
            Ds[c4 * 4 + 2][r] = v.z;  Ds[c4 * 4 + 3][r] = v.w;
        }
        __syncthreads();

        float s0[4] = {0.f, 0.f, 0.f, 0.f};
        float s1[4] = {0.f, 0.f, 0.f, 0.f};
        #pragma unroll 8
        for (int kk = 0; kk < 128; kk++) {
            float a0 = Ds[kk][td];
            float a1 = Ds[kk][td + 32];
            float4 bq = *(const float4*)&Qs[kk][tq * 4];
            s0[0] = fmaf(a0, bq.x, s0[0]);  s0[1] = fmaf(a0, bq.y, s0[1]);
            s0[2] = fmaf(a0, bq.z, s0[2]);  s0[3] = fmaf(a0, bq.w, s0[3]);
            s1[0] = fmaf(a1, bq.x, s1[0]);  s1[1] = fmaf(a1, bq.y, s1[1]);
            s1[2] = fmaf(a1, bq.z, s1[2]);  s1[3] = fmaf(a1, bq.w, s1[3]);
        }
        float sel0 = (dt * 64 + td      < dlen_v) ? 1.f : 0.f;
        float sel1 = (dt * 64 + td + 32 < dlen_v) ? 1.f : 0.f;
        #pragma unroll
        for (int qi = 0; qi < 4; qi++) {
            accum_bins(hist[qi], s0[qi], sel0);
            accum_bins(hist[qi], s1[qi], sel1);
        }
    }

    #pragma unroll
    for (int qi = 0; qi < 4; qi++)
        #pragma unroll
        for (int j = 0; j < 21; j++) {
            float v = hist[qi][j];
            #pragma unroll
            for (int off = 16; off > 0; off >>= 1)
                v += __shfl_down_sync(0xffffffffu, v, off);
            hist[qi][j] = v;
        }

    if (td == 0) {
        float part[21];
        #pragma unroll
        for (int j = 0; j < 21; j++) part[j] = 0.f;
        #pragma unroll
        for (int qi = 0; qi < 4; qi++) {
            int qrow = tq * 4 + qi;
            float w = (qrow < qlen_v) ? qmasks[b * QLEN + qrow] : 0.f;
            #pragma unroll
            for (int j = 0; j < 21; j++)
                part[j] += __logf(fmaxf(hist[qi][j], 1e-10f)) * 0.01f * w;
        }
        #pragma unroll
        for (int j = 0; j < 21; j++) warp_out[tq][j] = part[j];
    }
    __syncthreads();
    if (tid < 21) {
        float s = 0.f;
        #pragma unroll
        for (int w = 0; w < 8; w++) s += warp_out[w][tid];
        g_LOGITS[b * 189 + pair * 21 + tid] = s;
    }
}

// ---------------- 6) dense score + output ----------------
__global__ void score_kernel(const float* __restrict__ dw, const float* __restrict__ db,
                             float* __restrict__ out, int out_size) {
    __shared__ float red[256];
    int b = blockIdx.x, tid = threadIdx.x;
    float v = (tid < 189) ? g_LOGITS[b * 189 + tid] * dw[tid] : 0.f;
    red[tid] = v;
    __syncthreads();
    for (int s = 128; s > 0; s >>= 1) {
        if (tid < s) red[tid] += red[tid + s];
        __syncthreads();
    }
    float score = red[0] + db[0];
    if (out_size >= B + B * 189) {
        if (tid == 0) out[b] = score;
        if (tid < 189) out[B + b * 189 + tid] = g_LOGITS[b * 189 + tid];
    } else if (out_size == B * 189) {
        if (tid < 189) out[b * 189 + tid] = g_LOGITS[b * 189 + tid];
    } else {
        if (tid == 0 && b < out_size) out[b] = score;
    }
}

// ---------------- launch ----------------
extern "C" void kernel_launch(void* const* d_in, const int* in_sizes, int n_in,
                              void* d_out, int out_size) {
    const int*   qids   = (const int*)d_in[0];
    const float* qmask  = (const float*)d_in[1];
    const int*   dids   = (const int*)d_in[2];
    const float* dmask  = (const float*)d_in[3];
    const float* emb    = (const float*)d_in[4];
    const float* w1     = (const float*)d_in[5];
    const float* b1     = (const float*)d_in[6];
    const float* w2     = (const float*)d_in[7];
    const float* b2     = (const float*)d_in[8];
    const float* w3     = (const float*)d_in[9];
    const float* b3     = (const float*)d_in[10];
    const float* dw     = (const float*)d_in[11];
    const float* db     = (const float*)d_in[12];
    float* out = (float*)d_out;

    cudaFuncSetAttribute(conv_mix_kernel, cudaFuncAttributeMaxDynamicSharedMemorySize, SMEM_DYN);

    gather_kernel<<<((MD + MQ) * 32 + 255) / 256, 256>>>(qids, dids, emb);
    wcat_kernel<<<(NCAT * KPAD + 255) / 256, 256>>>(w1, w2, w3);
    conv_mix_kernel<<<dim3(3, MTILES), 256, SMEM_DYN>>>();
    combine_kernel<<<((MD + MQ) * 3 * 32 + 255) / 256, 256>>>(b1, b2, b3, qmask, dmask);
    matcher_kernel<<<dim3(B, 9), 256>>>(qmask);
    score_kernel<<<B, 256>>>(dw, db, out, out_size);
}

// round 9
// speedup vs baseline: 1.1886x; 1.0585x over previous
#include <cuda_runtime.h>
#include <cuda_bf16.h>
#include <cstdint>

#define B      32
#define QLEN   32
#define DLEN   1024
#define EMB    300
#define CDIM   128
#define MD     (B*DLEN)
#define MQ     (B*QLEN)

#define QROW0   32896
#define NROWS   33924
#define KPAD    320
#define KC2     640
#define NCAT    768
#define MTILES  264

// ---------------- device scratch ----------------
__device__ float         g_Ehi[(size_t)NROWS * KPAD];
__device__ __nv_bfloat16 g_Ecorr[(size_t)NROWS * KC2];
__device__ float         g_Whi[NCAT * KPAD];
__device__ __nv_bfloat16 g_Wcorr[NCAT * KC2];
__device__ float g_P[(size_t)NROWS * NCAT];
// matcher-ready encodings: hi f32 + corr bf16, chunked [enc][b][4 chunks][rows][144B-stride]
__device__ float g_DHI[3ull * 32 * 4 * 1024 * 36];
__device__ char  g_DCO[3ull * 32 * 4 * 1024 * 144];   // row: [hi-bf16 64B][lo-bf16 64B][pad 16]
__device__ float g_QHI[3ull * 32 * 4 * 32 * 36];
__device__ char  g_QCO[3ull * 32 * 4 * 32 * 144];     // row: [lo-bf16 64B][hi-bf16 64B][pad 16]
__device__ float g_LOGITS[B * 189];

__device__ __forceinline__ uint32_t smem_u32(const void* p) {
    uint32_t a;
    asm("{ .reg .u64 t; cvta.to.shared.u64 t, %1; cvt.u32.u64 %0, t; }" : "=r"(a) : "l"(p));
    return a;
}
__device__ __forceinline__ float f2tf32(float x) {
    uint32_t r;
    asm("cvt.rna.tf32.f32 %0, %1;" : "=r"(r) : "f"(x));
    return __uint_as_float(r);
}
__device__ __forceinline__ void ldmx4(uint32_t* r, uint32_t addr) {
    asm volatile("ldmatrix.sync.aligned.m8n8.x4.shared.b16 {%0,%1,%2,%3}, [%4];"
                 : "=r"(r[0]), "=r"(r[1]), "=r"(r[2]), "=r"(r[3]) : "r"(addr));
}
__device__ __forceinline__ void mma_tf32(float* c, const uint32_t* a, const uint32_t* b) {
    asm volatile("mma.sync.aligned.m16n8k8.row.col.f32.tf32.tf32.f32 "
                 "{%0,%1,%2,%3}, {%4,%5,%6,%7}, {%8,%9}, {%0,%1,%2,%3};"
                 : "+f"(c[0]), "+f"(c[1]), "+f"(c[2]), "+f"(c[3])
                 : "r"(a[0]), "r"(a[1]), "r"(a[2]), "r"(a[3]), "r"(b[0]), "r"(b[1]));
}
__device__ __forceinline__ void mma_bf16(float* c, const uint32_t* a, const uint32_t* b) {
    asm volatile("mma.sync.aligned.m16n8k16.row.col.f32.bf16.bf16.f32 "
                 "{%0,%1,%2,%3}, {%4,%5,%6,%7}, {%8,%9}, {%0,%1,%2,%3};"
                 : "+f"(c[0]), "+f"(c[1]), "+f"(c[2]), "+f"(c[3])
                 : "r"(a[0]), "r"(a[1]), "r"(a[2]), "r"(a[3]), "r"(b[0]), "r"(b[1]));
}
__device__ __forceinline__ void cp16(uint32_t dst, const void* src) {
    asm volatile("cp.async.cg.shared.global [%0], [%1], 16;" :: "r"(dst), "l"(src));
}
__device__ __forceinline__ void cp_commit() {
    asm volatile("cp.async.commit_group;" ::: "memory");
}
template <int N>
__device__ __forceinline__ void cp_wait() {
    asm volatile("cp.async.wait_group %0;" :: "n"(N) : "memory");
}

// ---------------- 1) gather ----------------
__global__ void gather_kernel(const int* __restrict__ qids, const int* __restrict__ dids,
                              const float* __restrict__ emb) {
    int w = (blockIdx.x * blockDim.x + threadIdx.x) >> 5;
    int lane = threadIdx.x & 31;
    if (w >= MD + MQ) return;
    int id, drow;
    if (w < MD) { id = dids[w]; drow = w; }
    else        { id = qids[w - MD]; drow = QROW0 + (w - MD); }
    const float* src = emb + (size_t)id * EMB;
    float* dh = g_Ehi + (size_t)drow * KPAD;
    __nv_bfloat16* dc = g_Ecorr + (size_t)drow * KC2;
    #pragma unroll
    for (int i = 0; i < 10; i++) {
        int c = lane + i * 32;
        float x = (c < EMB) ? src[c] : 0.f;
        float h = f2tf32(x);
        float l = x - h;
        dh[c] = h;
        dc[c]        = __float2bfloat16(l);
        dc[c + KPAD] = __float2bfloat16(h);
    }
}

// ---------------- 2) Wcat ----------------
__global__ void wcat_kernel(const float* __restrict__ w1, const float* __restrict__ w2,
                            const float* __restrict__ w3) {
    int idx = blockIdx.x * blockDim.x + threadIdx.x;
    if (idx >= NCAT * KPAD) return;
    int j = idx / KPAD, e = idx % KPAD;
    int g = j >> 7, c = j & 127;
    float v = 0.f;
    if (e < EMB) {
        if (g == 0)      v = w1[c * EMB + e];
        else if (g == 1) v = w2[(c * EMB + e) * 2 + 0];
        else if (g == 2) v = w2[(c * EMB + e) * 2 + 1];
        else             v = w3[(c * EMB + e) * 3 + (g - 3)];
    }
    float h = f2tf32(v);
    float l = v - h;
    g_Whi[idx] = h;
    g_Wcorr[(size_t)j * KC2 + e]        = __float2bfloat16(h);
    g_Wcorr[(size_t)j * KC2 + e + KPAD] = __float2bfloat16(l);
}

// ---------------- 3) conv GEMM (unchanged from R8) ----------------
#define STRIDE_B  144
#define A_TILE_B  (128 * STRIDE_B)
#define B_TILE_B  (256 * STRIDE_B)
#define STAGE_B   (2 * A_TILE_B + 2 * B_TILE_B)
#define SMEM_DYN  (2 * STAGE_B)

__global__ void __launch_bounds__(256, 1) conv_mix_kernel() {
    extern __shared__ char sm[];
    const int mt = blockIdx.y, pass = blockIdx.x;
    const int mbase = (mt < 256) ? mt * 128 : QROW0 + (mt - 256) * 128;
    const int jbase = pass * 256;
    const int tid = threadIdx.x, wid = tid >> 5, lane = tid & 31;
    const int wm = wid & 1, wn = wid >> 1;

    const uint32_t smb = smem_u32(sm);
    const float*         Ah_src = g_Ehi   + (size_t)mbase * KPAD;
    const __nv_bfloat16* Ac_src = g_Ecorr + (size_t)mbase * KC2;
    const float*         Bh_src = g_Whi   + (size_t)jbase * KPAD;
    const __nv_bfloat16* Bc_src = g_Wcorr + (size_t)jbase * KC2;

    auto load_stage = [&](int s, int kc) {
        const uint32_t st = smb + s * STAGE_B;
        const int kof = kc * 32;
        #pragma unroll
        for (int i = 0; i < 4; i++) {
            int q = tid + i * 256;
            int r = q >> 3, c = q & 7;
            uint32_t doff = (uint32_t)r * STRIDE_B + c * 16;
            cp16(st + doff, Ah_src + (size_t)r * KPAD + kof + c * 4);
            int cc = (c < 4) ? (kof + c * 8) : (KPAD + kof + (c - 4) * 8);
            cp16(st + A_TILE_B + doff, Ac_src + (size_t)r * KC2 + cc);
        }
        #pragma unroll
        for (int i = 0; i < 8; i++) {
            int q = tid + i * 256;
            int r = q >> 3, c = q & 7;
            uint32_t doff = (uint32_t)r * STRIDE_B + c * 16;
            cp16(st + 2 * A_TILE_B + doff, Bh_src + (size_t)r * KPAD + kof + c * 4);
            int cc = (c < 4) ? (kof + c * 8) : (KPAD + kof + (c - 4) * 8);
            cp16(st + 2 * A_TILE_B + B_TILE_B + doff, Bc_src + (size_t)r * KC2 + cc);
        }
        cp_commit();
    };

    float acc[4][8][4];
    #pragma unroll
    for (int i = 0; i < 4; i++)
        #pragma unroll
        for (int j = 0; j < 8; j++)
            #pragma unroll
            for (int k = 0; k < 4; k++) acc[i][j][k] = 0.f;

    const int lg = lane >> 3, lj = lane & 7;
    const uint32_t a_off = (uint32_t)(lj + 8 * (lg & 1)) * STRIDE_B + (uint32_t)(lg >> 1) * 16;
    const uint32_t b_off = (uint32_t)(lj + 8 * (lg >> 1)) * STRIDE_B + (uint32_t)(lg & 1) * 16;

    load_stage(0, 0);

    for (int kc = 0; kc < 10; kc++) {
        const int s = kc & 1;
        if (kc + 1 < 10) { load_stage(s ^ 1, kc + 1); cp_wait<1>(); }
        else             { cp_wait<0>(); }
        __syncthreads();

        const uint32_t Ahi = smb + s * STAGE_B;
        const uint32_t Aco = Ahi + A_TILE_B;
        const uint32_t Bhi = Ahi + 2 * A_TILE_B;
        const uint32_t Bco = Bhi + B_TILE_B;

        #pragma unroll
        for (int ks = 0; ks < 4; ks++) {
            const uint32_t kb = ks * 32;
            {
                uint32_t bh[8][2];
                #pragma unroll
                for (int h = 0; h < 4; h++) {
                    uint32_t off = (uint32_t)(wn * 64 + h * 16) * STRIDE_B + kb + b_off;
                    uint32_t r[4];
                    ldmx4(r, Bhi + off);
                    bh[h * 2 + 0][0] = r[0]; bh[h * 2 + 0][1] = r[1];
                    bh[h * 2 + 1][0] = r[2]; bh[h * 2 + 1][1] = r[3];
                }
                #pragma unroll
                for (int mf = 0; mf < 4; mf++) {
                    uint32_t ah[4];
                    ldmx4(ah, Ahi + (uint32_t)(wm * 64 + mf * 16) * STRIDE_B + kb + a_off);
                    #pragma unroll
                    for (int nf = 0; nf < 8; nf++) mma_tf32(acc[mf][nf], ah, bh[nf]);
                }
            }
            {
                uint32_t bc[8][2];
                #pragma unroll
                for (int h = 0; h < 4; h++) {
                    uint32_t off = (uint32_t)(wn * 64 + h * 16) * STRIDE_B + kb + b_off;
                    uint32_t r[4];
                    ldmx4(r, Bco + off);
                    bc[h * 2 + 0][0] = r[0]; bc[h * 2 + 0][1] = r[1];
                    bc[h * 2 + 1][0] = r[2]; bc[h * 2 + 1][1] = r[3];
                }
                #pragma unroll
                for (int mf = 0; mf < 4; mf++) {
                    uint32_t ac[4];
                    ldmx4(ac, Aco + (uint32_t)(wm * 64 + mf * 16) * STRIDE_B + kb + a_off);
                    #pragma unroll
                    for (int nf = 0; nf < 8; nf++) mma_bf16(acc[mf][nf], ac, bc[nf]);
                }
            }
        }
        __syncthreads();
    }

    const int r0 = lane >> 2, c0 = (lane & 3) * 2;
    #pragma unroll
    for (int mf = 0; mf < 4; mf++) {
        int row = mbase + wm * 64 + mf * 16 + r0;
        #pragma unroll
        for (int nf = 0; nf < 8; nf++) {
            int col = jbase + wn * 64 + nf * 8 + c0;
            float* p = g_P + (size_t)row * NCAT + col;
            *(float2*)p                      = make_float2(acc[mf][nf][0], acc[mf][nf][1]);
            *(float2*)(p + (size_t)8 * NCAT) = make_float2(acc[mf][nf][2], acc[mf][nf][3]);
        }
    }
}

// ---------------- 4) combine: taps+bias+relu+L2+mask -> split matcher layout ----------------
__global__ void combine_kernel(const float* __restrict__ b1, const float* __restrict__ b2,
                               const float* __restrict__ b3,
                               const float* __restrict__ qmask, const float* __restrict__ dmask) {
    int w = (blockIdx.x * blockDim.x + threadIdx.x) >> 5;
    int lane = threadIdx.x & 31;
    if (w >= (MD + MQ) * 3) return;
    int kidx = w % 3;
    int row  = w / 3;
    int prow, bb, pos, is_q;
    float mk;
    if (row < MD) { is_q = 0; prow = row; bb = row / DLEN; pos = row % DLEN; mk = dmask[row]; }
    else {
        is_q = 1;
        int q = row - MD;
        prow = QROW0 + q; bb = q / QLEN; pos = q % QLEN; mk = qmask[q];
    }
    const int len = is_q ? QLEN : DLEN;
    const float* bias = (kidx == 0) ? b1 : (kidx == 1 ? b2 : b3);
    const float* P0 = g_P + (size_t)prow * NCAT;
    int c = lane * 4;
    float4 v;
    if (kidx == 0) {
        v = *(const float4*)(P0 + c);
    } else if (kidx == 1) {
        float4 a = *(const float4*)(P0 + 128 + c);
        float4 b = *(const float4*)(P0 + NCAT + 256 + c);
        v = make_float4(a.x + b.x, a.y + b.y, a.z + b.z, a.w + b.w);
    } else {
        float4 a = *(const float4*)(P0 + 384 + c);
        float4 b = *(const float4*)(P0 + NCAT + 512 + c);
        float4 d = *(const float4*)(P0 + 2 * NCAT + 640 + c);
        v = make_float4(a.x + b.x + d.x, a.y + b.y + d.y, a.z + b.z + d.z, a.w + b.w + d.w);
    }
    float4 bv = *(const float4*)(bias + c);
    v.x = fmaxf(v.x + bv.x, 0.f);  v.y = fmaxf(v.y + bv.y, 0.f);
    v.z = fmaxf(v.z + bv.z, 0.f);  v.w = fmaxf(v.w + bv.w, 0.f);
    float ss = v.x * v.x + v.y * v.y + v.z * v.z + v.w * v.w;
    #pragma unroll
    for (int off = 16; off > 0; off >>= 1)
        ss += __shfl_xor_sync(0xffffffffu, ss, off);
    float sc = mk / (sqrtf(ss) + 1e-13f);
    if (pos >= len - kidx) sc = 0.f;                 // zero invalid conv tail rows
    v.x *= sc; v.y *= sc; v.z *= sc; v.w *= sc;

    // split
    float4 hi = make_float4(f2tf32(v.x), f2tf32(v.y), f2tf32(v.z), f2tf32(v.w));
    __nv_bfloat16 lo16[4] = { __float2bfloat16(v.x - hi.x), __float2bfloat16(v.y - hi.y),
                              __float2bfloat16(v.z - hi.z), __float2bfloat16(v.w - hi.w) };
    __nv_bfloat16 hi16[4] = { __float2bfloat16(hi.x), __float2bfloat16(hi.y),
                              __float2bfloat16(hi.z), __float2bfloat16(hi.w) };

    int ch = lane >> 3, w32 = (lane & 7) * 4;
    if (!is_q) {
        size_t blk = (((size_t)kidx * 32 + bb) * 4 + ch) * 1024 + pos;
        *(float4*)(g_DHI + blk * 36 + w32) = hi;
        char* co = g_DCO + blk * 144;
        *(uint2*)(co + w32 * 2)      = *(const uint2*)hi16;   // D corr: [hi|lo]
        *(uint2*)(co + 64 + w32 * 2) = *(const uint2*)lo16;
    } else {
        size_t blk = (((size_t)kidx * 32 + bb) * 4 + ch) * 32 + pos;
        *(float4*)(g_QHI + blk * 36 + w32) = hi;
        char* co = g_QCO + blk * 144;
        *(uint2*)(co + w32 * 2)      = *(const uint2*)lo16;   // Q corr: [lo|hi]
        *(uint2*)(co + 64 + w32 * 2) = *(const uint2*)hi16;
    }
}

// ---------------- 5) tensor matcher ----------------
__device__ __forceinline__ void accum_bins(float* h, float s) {
    float d1 = s - 1.0f;
    if (fabsf(d1) < 0.012f)
        h[0] += __expf(-500000.f * d1 * d1);
    float d0 = s - 0.95f;
    float g = __expf(-50.f * d0 * d0);
    float t = __expf(-10.f * d0) * 0.60653065971f;
    #pragma unroll
    for (int j = 1; j <= 20; j++) {
        h[j] += g;
        g *= t;
        t *= 0.36787944117f;
    }
}

#define MQ_SZ   18432                         // one Q array (hi or corr)
#define MD_SZ   36864                         // one D tile array
#define MD_STG  (2 * MD_SZ)                   // 73728
#define SMEM_M  (2 * MQ_SZ + 2 * MD_STG)      // 184320

__global__ void __launch_bounds__(256, 1) matcher_kernel(const float* __restrict__ qmasks) {
    extern __shared__ char sm[];
    __shared__ float H[8][16][21];
    __shared__ float KW[32][21];

    const int b    = blockIdx.x;
    const int pair = blockIdx.y;
    const int qk   = pair / 3, dk = pair % 3;
    const int qlen_v = QLEN - qk;
    const int tid = threadIdx.x, wid = tid >> 5, lane = tid & 31;
    const int mh = wid & 1, nh = wid >> 1;

    const uint32_t smb = smem_u32(sm);
    const uint32_t QHI = smb, QCO = smb + MQ_SZ;
    const uint32_t DST = smb + 2 * MQ_SZ;

    const char* qhi_g = (const char*)g_QHI + ((size_t)qk * 32 + b) * MQ_SZ;
    const char* qco_g = g_QCO + ((size_t)qk * 32 + b) * MQ_SZ;
    const char* dhi_g = (const char*)g_DHI + ((size_t)dk * 32 + b) * 589824;
    const char* dco_g = g_DCO + ((size_t)dk * 32 + b) * 589824;

    auto load_D = [&](int s, int dt) {
        const uint32_t st = DST + s * MD_STG;
        #pragma unroll
        for (int i = 0; i < 9; i++) {
            int idx = tid + i * 256;
            if (idx < 2304) {
                int ch = idx / 576;
                size_t go = (size_t)idx * 16 + (size_t)ch * 138240 + (size_t)dt * 9216;
                cp16(st + idx * 16, dhi_g + go);
                cp16(st + MD_SZ + idx * 16, dco_g + go);
            }
        }
        cp_commit();
    };

    // Q load (1152 16B chunks per array)
    #pragma unroll
    for (int i = 0; i < 5; i++) {
        int idx = tid + i * 256;
        if (idx < 1152) {
            cp16(QHI + idx * 16, qhi_g + (size_t)idx * 16);
            cp16(QCO + idx * 16, qco_g + (size_t)idx * 16);
        }
    }
    load_D(0, 0);   // commits Q+D0 together

    const int lg = lane >> 3, lj = lane & 7;
    const uint32_t a_off = (uint32_t)(lj + 8 * (lg & 1)) * STRIDE_B + (uint32_t)(lg >> 1) * 16;
    const uint32_t b_off = (uint32_t)(lj + 8 * (lg >> 1)) * STRIDE_B + (uint32_t)(lg & 1) * 16;
    const uint32_t qa_hi = QHI + (uint32_t)(mh * 16) * STRIDE_B + a_off;
    const uint32_t qa_co = QCO + (uint32_t)(mh * 16) * STRIDE_B + a_off;

    float hist[2][21];
    #pragma unroll
    for (int r = 0; r < 2; r++)
        #pragma unroll
        for (int j = 0; j < 21; j++) hist[r][j] = 0.f;

    for (int dt = 0; dt < 16; dt++) {
        const int s = dt & 1;
        if (dt + 1 < 16) { load_D(s ^ 1, dt + 1); cp_wait<1>(); }
        else             { cp_wait<0>(); }
        __syncthreads();

        const uint32_t Dhi = DST + s * MD_STG + (uint32_t)(nh * 16) * STRIDE_B + b_off;
        const uint32_t Dco = Dhi + MD_SZ;

        float acc[2][4];
        #pragma unroll
        for (int t = 0; t < 2; t++)
            #pragma unroll
            for (int k = 0; k < 4; k++) acc[t][k] = 0.f;

        #pragma unroll
        for (int kc = 0; kc < 4; kc++) {
            #pragma unroll
            for (int ks = 0; ks < 4; ks++) {
                uint32_t a[4], bb[4];
                ldmx4(a, qa_hi + kc * 4608 + ks * 32);
                ldmx4(bb, Dhi + kc * 9216 + ks * 32);
                mma_tf32(acc[0], a, bb);
                mma_tf32(acc[1], a, bb + 2);
            }
            #pragma unroll
            for (int ks = 0; ks < 4; ks++) {
                uint32_t a[4], bb[4];
                ldmx4(a, qa_co + kc * 4608 + ks * 32);
                ldmx4(bb, Dco + kc * 9216 + ks * 32);
                mma_bf16(acc[0], a, bb);
                mma_bf16(acc[1], a, bb + 2);
            }
        }
        #pragma unroll
        for (int t = 0; t < 2; t++) {
            accum_bins(hist[0], acc[t][0]);
            accum_bins(hist[0], acc[t][1]);
            accum_bins(hist[1], acc[t][2]);
            accum_bins(hist[1], acc[t][3]);
        }
        __syncthreads();
    }

    // reduce hist over the 4 lanes sharing a q-row
    #pragma unroll
    for (int r = 0; r < 2; r++)
        #pragma unroll
        for (int j = 0; j < 21; j++) {
            float v = hist[r][j];
            v += __shfl_xor_sync(0xffffffffu, v, 1);
            v += __shfl_xor_sync(0xffffffffu, v, 2);
            hist[r][j] = v;
        }
    if ((lane & 3) == 0) {
        int lr = lane >> 2;
        #pragma unroll
        for (int j = 0; j < 21; j++) {
            H[wid][lr][j]     = hist[0][j];
            H[wid][lr + 8][j] = hist[1][j];
        }
    }
    __syncthreads();

    if (tid < 32) {
        int q = tid;
        int qmh = q >> 4, local = q & 15;
        float g0[21];
        #pragma unroll
        for (int j = 0; j < 21; j++) g0[j] = 0.f;
        accum_bins(g0, 0.f);                       // bit-identical zero-sim contribution
        float w = (q < qlen_v) ? qmasks[b * QLEN + q] : 0.f;
        #pragma unroll
        for (int j = 0; j < 21; j++) {
            float tot = 0.f;
            #pragma unroll
            for (int n = 0; n < 4; n++) tot += H[2 * n + qmh][local][j];
            tot -= (float)dk * g0[j];
            KW[q][j] = __logf(fmaxf(tot, 1e-10f)) * 0.01f * w;
        }
    }
    __syncthreads();
    if (tid < 21) {
        float s = 0.f;
        #pragma unroll
        for (int q = 0; q < 32; q++) s += KW[q][tid];
        g_LOGITS[b * 189 + pair * 21 + tid] = s;
    }
}

// ---------------- 6) score ----------------
__global__ void score_kernel(const float* __restrict__ dw, const float* __restrict__ db,
                             float* __restrict__ out, int out_size) {
    __shared__ float red[256];
    int b = blockIdx.x, tid = threadIdx.x;
    float v = (tid < 189) ? g_LOGITS[b * 189 + tid] * dw[tid] : 0.f;
    red[tid] = v;
    __syncthreads();
    for (int s = 128; s > 0; s >>= 1) {
        if (tid < s) red[tid] += red[tid + s];
        __syncthreads();
    }
    float score = red[0] + db[0];
    if (out_size >= B + B * 189) {
        if (tid == 0) out[b] = score;
        if (tid < 189) out[B + b * 189 + tid] = g_LOGITS[b * 189 + tid];
    } else if (out_size == B * 189) {
        if (tid < 189) out[b * 189 + tid] = g_LOGITS[b * 189 + tid];
    } else {
        if (tid == 0 && b < out_size) out[b] = score;
    }
}

// ---------------- launch ----------------
extern "C" void kernel_launch(void* const* d_in, const int* in_sizes, int n_in,
                              void* d_out, int out_size) {
    const int*   qids   = (const int*)d_in[0];
    const float* qmask  = (const float*)d_in[1];
    const int*   dids   = (const int*)d_in[2];
    const float* dmask  = (const float*)d_in[3];
    const float* emb    = (const float*)d_in[4];
    const float* w1     = (const float*)d_in[5];
    const float* b1     = (const float*)d_in[6];
    const float* w2     = (const float*)d_in[7];
    const float* b2     = (const float*)d_in[8];
    const float* w3     = (const float*)d_in[9];
    const float* b3     = (const float*)d_in[10];
    const float* dw     = (const float*)d_in[11];
    const float* db     = (const float*)d_in[12];
    float* out = (float*)d_out;

    cudaFuncSetAttribute(conv_mix_kernel, cudaFuncAttributeMaxDynamicSharedMemorySize, SMEM_DYN);
    cudaFuncSetAttribute(matcher_kernel, cudaFuncAttributeMaxDynamicSharedMemorySize, SMEM_M);

    gather_kernel<<<((MD + MQ) * 32 + 255) / 256, 256>>>(qids, dids, emb);
    wcat_kernel<<<(NCAT * KPAD + 255) / 256, 256>>>(w1, w2, w3);
    conv_mix_kernel<<<dim3(3, MTILES), 256, SMEM_DYN>>>();
    combine_kernel<<<((MD + MQ) * 3 * 32 + 255) / 256, 256>>>(b1, b2, b3, qmask, dmask);
    matcher_kernel<<<dim3(B, 9), 256, SMEM_M>>>(qmask);
    score_kernel<<<B, 256>>>(dw, db, out, out_size);
}

// round 10
// speedup vs baseline: 1.4073x; 1.1840x over previous
#include <cuda_runtime.h>
#include <cuda_bf16.h>
#include <cuda_fp16.h>
#include <cstdint>

#define B      32
#define QLEN   32
#define DLEN   1024
#define EMB    300
#define CDIM   128
#define MD     (B*DLEN)
#define MQ     (B*QLEN)

#define QROW0   32896
#define NROWS   33924
#define KPAD    320
#define KC2     640
#define NCAT    768
#define MTILES  264

// ---------------- device scratch (zero-initialized) ----------------
__device__ __half        g_Eh[(size_t)NROWS * KPAD];    // fp16 hi
__device__ __nv_bfloat16 g_Ecorr[(size_t)NROWS * KC2];  // [lo16 | hi16]
__device__ __half        g_Wh[NCAT * KPAD];
__device__ __nv_bfloat16 g_Wcorr[NCAT * KC2];           // [hi16 | lo16]
__device__ float g_P[(size_t)NROWS * NCAT];
// matcher-ready: hi fp16 (80B-stride rows incl pad), corr bf16 (144B-stride rows)
__device__ char g_DH[3ull * 32 * 4 * 1024 * 80];
__device__ char g_DCO[3ull * 32 * 4 * 1024 * 144];      // row: [hi-bf16 64B][lo-bf16 64B][pad]
__device__ char g_QH[3ull * 32 * 4 * 32 * 80];
__device__ char g_QCO[3ull * 32 * 4 * 32 * 144];        // row: [lo-bf16 64B][hi-bf16 64B][pad]
__device__ float g_LOGITS[B * 189];

__device__ __forceinline__ uint32_t smem_u32(const void* p) {
    uint32_t a;
    asm("{ .reg .u64 t; cvta.to.shared.u64 t, %1; cvt.u32.u64 %0, t; }" : "=r"(a) : "l"(p));
    return a;
}
__device__ __forceinline__ void ldmx4(uint32_t* r, uint32_t addr) {
    asm volatile("ldmatrix.sync.aligned.m8n8.x4.shared.b16 {%0,%1,%2,%3}, [%4];"
                 : "=r"(r[0]), "=r"(r[1]), "=r"(r[2]), "=r"(r[3]) : "r"(addr));
}
__device__ __forceinline__ void mma_f16(float* c, const uint32_t* a, const uint32_t* b) {
    asm volatile("mma.sync.aligned.m16n8k16.row.col.f32.f16.f16.f32 "
                 "{%0,%1,%2,%3}, {%4,%5,%6,%7}, {%8,%9}, {%0,%1,%2,%3};"
                 : "+f"(c[0]), "+f"(c[1]), "+f"(c[2]), "+f"(c[3])
                 : "r"(a[0]), "r"(a[1]), "r"(a[2]), "r"(a[3]), "r"(b[0]), "r"(b[1]));
}
__device__ __forceinline__ void mma_bf16(float* c, const uint32_t* a, const uint32_t* b) {
    asm volatile("mma.sync.aligned.m16n8k16.row.col.f32.bf16.bf16.f32 "
                 "{%0,%1,%2,%3}, {%4,%5,%6,%7}, {%8,%9}, {%0,%1,%2,%3};"
                 : "+f"(c[0]), "+f"(c[1]), "+f"(c[2]), "+f"(c[3])
                 : "r"(a[0]), "r"(a[1]), "r"(a[2]), "r"(a[3]), "r"(b[0]), "r"(b[1]));
}
__device__ __forceinline__ void cp16(uint32_t dst, const void* src) {
    asm volatile("cp.async.cg.shared.global [%0], [%1], 16;" :: "r"(dst), "l"(src));
}
__device__ __forceinline__ void cp_commit() {
    asm volatile("cp.async.commit_group;" ::: "memory");
}
template <int N>
__device__ __forceinline__ void cp_wait() {
    asm volatile("cp.async.wait_group %0;" :: "n"(N) : "memory");
}

// ---------------- 1) gather: fp16 hi + bf16 corr ----------------
__global__ void gather_kernel(const int* __restrict__ qids, const int* __restrict__ dids,
                              const float* __restrict__ emb) {
    int w = (blockIdx.x * blockDim.x + threadIdx.x) >> 5;
    int lane = threadIdx.x & 31;
    if (w >= MD + MQ) return;
    int id, drow;
    if (w < MD) { id = dids[w]; drow = w; }
    else        { id = qids[w - MD]; drow = QROW0 + (w - MD); }
    const float* src = emb + (size_t)id * EMB;
    __half* dh = g_Eh + (size_t)drow * KPAD;
    __nv_bfloat16* dc = g_Ecorr + (size_t)drow * KC2;
    #pragma unroll
    for (int i = 0; i < 10; i++) {
        int c = lane + i * 32;
        float x = (c < EMB) ? src[c] : 0.f;
        __half h = __float2half(x);
        float hf = __half2float(h);
        dh[c] = h;
        dc[c]        = __float2bfloat16(x - hf);   // lo
        dc[c + KPAD] = __float2bfloat16(hf);       // hi16
    }
}

// ---------------- 2) Wcat ----------------
__global__ void wcat_kernel(const float* __restrict__ w1, const float* __restrict__ w2,
                            const float* __restrict__ w3) {
    int idx = blockIdx.x * blockDim.x + threadIdx.x;
    if (idx >= NCAT * KPAD) return;
    int j = idx / KPAD, e = idx % KPAD;
    int g = j >> 7, c = j & 127;
    float v = 0.f;
    if (e < EMB) {
        if (g == 0)      v = w1[c * EMB + e];
        else if (g == 1) v = w2[(c * EMB + e) * 2 + 0];
        else if (g == 2) v = w2[(c * EMB + e) * 2 + 1];
        else             v = w3[(c * EMB + e) * 3 + (g - 3)];
    }
    __half h = __float2half(v);
    float hf = __half2float(h);
    g_Wh[idx] = h;
    g_Wcorr[(size_t)j * KC2 + e]        = __float2bfloat16(hf);      // hi16
    g_Wcorr[(size_t)j * KC2 + e + KPAD] = __float2bfloat16(v - hf);  // lo
}

// ---------------- 3) fp16-main + bf16-corr GEMM: P[128 x 256] per CTA ----------------
#define S80   80
#define S144  144
#define AHI_OFF  0
#define ACO_OFF  10240
#define BHI_OFF  28672
#define BCO_OFF  49152
#define STAGE_B  86016
#define SMEM_DYN (2 * STAGE_B)     // 172032

__global__ void __launch_bounds__(256, 1) conv_mix_kernel() {
    extern __shared__ char sm[];
    const int mt = blockIdx.y, pass = blockIdx.x;
    const int mbase = (mt < 256) ? mt * 128 : QROW0 + (mt - 256) * 128;
    const int jbase = pass * 256;
    const int tid = threadIdx.x, wid = tid >> 5, lane = tid & 31;
    const int wm = wid & 1, wn = wid >> 1;

    const uint32_t smb = smem_u32(sm);
    const char*          Ah_src = (const char*)(g_Eh + (size_t)mbase * KPAD);
    const __nv_bfloat16* Ac_src = g_Ecorr + (size_t)mbase * KC2;
    const char*          Bh_src = (const char*)(g_Wh + (size_t)jbase * KPAD);
    const __nv_bfloat16* Bc_src = g_Wcorr + (size_t)jbase * KC2;

    auto load_stage = [&](int s, int kc) {
        const uint32_t st = smb + s * STAGE_B;
        const int kof = kc * 32;          // element offset within K
        // A-hi: 512 chunks (2/thread)
        #pragma unroll
        for (int i = 0; i < 2; i++) {
            int idx = tid + i * 256;
            int r = idx >> 2, c = idx & 3;
            cp16(st + AHI_OFF + (uint32_t)r * S80 + c * 16,
                 Ah_src + (size_t)r * 640 + kof * 2 + c * 16);
        }
        // B-hi: 1024 chunks (4/thread)
        #pragma unroll
        for (int i = 0; i < 4; i++) {
            int idx = tid + i * 256;
            int r = idx >> 2, c = idx & 3;
            cp16(st + BHI_OFF + (uint32_t)r * S80 + c * 16,
                 Bh_src + (size_t)r * 640 + kof * 2 + c * 16);
        }
        // A-corr: 1024 chunks (4/thread)
        #pragma unroll
        for (int i = 0; i < 4; i++) {
            int idx = tid + i * 256;
            int r = idx >> 3, c = idx & 7;
            int cc = (c < 4) ? (kof + c * 8) : (KPAD + kof + (c - 4) * 8);
            cp16(st + ACO_OFF + (uint32_t)r * S144 + c * 16, Ac_src + (size_t)r * KC2 + cc);
        }
        // B-corr: 2048 chunks (8/thread)
        #pragma unroll
        for (int i = 0; i < 8; i++) {
            int idx = tid + i * 256;
            int r = idx >> 3, c = idx & 7;
            int cc = (c < 4) ? (kof + c * 8) : (KPAD + kof + (c - 4) * 8);
            cp16(st + BCO_OFF + (uint32_t)r * S144 + c * 16, Bc_src + (size_t)r * KC2 + cc);
        }
        cp_commit();
    };

    float acc[4][8][4];
    #pragma unroll
    for (int i = 0; i < 4; i++)
        #pragma unroll
        for (int j = 0; j < 8; j++)
            #pragma unroll
            for (int k = 0; k < 4; k++) acc[i][j][k] = 0.f;

    const int lg = lane >> 3, lj = lane & 7;
    const uint32_t a80  = (uint32_t)(lj + 8 * (lg & 1)) * S80  + (uint32_t)(lg >> 1) * 16;
    const uint32_t b80  = (uint32_t)(lj + 8 * (lg >> 1)) * S80  + (uint32_t)(lg & 1) * 16;
    const uint32_t a144 = (uint32_t)(lj + 8 * (lg & 1)) * S144 + (uint32_t)(lg >> 1) * 16;
    const uint32_t b144 = (uint32_t)(lj + 8 * (lg >> 1)) * S144 + (uint32_t)(lg & 1) * 16;

    load_stage(0, 0);

    for (int kc = 0; kc < 10; kc++) {
        const int s = kc & 1;
        if (kc + 1 < 10) { load_stage(s ^ 1, kc + 1); cp_wait<1>(); }
        else             { cp_wait<0>(); }
        __syncthreads();

        const uint32_t Ahi = smb + s * STAGE_B + AHI_OFF;
        const uint32_t Aco = smb + s * STAGE_B + ACO_OFF;
        const uint32_t Bhi = smb + s * STAGE_B + BHI_OFF;
        const uint32_t Bco = smb + s * STAGE_B + BCO_OFF;

        // main term: fp16 k16, 2 steps
        #pragma unroll
        for (int ks = 0; ks < 2; ks++) {
            const uint32_t kb = ks * 32;
            uint32_t bh[8][2];
            #pragma unroll
            for (int h = 0; h < 4; h++) {
                uint32_t r[4];
                ldmx4(r, Bhi + (uint32_t)(wn * 64 + h * 16) * S80 + kb + b80);
                bh[h * 2 + 0][0] = r[0]; bh[h * 2 + 0][1] = r[1];
                bh[h * 2 + 1][0] = r[2]; bh[h * 2 + 1][1] = r[3];
            }
            #pragma unroll
            for (int mf = 0; mf < 4; mf++) {
                uint32_t ah[4];
                ldmx4(ah, Ahi + (uint32_t)(wm * 64 + mf * 16) * S80 + kb + a80);
                #pragma unroll
                for (int nf = 0; nf < 8; nf++) mma_f16(acc[mf][nf], ah, bh[nf]);
            }
        }
        // correction: bf16 k16 over [lo|hi]x[hi|lo], 4 steps
        #pragma unroll
        for (int ks = 0; ks < 4; ks++) {
            const uint32_t kb = ks * 32;
            uint32_t bc[8][2];
            #pragma unroll
            for (int h = 0; h < 4; h++) {
                uint32_t r[4];
                ldmx4(r, Bco + (uint32_t)(wn * 64 + h * 16) * S144 + kb + b144);
                bc[h * 2 + 0][0] = r[0]; bc[h * 2 + 0][1] = r[1];
                bc[h * 2 + 1][0] = r[2]; bc[h * 2 + 1][1] = r[3];
            }
            #pragma unroll
            for (int mf = 0; mf < 4; mf++) {
                uint32_t ac[4];
                ldmx4(ac, Aco + (uint32_t)(wm * 64 + mf * 16) * S144 + kb + a144);
                #pragma unroll
                for (int nf = 0; nf < 8; nf++) mma_bf16(acc[mf][nf], ac, bc[nf]);
            }
        }
        __syncthreads();
    }

    const int r0 = lane >> 2, c0 = (lane & 3) * 2;
    #pragma unroll
    for (int mf = 0; mf < 4; mf++) {
        int row = mbase + wm * 64 + mf * 16 + r0;
        #pragma unroll
        for (int nf = 0; nf < 8; nf++) {
            int col = jbase + wn * 64 + nf * 8 + c0;
            float* p = g_P + (size_t)row * NCAT + col;
            *(float2*)p                      = make_float2(acc[mf][nf][0], acc[mf][nf][1]);
            *(float2*)(p + (size_t)8 * NCAT) = make_float2(acc[mf][nf][2], acc[mf][nf][3]);
        }
    }
}

// ---------------- 4) combine -> fp16-hi + bf16-corr matcher layout ----------------
__global__ void combine_kernel(const float* __restrict__ b1, const float* __restrict__ b2,
                               const float* __restrict__ b3,
                               const float* __restrict__ qmask, const float* __restrict__ dmask) {
    int w = (blockIdx.x * blockDim.x + threadIdx.x) >> 5;
    int lane = threadIdx.x & 31;
    if (w >= (MD + MQ) * 3) return;
    int kidx = w % 3;
    int row  = w / 3;
    int prow, bb, pos, is_q;
    float mk;
    if (row < MD) { is_q = 0; prow = row; bb = row / DLEN; pos = row % DLEN; mk = dmask[row]; }
    else {
        is_q = 1;
        int q = row - MD;
        prow = QROW0 + q; bb = q / QLEN; pos = q % QLEN; mk = qmask[q];
    }
    const int len = is_q ? QLEN : DLEN;
    const float* bias = (kidx == 0) ? b1 : (kidx == 1 ? b2 : b3);
    const float* P0 = g_P + (size_t)prow * NCAT;
    int c = lane * 4;
    float4 v;
    if (kidx == 0) {
        v = *(const float4*)(P0 + c);
    } else if (kidx == 1) {
        float4 a = *(const float4*)(P0 + 128 + c);
        float4 b = *(const float4*)(P0 + NCAT + 256 + c);
        v = make_float4(a.x + b.x, a.y + b.y, a.z + b.z, a.w + b.w);
    } else {
        float4 a = *(const float4*)(P0 + 384 + c);
        float4 b = *(const float4*)(P0 + NCAT + 512 + c);
        float4 d = *(const float4*)(P0 + 2 * NCAT + 640 + c);
        v = make_float4(a.x + b.x + d.x, a.y + b.y + d.y, a.z + b.z + d.z, a.w + b.w + d.w);
    }
    float4 bv = *(const float4*)(bias + c);
    v.x = fmaxf(v.x + bv.x, 0.f);  v.y = fmaxf(v.y + bv.y, 0.f);
    v.z = fmaxf(v.z + bv.z, 0.f);  v.w = fmaxf(v.w + bv.w, 0.f);
    float ss = v.x * v.x + v.y * v.y + v.z * v.z + v.w * v.w;
    #pragma unroll
    for (int off = 16; off > 0; off >>= 1)
        ss += __shfl_xor_sync(0xffffffffu, ss, off);
    float sc = mk / (sqrtf(ss) + 1e-13f);
    if (pos >= len - kidx) sc = 0.f;
    v.x *= sc; v.y *= sc; v.z *= sc; v.w *= sc;

    float vv[4] = {v.x, v.y, v.z, v.w};
    __half h4[4];
    __nv_bfloat16 lo16[4], hi16[4];
    #pragma unroll
    for (int i = 0; i < 4; i++) {
        h4[i] = __float2half(vv[i]);
        float hf = __half2float(h4[i]);
        lo16[i] = __float2bfloat16(vv[i] - hf);
        hi16[i] = __float2bfloat16(hf);
    }

    int ch = lane >> 3, e8 = lane & 7;
    if (!is_q) {
        size_t blk = (((size_t)kidx * 32 + bb) * 4 + ch) * 1024 + pos;
        *(uint2*)(g_DH + blk * 80 + e8 * 8) = *(const uint2*)h4;
        char* co = g_DCO + blk * 144;
        *(uint2*)(co + e8 * 8)      = *(const uint2*)hi16;   // D corr: [hi|lo]
        *(uint2*)(co + 64 + e8 * 8) = *(const uint2*)lo16;
    } else {
        size_t blk = (((size_t)kidx * 32 + bb) * 4 + ch) * 32 + pos;
        *(uint2*)(g_QH + blk * 80 + e8 * 8) = *(const uint2*)h4;
        char* co = g_QCO + blk * 144;
        *(uint2*)(co + e8 * 8)      = *(const uint2*)lo16;   // Q corr: [lo|hi]
        *(uint2*)(co + 64 + e8 * 8) = *(const uint2*)hi16;
    }
}

// ---------------- 5) tensor matcher ----------------
__device__ __forceinline__ void accum_bins(float* h, float s) {
    float d1 = s - 1.0f;
    if (fabsf(d1) < 0.012f)
        h[0] += __expf(-500000.f * d1 * d1);
    float d0 = s - 0.95f;
    float g = __expf(-50.f * d0 * d0);
    float t = __expf(-10.f * d0) * 0.60653065971f;
    #pragma unroll
    for (int j = 1; j <= 20; j++) {
        h[j] += g;
        g *= t;
        t *= 0.36787944117f;
    }
}

#define MQH_SZ  10240
#define MQC_SZ  18432
#define MDH_SZ  20480
#define MDC_SZ  36864
#define MD_STG  (MDH_SZ + MDC_SZ)                 // 57344
#define SMEM_M  (MQH_SZ + MQC_SZ + 2 * MD_STG)    // 143360

__global__ void __launch_bounds__(256, 1) matcher_kernel(const float* __restrict__ qmasks) {
    extern __shared__ char sm[];
    __shared__ float H[8][16][21];
    __shared__ float KW[32][21];

    const int b    = blockIdx.x;
    const int pair = blockIdx.y;
    const int qk   = pair / 3, dk = pair % 3;
    const int qlen_v = QLEN - qk;
    const int tid = threadIdx.x, wid = tid >> 5, lane = tid & 31;
    const int mh = wid & 1, nh = wid >> 1;

    const uint32_t smb = smem_u32(sm);
    const uint32_t QHIs = smb, QCOs = smb + MQH_SZ;
    const uint32_t DST  = smb + MQH_SZ + MQC_SZ;

    const char* qh_g = g_QH  + ((size_t)qk * 32 + b) * MQH_SZ;
    const char* qc_g = g_QCO + ((size_t)qk * 32 + b) * MQC_SZ;
    const char* dh_g = g_DH  + ((size_t)dk * 32 + b) * 327680;
    const char* dc_g = g_DCO + ((size_t)dk * 32 + b) * 589824;

    auto load_D = [&](int s, int dt) {
        const uint32_t st = DST + s * MD_STG;
        // hi: 1280 chunks (5/thread)
        #pragma unroll
        for (int i = 0; i < 5; i++) {
            int idx = tid + i * 256;
            int ch = idx / 320;
            cp16(st + idx * 16, dh_g + (size_t)ch * 76800 + (size_t)dt * 5120 + (size_t)idx * 16);
        }
        // corr: 2304 chunks (9/thread)
        #pragma unroll
        for (int i = 0; i < 9; i++) {
            int idx = tid + i * 256;
            if (idx < 2304) {
                int ch = idx / 576;
                cp16(st + MDH_SZ + idx * 16,
                     dc_g + (size_t)ch * 138240 + (size_t)dt * 9216 + (size_t)idx * 16);
            }
        }
        cp_commit();
    };

    // Q load: hi 640 chunks, corr 1152 chunks
    #pragma unroll
    for (int i = 0; i < 3; i++) {
        int idx = tid + i * 256;
        if (idx < 640) cp16(QHIs + idx * 16, qh_g + (size_t)idx * 16);
    }
    #pragma unroll
    for (int i = 0; i < 5; i++) {
        int idx = tid + i * 256;
        if (idx < 1152) cp16(QCOs + idx * 16, qc_g + (size_t)idx * 16);
    }
    load_D(0, 0);

    const int lg = lane >> 3, lj = lane & 7;
    const uint32_t a80  = (uint32_t)(lj + 8 * (lg & 1)) * S80  + (uint32_t)(lg >> 1) * 16;
    const uint32_t b80  = (uint32_t)(lj + 8 * (lg >> 1)) * S80  + (uint32_t)(lg & 1) * 16;
    const uint32_t a144 = (uint32_t)(lj + 8 * (lg & 1)) * S144 + (uint32_t)(lg >> 1) * 16;
    const uint32_t b144 = (uint32_t)(lj + 8 * (lg >> 1)) * S144 + (uint32_t)(lg & 1) * 16;
    const uint32_t qa_hi = QHIs + (uint32_t)(mh * 16) * S80 + a80;
    const uint32_t qa_co = QCOs + (uint32_t)(mh * 16) * S144 + a144;

    float hist[2][21];
    #pragma unroll
    for (int r = 0; r < 2; r++)
        #pragma unroll
        for (int j = 0; j < 21; j++) hist[r][j] = 0.f;

    for (int dt = 0; dt < 16; dt++) {
        const int s = dt & 1;
        if (dt + 1 < 16) { load_D(s ^ 1, dt + 1); cp_wait<1>(); }
        else             { cp_wait<0>(); }
        __syncthreads();

        const uint32_t Dhi = DST + s * MD_STG + (uint32_t)(nh * 16) * S80 + b80;
        const uint32_t Dco = DST + s * MD_STG + MDH_SZ + (uint32_t)(nh * 16) * S144 + b144;

        float acc[2][4];
        #pragma unroll
        for (int t = 0; t < 2; t++)
            #pragma unroll
            for (int k = 0; k < 4; k++) acc[t][k] = 0.f;

        #pragma unroll
        for (int kc = 0; kc < 4; kc++) {
            #pragma unroll
            for (int ks = 0; ks < 2; ks++) {
                uint32_t a[4], bb[4];
                ldmx4(a, qa_hi + kc * 2560 + ks * 32);
                ldmx4(bb, Dhi + kc * 5120 + ks * 32);
                mma_f16(acc[0], a, bb);
                mma_f16(acc[1], a, bb + 2);
            }
            #pragma unroll
            for (int ks = 0; ks < 4; ks++) {
                uint32_t a[4], bb[4];
                ldmx4(a, qa_co + kc * 4608 + ks * 32);
                ldmx4(bb, Dco + kc * 9216 + ks * 32);
                mma_bf16(acc[0], a, bb);
                mma_bf16(acc[1], a, bb + 2);
            }
        }
        #pragma unroll
        for (int t = 0; t < 2; t++) {
            accum_bins(hist[0], acc[t][0]);
            accum_bins(hist[0], acc[t][1]);
            accum_bins(hist[1], acc[t][2]);
            accum_bins(hist[1], acc[t][3]);
        }
        __syncthreads();
    }

    #pragma unroll
    for (int r = 0; r < 2; r++)
        #pragma unroll
        for (int j = 0; j < 21; j++) {
            float v = hist[r][j];
            v += __shfl_xor_sync(0xffffffffu, v, 1);
            v += __shfl_xor_sync(0xffffffffu, v, 2);
            hist[r][j] = v;
        }
    if ((lane & 3) == 0) {
        int lr = lane >> 2;
        #pragma unroll
        for (int j = 0; j < 21; j++) {
            H[wid][lr][j]     = hist[0][j];
            H[wid][lr + 8][j] = hist[1][j];
        }
    }
    __syncthreads();

    if (tid < 32) {
        int q = tid;
        int qmh = q >> 4, local = q & 15;
        float g0[21];
        #pragma unroll
        for (int j = 0; j < 21; j++) g0[j] = 0.f;
        accum_bins(g0, 0.f);
        float w = (q < qlen_v) ? qmasks[b * QLEN + q] : 0.f;
        #pragma unroll
        for (int j = 0; j < 21; j++) {
            float tot = 0.f;
            #pragma unroll
            for (int n = 0; n < 4; n++) tot += H[2 * n + qmh][local][j];
            tot -= (float)dk * g0[j];
            KW[q][j] = __logf(fmaxf(tot, 1e-10f)) * 0.01f * w;
        }
    }
    __syncthreads();
    if (tid < 21) {
        float s = 0.f;
        #pragma unroll
        for (int q = 0; q < 32; q++) s += KW[q][tid];
        g_LOGITS[b * 189 + pair * 21 + tid] = s;
    }
}

// ---------------- 6) score ----------------
__global__ void score_kernel(const float* __restrict__ dw, const float* __restrict__ db,
                             float* __restrict__ out, int out_size) {
    __shared__ float red[256];
    int b = blockIdx.x, tid = threadIdx.x;
    float v = (tid < 189) ? g_LOGITS[b * 189 + tid] * dw[tid] : 0.f;
    red[tid] = v;
    __syncthreads();
    for (int s = 128; s > 0; s >>= 1) {
        if (tid < s) red[tid] += red[tid + s];
        __syncthreads();
    }
    float score = red[0] + db[0];
    if (out_size >= B + B * 189) {
        if (tid == 0) out[b] = score;
        if (tid < 189) out[B + b * 189 + tid] = g_LOGITS[b * 189 + tid];
    } else if (out_size == B * 189) {
        if (tid < 189) out[b * 189 + tid] = g_LOGITS[b * 189 + tid];
    } else {
        if (tid == 0 && b < out_size) out[b] = score;
    }
}

// ---------------- launch ----------------
extern "C" void kernel_launch(void* const* d_in, const int* in_sizes, int n_in,
                              void* d_out, int out_size) {
    const int*   qids   = (const int*)d_in[0];
    const float* qmask  = (const float*)d_in[1];
    const int*   dids   = (const int*)d_in[2];
    const float* dmask  = (const float*)d_in[3];
    const float* emb    = (const float*)d_in[4];
    const float* w1     = (const float*)d_in[5];
    const float* b1     = (const float*)d_in[6];
    const float* w2     = (const float*)d_in[7];
    const float* b2     = (const float*)d_in[8];
    const float* w3     = (const float*)d_in[9];
    const float* b3     = (const float*)d_in[10];
    const float* dw     = (const float*)d_in[11];
    const float* db     = (const float*)d_in[12];
    float* out = (float*)d_out;

    cudaFuncSetAttribute(conv_mix_kernel, cudaFuncAttributeMaxDynamicSharedMemorySize, SMEM_DYN);
    cudaFuncSetAttribute(matcher_kernel, cudaFuncAttributeMaxDynamicSharedMemorySize, SMEM_M);

    gather_kernel<<<((MD + MQ) * 32 + 255) / 256, 256>>>(qids, dids, emb);
    wcat_kernel<<<(NCAT * KPAD + 255) / 256, 256>>>(w1, w2, w3);
    conv_mix_kernel<<<dim3(3, MTILES), 256, SMEM_DYN>>>();
    combine_kernel<<<((MD + MQ) * 3 * 32 + 255) / 256, 256>>>(b1, b2, b3, qmask, dmask);
    matcher_kernel<<<dim3(B, 9), 256, SMEM_M>>>(qmask);
    score_kernel<<<B, 256>>>(dw, db, out, out_size);
}

// round 11
// speedup vs baseline: 1.6266x; 1.1558x over previous
#include <cuda_runtime.h>
#include <cuda_bf16.h>
#include <cuda_fp16.h>
#include <cstdint>

#define B      32
#define QLEN   32
#define DLEN   1024
#define EMB    300
#define CDIM   128
#define MD     (B*DLEN)
#define MQ     (B*QLEN)

#define QROW0   32896
#define NROWS   33924
#define KPAD    320
#define NCAT    768
#define MTILES  264

// ---------------- device scratch (zero-initialized) ----------------
__device__ __half g_Eh[(size_t)NROWS * KPAD];   // fp16 hi
__device__ __half g_El[(size_t)NROWS * KPAD];   // fp16 residual (denormals OK)
__device__ __half g_Wh[NCAT * KPAD];
__device__ __half g_Wl[NCAT * KPAD];
__device__ float g_P[(size_t)NROWS * NCAT];
// matcher-ready packed: per (kidx,b): [chunk 0..3][row][64B of 32 fp16]
__device__ char g_DH[3ull * 32 * 4 * 1024 * 64];
__device__ char g_DL[3ull * 32 * 4 * 1024 * 64];
__device__ char g_QH[3ull * 32 * 4 * 32 * 64];
__device__ char g_QL[3ull * 32 * 4 * 32 * 64];
__device__ float g_LOGITS[B * 189];

__device__ __forceinline__ uint32_t smem_u32(const void* p) {
    uint32_t a;
    asm("{ .reg .u64 t; cvta.to.shared.u64 t, %1; cvt.u32.u64 %0, t; }" : "=r"(a) : "l"(p));
    return a;
}
__device__ __forceinline__ void ldmx4(uint32_t* r, uint32_t addr) {
    asm volatile("ldmatrix.sync.aligned.m8n8.x4.shared.b16 {%0,%1,%2,%3}, [%4];"
                 : "=r"(r[0]), "=r"(r[1]), "=r"(r[2]), "=r"(r[3]) : "r"(addr));
}
__device__ __forceinline__ void mma_f16(float* c, const uint32_t* a, const uint32_t* b) {
    asm volatile("mma.sync.aligned.m16n8k16.row.col.f32.f16.f16.f32 "
                 "{%0,%1,%2,%3}, {%4,%5,%6,%7}, {%8,%9}, {%0,%1,%2,%3};"
                 : "+f"(c[0]), "+f"(c[1]), "+f"(c[2]), "+f"(c[3])
                 : "r"(a[0]), "r"(a[1]), "r"(a[2]), "r"(a[3]), "r"(b[0]), "r"(b[1]));
}
__device__ __forceinline__ void cp16(uint32_t dst, const void* src) {
    asm volatile("cp.async.cg.shared.global [%0], [%1], 16;" :: "r"(dst), "l"(src));
}
__device__ __forceinline__ void cp_commit() {
    asm volatile("cp.async.commit_group;" ::: "memory");
}
template <int N>
__device__ __forceinline__ void cp_wait() {
    asm volatile("cp.async.wait_group %0;" :: "n"(N) : "memory");
}

// ---------------- 1) fused gather + wcat ----------------
#define GATHER_BLOCKS  (((MD + MQ) * 32) / 256)      // 4224
#define WCAT_ELEMS     (NCAT * KPAD)                 // 245760
#define WCAT_BLOCKS    (WCAT_ELEMS / 256)            // 960

__global__ void prep_kernel(const int* __restrict__ qids, const int* __restrict__ dids,
                            const float* __restrict__ emb,
                            const float* __restrict__ w1, const float* __restrict__ w2,
                            const float* __restrict__ w3) {
    if (blockIdx.x < GATHER_BLOCKS) {
        int w = (blockIdx.x * blockDim.x + threadIdx.x) >> 5;
        int lane = threadIdx.x & 31;
        if (w >= MD + MQ) return;
        int id, drow;
        if (w < MD) { id = dids[w]; drow = w; }
        else        { id = qids[w - MD]; drow = QROW0 + (w - MD); }
        const float* src = emb + (size_t)id * EMB;
        __half* dh = g_Eh + (size_t)drow * KPAD;
        __half* dl = g_El + (size_t)drow * KPAD;
        #pragma unroll
        for (int i = 0; i < 10; i++) {
            int c = lane + i * 32;
            float x = (c < EMB) ? src[c] : 0.f;
            __half h = __float2half(x);
            dh[c] = h;
            dl[c] = __float2half(x - __half2float(h));
        }
    } else {
        int idx = (blockIdx.x - GATHER_BLOCKS) * 256 + threadIdx.x;
        if (idx >= WCAT_ELEMS) return;
        int j = idx / KPAD, e = idx % KPAD;
        int g = j >> 7, c = j & 127;
        float v = 0.f;
        if (e < EMB) {
            if (g == 0)      v = w1[c * EMB + e];
            else if (g == 1) v = w2[(c * EMB + e) * 2 + 0];
            else if (g == 2) v = w2[(c * EMB + e) * 2 + 1];
            else             v = w3[(c * EMB + e) * 3 + (g - 3)];
        }
        __half h = __float2half(v);
        g_Wh[idx] = h;
        g_Wl[idx] = __float2half(v - __half2float(h));
    }
}

// ---------------- 2) conv GEMM: all-fp16 2-term split, 3-stage pipeline ----------------
// D = Ah*Bh + Al*Bh + Ah*Bl ; per CTA P[128 x 256], grid (3, 264)
#define S80   80
#define AH_OFF  0
#define AL_OFF  10240
#define BH_OFF  20480
#define BL_OFF  40960
#define STAGE_B 61440
#define SMEM_DYN (3 * STAGE_B)     // 184320

__global__ void __launch_bounds__(256, 1) conv_mix_kernel() {
    extern __shared__ char sm[];
    const int mt = blockIdx.y, pass = blockIdx.x;
    const int mbase = (mt < 256) ? mt * 128 : QROW0 + (mt - 256) * 128;
    const int jbase = pass * 256;
    const int tid = threadIdx.x, wid = tid >> 5, lane = tid & 31;
    const int wm = wid & 1, wn = wid >> 1;

    const uint32_t smb = smem_u32(sm);
    const char* Ah_src = (const char*)(g_Eh + (size_t)mbase * KPAD);
    const char* Al_src = (const char*)(g_El + (size_t)mbase * KPAD);
    const char* Bh_src = (const char*)(g_Wh + (size_t)jbase * KPAD);
    const char* Bl_src = (const char*)(g_Wl + (size_t)jbase * KPAD);

    auto load_stage = [&](int s, int kc) {
        const uint32_t st = smb + s * STAGE_B;
        const int kof = kc * 64;                     // byte offset of chunk in a 640B row
        // A tiles: 128 rows x 64B -> 512 cp16 each (2/thread)
        #pragma unroll
        for (int i = 0; i < 2; i++) {
            int idx = tid + i * 256;
            int r = idx >> 2, c = idx & 3;
            uint32_t doff = (uint32_t)r * S80 + c * 16;
            const char* so = (const char*)0 + (size_t)r * 640 + kof + c * 16;
            cp16(st + AH_OFF + doff, Ah_src + (size_t)so);
            cp16(st + AL_OFF + doff, Al_src + (size_t)so);
        }
        // B tiles: 256 rows -> 1024 cp16 each (4/thread)
        #pragma unroll
        for (int i = 0; i < 4; i++) {
            int idx = tid + i * 256;
            int r = idx >> 2, c = idx & 3;
            uint32_t doff = (uint32_t)r * S80 + c * 16;
            size_t so = (size_t)r * 640 + kof + c * 16;
            cp16(st + BH_OFF + doff, Bh_src + so);
            cp16(st + BL_OFF + doff, Bl_src + so);
        }
        cp_commit();
    };

    float acc[4][8][4];
    #pragma unroll
    for (int i = 0; i < 4; i++)
        #pragma unroll
        for (int j = 0; j < 8; j++)
            #pragma unroll
            for (int k = 0; k < 4; k++) acc[i][j][k] = 0.f;

    const int lg = lane >> 3, lj = lane & 7;
    const uint32_t a80 = (uint32_t)(lj + 8 * (lg & 1)) * S80 + (uint32_t)(lg >> 1) * 16;
    const uint32_t b80 = (uint32_t)(lj + 8 * (lg >> 1)) * S80 + (uint32_t)(lg & 1) * 16;

    load_stage(0, 0);
    load_stage(1, 1);

    for (int kc = 0; kc < 10; kc++) {
        const int s = kc % 3;
        if (kc + 2 < 10)      { load_stage((kc + 2) % 3, kc + 2); cp_wait<2>(); }
        else if (kc + 1 < 10) { cp_wait<1>(); }
        else                  { cp_wait<0>(); }
        __syncthreads();

        const uint32_t AHs = smb + s * STAGE_B + AH_OFF;
        const uint32_t ALs = smb + s * STAGE_B + AL_OFF;
        const uint32_t BHs = smb + s * STAGE_B + BH_OFF;
        const uint32_t BLs = smb + s * STAGE_B + BL_OFF;

        #pragma unroll
        for (int ks = 0; ks < 2; ks++) {
            const uint32_t kb = ks * 32;
            uint32_t bh[8][2], bl[8][2];
            #pragma unroll
            for (int h = 0; h < 4; h++) {
                uint32_t off = (uint32_t)(wn * 64 + h * 16) * S80 + kb + b80;
                uint32_t r[4];
                ldmx4(r, BHs + off);
                bh[h * 2 + 0][0] = r[0]; bh[h * 2 + 0][1] = r[1];
                bh[h * 2 + 1][0] = r[2]; bh[h * 2 + 1][1] = r[3];
                ldmx4(r, BLs + off);
                bl[h * 2 + 0][0] = r[0]; bl[h * 2 + 0][1] = r[1];
                bl[h * 2 + 1][0] = r[2]; bl[h * 2 + 1][1] = r[3];
            }
            // main (h*h) + corr2 (h*l) share A-h fragments
            #pragma unroll
            for (int mf = 0; mf < 4; mf++) {
                uint32_t off = (uint32_t)(wm * 64 + mf * 16) * S80 + kb + a80;
                uint32_t ah[4];
                ldmx4(ah, AHs + off);
                #pragma unroll
                for (int nf = 0; nf < 8; nf++) {
                    mma_f16(acc[mf][nf], ah, bh[nf]);
                    mma_f16(acc[mf][nf], ah, bl[nf]);
                }
            }
            // corr1 (l*h)
            #pragma unroll
            for (int mf = 0; mf < 4; mf++) {
                uint32_t off = (uint32_t)(wm * 64 + mf * 16) * S80 + kb + a80;
                uint32_t al[4];
                ldmx4(al, ALs + off);
                #pragma unroll
                for (int nf = 0; nf < 8; nf++) mma_f16(acc[mf][nf], al, bh[nf]);
            }
        }
        __syncthreads();
    }

    const int r0 = lane >> 2, c0 = (lane & 3) * 2;
    #pragma unroll
    for (int mf = 0; mf < 4; mf++) {
        int row = mbase + wm * 64 + mf * 16 + r0;
        #pragma unroll
        for (int nf = 0; nf < 8; nf++) {
            int col = jbase + wn * 64 + nf * 8 + c0;
            float* p = g_P + (size_t)row * NCAT + col;
            *(float2*)p                      = make_float2(acc[mf][nf][0], acc[mf][nf][1]);
            *(float2*)(p + (size_t)8 * NCAT) = make_float2(acc[mf][nf][2], acc[mf][nf][3]);
        }
    }
}

// ---------------- 3) combine -> packed fp16 h/l matcher layout ----------------
__global__ void combine_kernel(const float* __restrict__ b1, const float* __restrict__ b2,
                               const float* __restrict__ b3,
                               const float* __restrict__ qmask, const float* __restrict__ dmask) {
    int w = (blockIdx.x * blockDim.x + threadIdx.x) >> 5;
    int lane = threadIdx.x & 31;
    if (w >= (MD + MQ) * 3) return;
    int kidx = w % 3;
    int row  = w / 3;
    int prow, bb, pos, is_q;
    float mk;
    if (row < MD) { is_q = 0; prow = row; bb = row / DLEN; pos = row % DLEN; mk = dmask[row]; }
    else {
        is_q = 1;
        int q = row - MD;
        prow = QROW0 + q; bb = q / QLEN; pos = q % QLEN; mk = qmask[q];
    }
    const int len = is_q ? QLEN : DLEN;
    const float* bias = (kidx == 0) ? b1 : (kidx == 1 ? b2 : b3);
    const float* P0 = g_P + (size_t)prow * NCAT;
    int c = lane * 4;
    float4 v;
    if (kidx == 0) {
        v = *(const float4*)(P0 + c);
    } else if (kidx == 1) {
        float4 a = *(const float4*)(P0 + 128 + c);
        float4 b = *(const float4*)(P0 + NCAT + 256 + c);
        v = make_float4(a.x + b.x, a.y + b.y, a.z + b.z, a.w + b.w);
    } else {
        float4 a = *(const float4*)(P0 + 384 + c);
        float4 b = *(const float4*)(P0 + NCAT + 512 + c);
        float4 d = *(const float4*)(P0 + 2 * NCAT + 640 + c);
        v = make_float4(a.x + b.x + d.x, a.y + b.y + d.y, a.z + b.z + d.z, a.w + b.w + d.w);
    }
    float4 bv = *(const float4*)(bias + c);
    v.x = fmaxf(v.x + bv.x, 0.f);  v.y = fmaxf(v.y + bv.y, 0.f);
    v.z = fmaxf(v.z + bv.z, 0.f);  v.w = fmaxf(v.w + bv.w, 0.f);
    float ss = v.x * v.x + v.y * v.y + v.z * v.z + v.w * v.w;
    #pragma unroll
    for (int off = 16; off > 0; off >>= 1)
        ss += __shfl_xor_sync(0xffffffffu, ss, off);
    float sc = mk / (sqrtf(ss) + 1e-13f);
    if (pos >= len - kidx) sc = 0.f;
    v.x *= sc; v.y *= sc; v.z *= sc; v.w *= sc;

    float vv[4] = {v.x, v.y, v.z, v.w};
    __half h4[4], l4[4];
    #pragma unroll
    for (int i = 0; i < 4; i++) {
        h4[i] = __float2half(vv[i]);
        l4[i] = __float2half(vv[i] - __half2float(h4[i]));
    }

    int ch = lane >> 3, e8 = lane & 7;
    if (!is_q) {
        size_t blk = (((size_t)kidx * 32 + bb) * 4 + ch) * 1024 + pos;
        *(uint2*)(g_DH + blk * 64 + e8 * 8) = *(const uint2*)h4;
        *(uint2*)(g_DL + blk * 64 + e8 * 8) = *(const uint2*)l4;
    } else {
        size_t blk = (((size_t)kidx * 32 + bb) * 4 + ch) * 32 + pos;
        *(uint2*)(g_QH + blk * 64 + e8 * 8) = *(const uint2*)h4;
        *(uint2*)(g_QL + blk * 64 + e8 * 8) = *(const uint2*)l4;
    }
}

// ---------------- 4) tensor matcher (fp16 2-term) ----------------
__device__ __forceinline__ void accum_bins(float* h, float s) {
    float d1 = s - 1.0f;
    if (fabsf(d1) < 0.012f)
        h[0] += __expf(-500000.f * d1 * d1);
    float d0 = s - 0.95f;
    float g = __expf(-50.f * d0 * d0);
    float t = __expf(-10.f * d0) * 0.60653065971f;
    #pragma unroll
    for (int j = 1; j <= 20; j++) {
        h[j] += g;
        g *= t;
        t *= 0.36787944117f;
    }
}

#define MQT_SZ  10240                      // 4 chunks x 32 rows x 80
#define MDT_SZ  20480                      // 4 chunks x 64 rows x 80
#define MD_STG  (2 * MDT_SZ)               // h + l per stage
#define SMEM_M  (2 * MQT_SZ + 2 * MD_STG)  // 102400

__global__ void __launch_bounds__(256, 1) matcher_kernel(const float* __restrict__ qmasks) {
    extern __shared__ char sm[];
    __shared__ float H[8][16][21];
    __shared__ float KW[32][21];

    const int b    = blockIdx.x;
    const int pair = blockIdx.y;
    const int qk   = pair / 3, dk = pair % 3;
    const int qlen_v = QLEN - qk;
    const int tid = threadIdx.x, wid = tid >> 5, lane = tid & 31;
    const int mh = wid & 1, nh = wid >> 1;

    const uint32_t smb = smem_u32(sm);
    const uint32_t QHs = smb, QLs = smb + MQT_SZ;
    const uint32_t DST = smb + 2 * MQT_SZ;

    const char* qh_g = g_QH + ((size_t)qk * 32 + b) * 8192;
    const char* ql_g = g_QL + ((size_t)qk * 32 + b) * 8192;
    const char* dh_g = g_DH + ((size_t)dk * 32 + b) * 262144;
    const char* dl_g = g_DL + ((size_t)dk * 32 + b) * 262144;

    auto load_D = [&](int s, int dt) {
        const uint32_t st = DST + s * MD_STG;
        #pragma unroll
        for (int i = 0; i < 4; i++) {
            int idx = tid + i * 256;              // 1024 chunks per array
            int ch = idx >> 8, rem = idx & 255;
            int rr = rem >> 2, c = rem & 3;
            size_t go = ((size_t)ch * 1024 + (size_t)dt * 64 + rr) * 64 + c * 16;
            uint32_t doff = (uint32_t)ch * (64 * S80) + (uint32_t)rr * S80 + c * 16;
            cp16(st + doff, dh_g + go);
            cp16(st + MDT_SZ + doff, dl_g + go);
        }
        cp_commit();
    };

    // Q load: 512 chunks per array (2/thread)
    #pragma unroll
    for (int i = 0; i < 2; i++) {
        int idx = tid + i * 256;
        int ch = idx >> 7, rem = idx & 127;
        int rr = rem >> 2, c = rem & 3;
        size_t go = ((size_t)ch * 32 + rr) * 64 + c * 16;
        uint32_t doff = (uint32_t)ch * (32 * S80) + (uint32_t)rr * S80 + c * 16;
        cp16(QHs + doff, qh_g + go);
        cp16(QLs + doff, ql_g + go);
    }
    load_D(0, 0);

    const int lg = lane >> 3, lj = lane & 7;
    const uint32_t a80 = (uint32_t)(lj + 8 * (lg & 1)) * S80 + (uint32_t)(lg >> 1) * 16;
    const uint32_t b80 = (uint32_t)(lj + 8 * (lg >> 1)) * S80 + (uint32_t)(lg & 1) * 16;
    const uint32_t qa_h = QHs + (uint32_t)(mh * 16) * S80 + a80;
    const uint32_t qa_l = QLs + (uint32_t)(mh * 16) * S80 + a80;

    float hist[2][21];
    #pragma unroll
    for (int r = 0; r < 2; r++)
        #pragma unroll
        for (int j = 0; j < 21; j++) hist[r][j] = 0.f;

    for (int dt = 0; dt < 16; dt++) {
        const int s = dt & 1;
        if (dt + 1 < 16) { load_D(s ^ 1, dt + 1); cp_wait<1>(); }
        else             { cp_wait<0>(); }
        __syncthreads();

        const uint32_t Dh = DST + s * MD_STG + (uint32_t)(nh * 16) * S80 + b80;
        const uint32_t Dl = Dh + MDT_SZ;

        float acc[2][4];
        #pragma unroll
        for (int t = 0; t < 2; t++)
            #pragma unroll
            for (int k = 0; k < 4; k++) acc[t][k] = 0.f;

        #pragma unroll
        for (int kc = 0; kc < 4; kc++) {
            #pragma unroll
            for (int ks = 0; ks < 2; ks++) {
                uint32_t ah[4], al[4], bh[4], bl[4];
                ldmx4(ah, qa_h + kc * 2560 + ks * 32);
                ldmx4(al, qa_l + kc * 2560 + ks * 32);
                ldmx4(bh, Dh + kc * 5120 + ks * 32);
                ldmx4(bl, Dl + kc * 5120 + ks * 32);
                mma_f16(acc[0], ah, bh);  mma_f16(acc[1], ah, bh + 2);
                mma_f16(acc[0], al, bh);  mma_f16(acc[1], al, bh + 2);
                mma_f16(acc[0], ah, bl);  mma_f16(acc[1], ah, bl + 2);
            }
        }
        #pragma unroll
        for (int t = 0; t < 2; t++) {
            accum_bins(hist[0], acc[t][0]);
            accum_bins(hist[0], acc[t][1]);
            accum_bins(hist[1], acc[t][2]);
            accum_bins(hist[1], acc[t][3]);
        }
        __syncthreads();
    }

    #pragma unroll
    for (int r = 0; r < 2; r++)
        #pragma unroll
        for (int j = 0; j < 21; j++) {
            float v = hist[r][j];
            v += __shfl_xor_sync(0xffffffffu, v, 1);
            v += __shfl_xor_sync(0xffffffffu, v, 2);
            hist[r][j] = v;
        }
    if ((lane & 3) == 0) {
        int lr = lane >> 2;
        #pragma unroll
        for (int j = 0; j < 21; j++) {
            H[wid][lr][j]     = hist[0][j];
            H[wid][lr + 8][j] = hist[1][j];
        }
    }
    __syncthreads();

    if (tid < 32) {
        int q = tid;
        int qmh = q >> 4, local = q & 15;
        float g0[21];
        #pragma unroll
        for (int j = 0; j < 21; j++) g0[j] = 0.f;
        accum_bins(g0, 0.f);
        float w = (q < qlen_v) ? qmasks[b * QLEN + q] : 0.f;
        #pragma unroll
        for (int j = 0; j < 21; j++) {
            float tot = 0.f;
            #pragma unroll
            for (int n = 0; n < 4; n++) tot += H[2 * n + qmh][local][j];
            tot -= (float)dk * g0[j];
            KW[q][j] = __logf(fmaxf(tot, 1e-10f)) * 0.01f * w;
        }
    }
    __syncthreads();
    if (tid < 21) {
        float s = 0.f;
        #pragma unroll
        for (int q = 0; q < 32; q++) s += KW[q][tid];
        g_LOGITS[b * 189 + pair * 21 + tid] = s;
    }
}

// ---------------- 5) score ----------------
__global__ void score_kernel(const float* __restrict__ dw, const float* __restrict__ db,
                             float* __restrict__ out, int out_size) {
    __shared__ float red[256];
    int b = blockIdx.x, tid = threadIdx.x;
    float v = (tid < 189) ? g_LOGITS[b * 189 + tid] * dw[tid] : 0.f;
    red[tid] = v;
    __syncthreads();
    for (int s = 128; s > 0; s >>= 1) {
        if (tid < s) red[tid] += red[tid + s];
        __syncthreads();
    }
    float score = red[0] + db[0];
    if (out_size >= B + B * 189) {
        if (tid == 0) out[b] = score;
        if (tid < 189) out[B + b * 189 + tid] = g_LOGITS[b * 189 + tid];
    } else if (out_size == B * 189) {
        if (tid < 189) out[b * 189 + tid] = g_LOGITS[b * 189 + tid];
    } else {
        if (tid == 0 && b < out_size) out[b] = score;
    }
}

// ---------------- launch ----------------
extern "C" void kernel_launch(void* const* d_in, const int* in_sizes, int n_in,
                              void* d_out, int out_size) {
    const int*   qids   = (const int*)d_in[0];
    const float* qmask  = (const float*)d_in[1];
    const int*   dids   = (const int*)d_in[2];
    const float* dmask  = (const float*)d_in[3];
    const float* emb    = (const float*)d_in[4];
    const float* w1     = (const float*)d_in[5];
    const float* b1     = (const float*)d_in[6];
    const float* w2     = (const float*)d_in[7];
    const float* b2     = (const float*)d_in[8];
    const float* w3     = (const float*)d_in[9];
    const float* b3     = (const float*)d_in[10];
    const float* dw     = (const float*)d_in[11];
    const float* db     = (const float*)d_in[12];
    float* out = (float*)d_out;

    cudaFuncSetAttribute(conv_mix_kernel, cudaFuncAttributeMaxDynamicSharedMemorySize, SMEM_DYN);
    cudaFuncSetAttribute(matcher_kernel, cudaFuncAttributeMaxDynamicSharedMemorySize, SMEM_M);

    prep_kernel<<<GATHER_BLOCKS + WCAT_BLOCKS, 256>>>(qids, dids, emb, w1, w2, w3);
    conv_mix_kernel<<<dim3(3, MTILES), 256, SMEM_DYN>>>();
    combine_kernel<<<((MD + MQ) * 3 * 32 + 255) / 256, 256>>>(b1, b2, b3, qmask, dmask);
    matcher_kernel<<<dim3(B, 9), 256, SMEM_M>>>(qmask);
    score_kernel<<<B, 256>>>(dw, db, out, out_size);
}

// round 12
// speedup vs baseline: 1.6477x; 1.0130x over previous
#include <cuda_runtime.h>
#include <cuda_bf16.h>
#include <cuda_fp16.h>
#include <cstdint>

#define B      32
#define QLEN   32
#define DLEN   1024
#define EMB    300
#define CDIM   128
#define MD     (B*DLEN)
#define MQ     (B*QLEN)

#define QROW0   32896
#define NROWS   33924
#define KPAD    320
#define NCAT    768
#define MTILES  264

// ---------------- device scratch (zero-initialized) ----------------
__device__ __half g_Eh[(size_t)NROWS * KPAD];   // fp16 hi
__device__ __half g_El[(size_t)NROWS * KPAD];   // fp16 residual (denormals OK)
__device__ __half g_Wh[NCAT * KPAD];
__device__ __half g_Wl[NCAT * KPAD];
__device__ float g_P[(size_t)NROWS * NCAT];
// matcher-ready packed: per (kidx,b): [chunk 0..3][row][64B of 32 fp16]
__device__ char g_DH[3ull * 32 * 4 * 1024 * 64];
__device__ char g_DL[3ull * 32 * 4 * 1024 * 64];
__device__ char g_QH[3ull * 32 * 4 * 32 * 64];
__device__ char g_QL[3ull * 32 * 4 * 32 * 64];
__device__ float g_HISTP[9ull * 32 * 4 * 32 * 21];   // partial histograms
__device__ float g_LOGITS[B * 189];

__device__ __forceinline__ uint32_t smem_u32(const void* p) {
    uint32_t a;
    asm("{ .reg .u64 t; cvta.to.shared.u64 t, %1; cvt.u32.u64 %0, t; }" : "=r"(a) : "l"(p));
    return a;
}
__device__ __forceinline__ void ldmx4(uint32_t* r, uint32_t addr) {
    asm volatile("ldmatrix.sync.aligned.m8n8.x4.shared.b16 {%0,%1,%2,%3}, [%4];"
                 : "=r"(r[0]), "=r"(r[1]), "=r"(r[2]), "=r"(r[3]) : "r"(addr));
}
__device__ __forceinline__ void mma_f16(float* c, const uint32_t* a, const uint32_t* b) {
    asm volatile("mma.sync.aligned.m16n8k16.row.col.f32.f16.f16.f32 "
                 "{%0,%1,%2,%3}, {%4,%5,%6,%7}, {%8,%9}, {%0,%1,%2,%3};"
                 : "+f"(c[0]), "+f"(c[1]), "+f"(c[2]), "+f"(c[3])
                 : "r"(a[0]), "r"(a[1]), "r"(a[2]), "r"(a[3]), "r"(b[0]), "r"(b[1]));
}
__device__ __forceinline__ void cp16(uint32_t dst, const void* src) {
    asm volatile("cp.async.cg.shared.global [%0], [%1], 16;" :: "r"(dst), "l"(src));
}
__device__ __forceinline__ void cp_commit() {
    asm volatile("cp.async.commit_group;" ::: "memory");
}
template <int N>
__device__ __forceinline__ void cp_wait() {
    asm volatile("cp.async.wait_group %0;" :: "n"(N) : "memory");
}

// ---------------- 1) fused gather + wcat ----------------
#define GATHER_BLOCKS  (((MD + MQ) * 32) / 256)      // 4224
#define WCAT_ELEMS     (NCAT * KPAD)                 // 245760
#define WCAT_BLOCKS    (WCAT_ELEMS / 256)            // 960

__global__ void prep_kernel(const int* __restrict__ qids, const int* __restrict__ dids,
                            const float* __restrict__ emb,
                            const float* __restrict__ w1, const float* __restrict__ w2,
                            const float* __restrict__ w3) {
    if (blockIdx.x < GATHER_BLOCKS) {
        int w = (blockIdx.x * blockDim.x + threadIdx.x) >> 5;
        int lane = threadIdx.x & 31;
        if (w >= MD + MQ) return;
        int id, drow;
        if (w < MD) { id = dids[w]; drow = w; }
        else        { id = qids[w - MD]; drow = QROW0 + (w - MD); }
        const float* src = emb + (size_t)id * EMB;
        __half* dh = g_Eh + (size_t)drow * KPAD;
        __half* dl = g_El + (size_t)drow * KPAD;
        #pragma unroll
        for (int i = 0; i < 10; i++) {
            int c = lane + i * 32;
            float x = (c < EMB) ? src[c] : 0.f;
            __half h = __float2half(x);
            dh[c] = h;
            dl[c] = __float2half(x - __half2float(h));
        }
    } else {
        int idx = (blockIdx.x - GATHER_BLOCKS) * 256 + threadIdx.x;
        if (idx >= WCAT_ELEMS) return;
        int j = idx / KPAD, e = idx % KPAD;
        int g = j >> 7, c = j & 127;
        float v = 0.f;
        if (e < EMB) {
            if (g == 0)      v = w1[c * EMB + e];
            else if (g == 1) v = w2[(c * EMB + e) * 2 + 0];
            else if (g == 2) v = w2[(c * EMB + e) * 2 + 1];
            else             v = w3[(c * EMB + e) * 3 + (g - 3)];
        }
        __half h = __float2half(v);
        g_Wh[idx] = h;
        g_Wl[idx] = __float2half(v - __half2float(h));
    }
}

// ---------------- 2) conv GEMM: all-fp16 2-term split, 3-stage pipeline ----------------
#define S80   80
#define AH_OFF  0
#define AL_OFF  10240
#define BH_OFF  20480
#define BL_OFF  40960
#define STAGE_B 61440
#define SMEM_DYN (3 * STAGE_B)     // 184320

__global__ void __launch_bounds__(256, 1) conv_mix_kernel() {
    extern __shared__ char sm[];
    const int mt = blockIdx.y, pass = blockIdx.x;
    const int mbase = (mt < 256) ? mt * 128 : QROW0 + (mt - 256) * 128;
    const int jbase = pass * 256;
    const int tid = threadIdx.x, wid = tid >> 5, lane = tid & 31;
    const int wm = wid & 1, wn = wid >> 1;

    const uint32_t smb = smem_u32(sm);
    const char* Ah_src = (const char*)(g_Eh + (size_t)mbase * KPAD);
    const char* Al_src = (const char*)(g_El + (size_t)mbase * KPAD);
    const char* Bh_src = (const char*)(g_Wh + (size_t)jbase * KPAD);
    const char* Bl_src = (const char*)(g_Wl + (size_t)jbase * KPAD);

    auto load_stage = [&](int s, int kc) {
        const uint32_t st = smb + s * STAGE_B;
        const int kof = kc * 64;
        #pragma unroll
        for (int i = 0; i < 2; i++) {
            int idx = tid + i * 256;
            int r = idx >> 2, c = idx & 3;
            uint32_t doff = (uint32_t)r * S80 + c * 16;
            size_t so = (size_t)r * 640 + kof + c * 16;
            cp16(st + AH_OFF + doff, Ah_src + so);
            cp16(st + AL_OFF + doff, Al_src + so);
        }
        #pragma unroll
        for (int i = 0; i < 4; i++) {
            int idx = tid + i * 256;
            int r = idx >> 2, c = idx & 3;
            uint32_t doff = (uint32_t)r * S80 + c * 16;
            size_t so = (size_t)r * 640 + kof + c * 16;
            cp16(st + BH_OFF + doff, Bh_src + so);
            cp16(st + BL_OFF + doff, Bl_src + so);
        }
        cp_commit();
    };

    float acc[4][8][4];
    #pragma unroll
    for (int i = 0; i < 4; i++)
        #pragma unroll
        for (int j = 0; j < 8; j++)
            #pragma unroll
            for (int k = 0; k < 4; k++) acc[i][j][k] = 0.f;

    const int lg = lane >> 3, lj = lane & 7;
    const uint32_t a80 = (uint32_t)(lj + 8 * (lg & 1)) * S80 + (uint32_t)(lg >> 1) * 16;
    const uint32_t b80 = (uint32_t)(lj + 8 * (lg >> 1)) * S80 + (uint32_t)(lg & 1) * 16;

    load_stage(0, 0);
    load_stage(1, 1);

    for (int kc = 0; kc < 10; kc++) {
        const int s = kc % 3;
        if (kc + 2 < 10)      { load_stage((kc + 2) % 3, kc + 2); cp_wait<2>(); }
        else if (kc + 1 < 10) { cp_wait<1>(); }
        else                  { cp_wait<0>(); }
        __syncthreads();

        const uint32_t AHs = smb + s * STAGE_B + AH_OFF;
        const uint32_t ALs = smb + s * STAGE_B + AL_OFF;
        const uint32_t BHs = smb + s * STAGE_B + BH_OFF;
        const uint32_t BLs = smb + s * STAGE_B + BL_OFF;

        #pragma unroll
        for (int ks = 0; ks < 2; ks++) {
            const uint32_t kb = ks * 32;
            uint32_t bh[8][2], bl[8][2];
            #pragma unroll
            for (int h = 0; h < 4; h++) {
                uint32_t off = (uint32_t)(wn * 64 + h * 16) * S80 + kb + b80;
                uint32_t r[4];
                ldmx4(r, BHs + off);
                bh[h * 2 + 0][0] = r[0]; bh[h * 2 + 0][1] = r[1];
                bh[h * 2 + 1][0] = r[2]; bh[h * 2 + 1][1] = r[3];
                ldmx4(r, BLs + off);
                bl[h * 2 + 0][0] = r[0]; bl[h * 2 + 0][1] = r[1];
                bl[h * 2 + 1][0] = r[2]; bl[h * 2 + 1][1] = r[3];
            }
            #pragma unroll
            for (int mf = 0; mf < 4; mf++) {
                uint32_t off = (uint32_t)(wm * 64 + mf * 16) * S80 + kb + a80;
                uint32_t ah[4];
                ldmx4(ah, AHs + off);
                #pragma unroll
                for (int nf = 0; nf < 8; nf++) {
                    mma_f16(acc[mf][nf], ah, bh[nf]);
                    mma_f16(acc[mf][nf], ah, bl[nf]);
                }
            }
            #pragma unroll
            for (int mf = 0; mf < 4; mf++) {
                uint32_t off = (uint32_t)(wm * 64 + mf * 16) * S80 + kb + a80;
                uint32_t al[4];
                ldmx4(al, ALs + off);
                #pragma unroll
                for (int nf = 0; nf < 8; nf++) mma_f16(acc[mf][nf], al, bh[nf]);
            }
        }
        __syncthreads();
    }

    const int r0 = lane >> 2, c0 = (lane & 3) * 2;
    #pragma unroll
    for (int mf = 0; mf < 4; mf++) {
        int row = mbase + wm * 64 + mf * 16 + r0;
        #pragma unroll
        for (int nf = 0; nf < 8; nf++) {
            int col = jbase + wn * 64 + nf * 8 + c0;
            float* p = g_P + (size_t)row * NCAT + col;
            *(float2*)p                      = make_float2(acc[mf][nf][0], acc[mf][nf][1]);
            *(float2*)(p + (size_t)8 * NCAT) = make_float2(acc[mf][nf][2], acc[mf][nf][3]);
        }
    }
}

// ---------------- 3) combine -> packed fp16 h/l matcher layout ----------------
__global__ void combine_kernel(const float* __restrict__ b1, const float* __restrict__ b2,
                               const float* __restrict__ b3,
                               const float* __restrict__ qmask, const float* __restrict__ dmask) {
    int w = (blockIdx.x * blockDim.x + threadIdx.x) >> 5;
    int lane = threadIdx.x & 31;
    if (w >= (MD + MQ) * 3) return;
    int kidx = w % 3;
    int row  = w / 3;
    int prow, bb, pos, is_q;
    float mk;
    if (row < MD) { is_q = 0; prow = row; bb = row / DLEN; pos = row % DLEN; mk = dmask[row]; }
    else {
        is_q = 1;
        int q = row - MD;
        prow = QROW0 + q; bb = q / QLEN; pos = q % QLEN; mk = qmask[q];
    }
    const int len = is_q ? QLEN : DLEN;
    const float* bias = (kidx == 0) ? b1 : (kidx == 1 ? b2 : b3);
    const float* P0 = g_P + (size_t)prow * NCAT;
    int c = lane * 4;
    float4 v;
    if (kidx == 0) {
        v = *(const float4*)(P0 + c);
    } else if (kidx == 1) {
        float4 a = *(const float4*)(P0 + 128 + c);
        float4 b = *(const float4*)(P0 + NCAT + 256 + c);
        v = make_float4(a.x + b.x, a.y + b.y, a.z + b.z, a.w + b.w);
    } else {
        float4 a = *(const float4*)(P0 + 384 + c);
        float4 b = *(const float4*)(P0 + NCAT + 512 + c);
        float4 d = *(const float4*)(P0 + 2 * NCAT + 640 + c);
        v = make_float4(a.x + b.x + d.x, a.y + b.y + d.y, a.z + b.z + d.z, a.w + b.w + d.w);
    }
    float4 bv = *(const float4*)(bias + c);
    v.x = fmaxf(v.x + bv.x, 0.f);  v.y = fmaxf(v.y + bv.y, 0.f);
    v.z = fmaxf(v.z + bv.z, 0.f);  v.w = fmaxf(v.w + bv.w, 0.f);
    float ss = v.x * v.x + v.y * v.y + v.z * v.z + v.w * v.w;
    #pragma unroll
    for (int off = 16; off > 0; off >>= 1)
        ss += __shfl_xor_sync(0xffffffffu, ss, off);
    float sc = mk / (sqrtf(ss) + 1e-13f);
    if (pos >= len - kidx) sc = 0.f;
    v.x *= sc; v.y *= sc; v.z *= sc; v.w *= sc;

    float vv[4] = {v.x, v.y, v.z, v.w};
    __half h4[4], l4[4];
    #pragma unroll
    for (int i = 0; i < 4; i++) {
        h4[i] = __float2half(vv[i]);
        l4[i] = __float2half(vv[i] - __half2float(h4[i]));
    }

    int ch = lane >> 3, e8 = lane & 7;
    if (!is_q) {
        size_t blk = (((size_t)kidx * 32 + bb) * 4 + ch) * 1024 + pos;
        *(uint2*)(g_DH + blk * 64 + e8 * 8) = *(const uint2*)h4;
        *(uint2*)(g_DL + blk * 64 + e8 * 8) = *(const uint2*)l4;
    } else {
        size_t blk = (((size_t)kidx * 32 + bb) * 4 + ch) * 32 + pos;
        *(uint2*)(g_QH + blk * 64 + e8 * 8) = *(const uint2*)h4;
        *(uint2*)(g_QL + blk * 64 + e8 * 8) = *(const uint2*)l4;
    }
}

// ---------------- 4) tensor matcher (partial over D quarters) ----------------
__device__ __forceinline__ void accum_bins(float* h, float s) {
    float d1 = s - 1.0f;
    if (fabsf(d1) < 0.012f)
        h[0] += __expf(-500000.f * d1 * d1);
    float d0 = s - 0.95f;
    float g = __expf(-50.f * d0 * d0);
    float t = __expf(-10.f * d0) * 0.60653065971f;
    #pragma unroll
    for (int j = 1; j <= 20; j++) {
        h[j] += g;
        g *= t;
        t *= 0.36787944117f;
    }
}

#define MQT_SZ   10240                     // 4 chunks x 32 rows x 80
#define MD_HALF  10240                     // 2 chunks x 64 rows x 80 (one array, one k-half)
#define MD_STG   (2 * MD_HALF)             // h + l per stage = 20480
#define SMEM_M   (2 * MQT_SZ + 2 * MD_STG) // 61440

__global__ void __launch_bounds__(256, 2) matcher_kernel() {
    extern __shared__ char sm[];
    __shared__ float H[8][16][21];

    const int b    = blockIdx.x;
    const int pair = blockIdx.y;
    const int part = blockIdx.z;           // D quarter
    const int qk   = pair / 3, dk = pair % 3;
    const int tid = threadIdx.x, wid = tid >> 5, lane = tid & 31;
    const int mh = wid & 1, nh = wid >> 1;

    const uint32_t smb = smem_u32(sm);
    const uint32_t QHs = smb, QLs = smb + MQT_SZ;
    const uint32_t DST = smb + 2 * MQT_SZ;

    const char* qh_g = g_QH + ((size_t)qk * 32 + b) * 8192;
    const char* ql_g = g_QL + ((size_t)qk * 32 + b) * 8192;
    const char* dh_g = g_DH + ((size_t)dk * 32 + b) * 262144;
    const char* dl_g = g_DL + ((size_t)dk * 32 + b) * 262144;

    // step = (tile within quarter)*2 + khalf ; 8 steps total
    auto load_step = [&](int s, int step) {
        int dt = part * 4 + (step >> 1);
        int kh = step & 1;
        const uint32_t st = DST + s * MD_STG;
        #pragma unroll
        for (int i = 0; i < 2; i++) {
            int idx = tid + i * 256;               // 0..511
            int chl = idx >> 8, rem = idx & 255;
            int rr = rem >> 2, c = rem & 3;
            int ch = kh * 2 + chl;
            size_t go = ((size_t)ch * 1024 + (size_t)dt * 64 + rr) * 64 + c * 16;
            uint32_t doff = (uint32_t)chl * 5120 + (uint32_t)rr * 80 + c * 16;
            cp16(st + doff, dh_g + go);
            cp16(st + MD_HALF + doff, dl_g + go);
        }
        cp_commit();
    };

    // Q load: 512 chunks per array (2/thread)
    #pragma unroll
    for (int i = 0; i < 2; i++) {
        int idx = tid + i * 256;
        int ch = idx >> 7, rem = idx & 127;
        int rr = rem >> 2, c = rem & 3;
        size_t go = ((size_t)ch * 32 + rr) * 64 + c * 16;
        uint32_t doff = (uint32_t)ch * (32 * S80) + (uint32_t)rr * S80 + c * 16;
        cp16(QHs + doff, qh_g + go);
        cp16(QLs + doff, ql_g + go);
    }
    load_step(0, 0);

    const int lg = lane >> 3, lj = lane & 7;
    const uint32_t a80 = (uint32_t)(lj + 8 * (lg & 1)) * S80 + (uint32_t)(lg >> 1) * 16;
    const uint32_t b80 = (uint32_t)(lj + 8 * (lg >> 1)) * S80 + (uint32_t)(lg & 1) * 16;
    const uint32_t qa_h = QHs + (uint32_t)(mh * 16) * S80 + a80;
    const uint32_t qa_l = QLs + (uint32_t)(mh * 16) * S80 + a80;

    float hist[2][21];
    #pragma unroll
    for (int r = 0; r < 2; r++)
        #pragma unroll
        for (int j = 0; j < 21; j++) hist[r][j] = 0.f;

    float acc[2][4];

    for (int step = 0; step < 8; step++) {
        const int s = step & 1;
        if (step + 1 < 8) { load_step(s ^ 1, step + 1); cp_wait<1>(); }
        else              { cp_wait<0>(); }
        __syncthreads();

        const int kh = step & 1;
        if (kh == 0) {
            #pragma unroll
            for (int t = 0; t < 2; t++)
                #pragma unroll
                for (int k = 0; k < 4; k++) acc[t][k] = 0.f;
        }

        const uint32_t Dh = DST + s * MD_STG + (uint32_t)(nh * 16) * S80 + b80;
        const uint32_t Dl = Dh + MD_HALF;

        #pragma unroll
        for (int kcl = 0; kcl < 2; kcl++) {
            const int kc = kh * 2 + kcl;
            #pragma unroll
            for (int ks = 0; ks < 2; ks++) {
                uint32_t ah[4], al[4], bh[4], bl[4];
                ldmx4(ah, qa_h + kc * 2560 + ks * 32);
                ldmx4(al, qa_l + kc * 2560 + ks * 32);
                ldmx4(bh, Dh + kcl * 5120 + ks * 32);
                ldmx4(bl, Dl + kcl * 5120 + ks * 32);
                mma_f16(acc[0], ah, bh);  mma_f16(acc[1], ah, bh + 2);
                mma_f16(acc[0], al, bh);  mma_f16(acc[1], al, bh + 2);
                mma_f16(acc[0], ah, bl);  mma_f16(acc[1], ah, bl + 2);
            }
        }

        if (kh == 1) {
            #pragma unroll
            for (int t = 0; t < 2; t++) {
                accum_bins(hist[0], acc[t][0]);
                accum_bins(hist[0], acc[t][1]);
                accum_bins(hist[1], acc[t][2]);
                accum_bins(hist[1], acc[t][3]);
            }
        }
        __syncthreads();
    }

    #pragma unroll
    for (int r = 0; r < 2; r++)
        #pragma unroll
        for (int j = 0; j < 21; j++) {
            float v = hist[r][j];
            v += __shfl_xor_sync(0xffffffffu, v, 1);
            v += __shfl_xor_sync(0xffffffffu, v, 2);
            hist[r][j] = v;
        }
    if ((lane & 3) == 0) {
        int lr = lane >> 2;
        #pragma unroll
        for (int j = 0; j < 21; j++) {
            H[wid][lr][j]     = hist[0][j];
            H[wid][lr + 8][j] = hist[1][j];
        }
    }
    __syncthreads();

    if (tid < 32) {
        int q = tid;
        int qmh = q >> 4, local = q & 15;
        float* dst = g_HISTP + ((((size_t)pair * 32 + b) * 4 + part) * 32 + q) * 21;
        #pragma unroll
        for (int j = 0; j < 21; j++) {
            float tot = 0.f;
            #pragma unroll
            for (int n = 0; n < 4; n++) tot += H[2 * n + qmh][local][j];
            dst[j] = tot;
        }
    }
}

// ---------------- 5) merge partials -> logits ----------------
__global__ void merge_kernel(const float* __restrict__ qmasks) {
    __shared__ float KW[32][21];
    const int b = blockIdx.x, pair = blockIdx.y;
    const int qk = pair / 3, dk = pair % 3;
    const int tid = threadIdx.x;
    if (tid < 32) {
        int q = tid;
        float g0[21];
        #pragma unroll
        for (int j = 0; j < 21; j++) g0[j] = 0.f;
        accum_bins(g0, 0.f);                           // bit-identical zero-sim term
        float w = (q < QLEN - qk) ? qmasks[b * QLEN + q] : 0.f;
        const float* src = g_HISTP + (((size_t)pair * 32 + b) * 4 * 32 + q) * 21;
        #pragma unroll
        for (int j = 0; j < 21; j++) {
            float tot = src[j] + src[672 + j] + src[2 * 672 + j] + src[3 * 672 + j]
                      - (float)dk * g0[j];
            KW[q][j] = __logf(fmaxf(tot, 1e-10f)) * 0.01f * w;
        }
    }
    __syncthreads();
    if (tid < 21) {
        float s = 0.f;
        #pragma unroll
        for (int q = 0; q < 32; q++) s += KW[q][tid];
        g_LOGITS[b * 189 + pair * 21 + tid] = s;
    }
}

// ---------------- 6) score ----------------
__global__ void score_kernel(const float* __restrict__ dw, const float* __restrict__ db,
                             float* __restrict__ out, int out_size) {
    __shared__ float red[256];
    int b = blockIdx.x, tid = threadIdx.x;
    float v = (tid < 189) ? g_LOGITS[b * 189 + tid] * dw[tid] : 0.f;
    red[tid] = v;
    __syncthreads();
    for (int s = 128; s > 0; s >>= 1) {
        if (tid < s) red[tid] += red[tid + s];
        __syncthreads();
    }
    float score = red[0] + db[0];
    if (out_size >= B + B * 189) {
        if (tid == 0) out[b] = score;
        if (tid < 189) out[B + b * 189 + tid] = g_LOGITS[b * 189 + tid];
    } else if (out_size == B * 189) {
        if (tid < 189) out[b * 189 + tid] = g_LOGITS[b * 189 + tid];
    } else {
        if (tid == 0 && b < out_size) out[b] = score;
    }
}

// ---------------- launch ----------------
extern "C" void kernel_launch(void* const* d_in, const int* in_sizes, int n_in,
                              void* d_out, int out_size) {
    const int*   qids   = (const int*)d_in[0];
    const float* qmask  = (const float*)d_in[1];
    const int*   dids   = (const int*)d_in[2];
    const float* dmask  = (const float*)d_in[3];
    const float* emb    = (const float*)d_in[4];
    const float* w1     = (const float*)d_in[5];
    const float* b1     = (const float*)d_in[6];
    const float* w2     = (const float*)d_in[7];
    const float* b2     = (const float*)d_in[8];
    const float* w3     = (const float*)d_in[9];
    const float* b3     = (const float*)d_in[10];
    const float* dw     = (const float*)d_in[11];
    const float* db     = (const float*)d_in[12];
    float* out = (float*)d_out;

    cudaFuncSetAttribute(conv_mix_kernel, cudaFuncAttributeMaxDynamicSharedMemorySize, SMEM_DYN);
    cudaFuncSetAttribute(matcher_kernel, cudaFuncAttributeMaxDynamicSharedMemorySize, SMEM_M);

    prep_kernel<<<GATHER_BLOCKS + WCAT_BLOCKS, 256>>>(qids, dids, emb, w1, w2, w3);
    conv_mix_kernel<<<dim3(3, MTILES), 256, SMEM_DYN>>>();
    combine_kernel<<<((MD + MQ) * 3 * 32 + 255) / 256, 256>>>(b1, b2, b3, qmask, dmask);
    matcher_kernel<<<dim3(B, 9, 4), 256, SMEM_M>>>();
    merge_kernel<<<dim3(B, 9), 64>>>(qmask);
    score_kernel<<<B, 256>>>(dw, db, out, out_size);
}

// round 13
// speedup vs baseline: 1.6857x; 1.0230x over previous
#include <cuda_runtime.h>
#include <cuda_bf16.h>
#include <cuda_fp16.h>
#include <cstdint>

#define B      32
#define QLEN   32
#define DLEN   1024
#define EMB    300
#define CDIM   128
#define MD     (B*DLEN)
#define MQ     (B*QLEN)

#define QROW0   32896
#define NROWS   33924
#define KPAD    320
#define NCAT    768
#define MTILES  264

// ---------------- device scratch (zero-initialized) ----------------
__device__ __half g_Eh[(size_t)NROWS * KPAD];   // fp16 hi
__device__ __half g_El[(size_t)NROWS * KPAD];   // fp16 residual (denormals OK)
__device__ __half g_Wh[NCAT * KPAD];
__device__ __half g_Wl[NCAT * KPAD];
__device__ float g_P[(size_t)NROWS * NCAT];
// matcher-ready packed: per (kidx,b): [chunk 0..3][row][64B of 32 fp16]
__device__ char g_DH[3ull * 32 * 4 * 1024 * 64];
__device__ char g_DL[3ull * 32 * 4 * 1024 * 64];
__device__ char g_QH[3ull * 32 * 4 * 32 * 64];
__device__ char g_QL[3ull * 32 * 4 * 32 * 64];
__device__ float g_HISTP[9ull * 32 * 4 * 32 * 21];   // partial histograms
__device__ float g_LOGITS[B * 189];

__device__ __forceinline__ uint32_t smem_u32(const void* p) {
    uint32_t a;
    asm("{ .reg .u64 t; cvta.to.shared.u64 t, %1; cvt.u32.u64 %0, t; }" : "=r"(a) : "l"(p));
    return a;
}
__device__ __forceinline__ void ldmx4(uint32_t* r, uint32_t addr) {
    asm volatile("ldmatrix.sync.aligned.m8n8.x4.shared.b16 {%0,%1,%2,%3}, [%4];"
                 : "=r"(r[0]), "=r"(r[1]), "=r"(r[2]), "=r"(r[3]) : "r"(addr));
}
__device__ __forceinline__ void mma_f16(float* c, const uint32_t* a, const uint32_t* b) {
    asm volatile("mma.sync.aligned.m16n8k16.row.col.f32.f16.f16.f32 "
                 "{%0,%1,%2,%3}, {%4,%5,%6,%7}, {%8,%9}, {%0,%1,%2,%3};"
                 : "+f"(c[0]), "+f"(c[1]), "+f"(c[2]), "+f"(c[3])
                 : "r"(a[0]), "r"(a[1]), "r"(a[2]), "r"(a[3]), "r"(b[0]), "r"(b[1]));
}
__device__ __forceinline__ void cp16(uint32_t dst, const void* src) {
    asm volatile("cp.async.cg.shared.global [%0], [%1], 16;" :: "r"(dst), "l"(src));
}
__device__ __forceinline__ void cp_commit() {
    asm volatile("cp.async.commit_group;" ::: "memory");
}
template <int N>
__device__ __forceinline__ void cp_wait() {
    asm volatile("cp.async.wait_group %0;" :: "n"(N) : "memory");
}

// ---- packed f32x2 helpers (Blackwell sm_100+) ----
__device__ __forceinline__ uint64_t pk2(float x, float y) {
    uint64_t r;
    asm("mov.b64 %0, {%1, %2};" : "=l"(r) : "f"(x), "f"(y));
    return r;
}
__device__ __forceinline__ void upk2(float& x, float& y, uint64_t v) {
    asm("mov.b64 {%0, %1}, %2;" : "=f"(x), "=f"(y) : "l"(v));
}
#define MUL2(o, a, b) asm("mul.rn.f32x2 %0, %1, %2;" : "=l"(o) : "l"(a), "l"(b))
#define ADD2(o, a, b) asm("add.rn.f32x2 %0, %1, %2;" : "=l"(o) : "l"(a), "l"(b))

#define EXP_M10   4.5399929762e-05f   // e^-10
#define EXP_M05   0.60653065971f      // e^-0.5
#define EXP_M1    0.36787944117f      // e^-1

// ---------------- 1) fused gather + wcat ----------------
#define GATHER_BLOCKS  (((MD + MQ) * 32) / 256)      // 4224
#define WCAT_ELEMS     (NCAT * KPAD)                 // 245760
#define WCAT_BLOCKS    (WCAT_ELEMS / 256)            // 960

__global__ void prep_kernel(const int* __restrict__ qids, const int* __restrict__ dids,
                            const float* __restrict__ emb,
                            const float* __restrict__ w1, const float* __restrict__ w2,
                            const float* __restrict__ w3) {
    if (blockIdx.x < GATHER_BLOCKS) {
        int w = (blockIdx.x * blockDim.x + threadIdx.x) >> 5;
        int lane = threadIdx.x & 31;
        if (w >= MD + MQ) return;
        int id, drow;
        if (w < MD) { id = dids[w]; drow = w; }
        else        { id = qids[w - MD]; drow = QROW0 + (w - MD); }
        const float* src = emb + (size_t)id * EMB;
        __half* dh = g_Eh + (size_t)drow * KPAD;
        __half* dl = g_El + (size_t)drow * KPAD;
        #pragma unroll
        for (int i = 0; i < 10; i++) {
            int c = lane + i * 32;
            float x = (c < EMB) ? src[c] : 0.f;
            __half h = __float2half(x);
            dh[c] = h;
            dl[c] = __float2half(x - __half2float(h));
        }
    } else {
        int idx = (blockIdx.x - GATHER_BLOCKS) * 256 + threadIdx.x;
        if (idx >= WCAT_ELEMS) return;
        int j = idx / KPAD, e = idx % KPAD;
        int g = j >> 7, c = j & 127;
        float v = 0.f;
        if (e < EMB) {
            if (g == 0)      v = w1[c * EMB + e];
            else if (g == 1) v = w2[(c * EMB + e) * 2 + 0];
            else if (g == 2) v = w2[(c * EMB + e) * 2 + 1];
            else             v = w3[(c * EMB + e) * 3 + (g - 3)];
        }
        __half h = __float2half(v);
        g_Wh[idx] = h;
        g_Wl[idx] = __float2half(v - __half2float(h));
    }
}

// ---------------- 2) conv GEMM: all-fp16 2-term split, 3-stage pipeline ----------------
#define S80   80
#define AH_OFF  0
#define AL_OFF  10240
#define BH_OFF  20480
#define BL_OFF  40960
#define STAGE_B 61440
#define SMEM_DYN (3 * STAGE_B)     // 184320

__global__ void __launch_bounds__(256, 1) conv_mix_kernel() {
    extern __shared__ char sm[];
    const int mt = blockIdx.y, pass = blockIdx.x;
    const int mbase = (mt < 256) ? mt * 128 : QROW0 + (mt - 256) * 128;
    const int jbase = pass * 256;
    const int tid = threadIdx.x, wid = tid >> 5, lane = tid & 31;
    const int wm = wid & 1, wn = wid >> 1;

    const uint32_t smb = smem_u32(sm);
    const char* Ah_src = (const char*)(g_Eh + (size_t)mbase * KPAD);
    const char* Al_src = (const char*)(g_El + (size_t)mbase * KPAD);
    const char* Bh_src = (const char*)(g_Wh + (size_t)jbase * KPAD);
    const char* Bl_src = (const char*)(g_Wl + (size_t)jbase * KPAD);

    auto load_stage = [&](int s, int kc) {
        const uint32_t st = smb + s * STAGE_B;
        const int kof = kc * 64;
        #pragma unroll
        for (int i = 0; i < 2; i++) {
            int idx = tid + i * 256;
            int r = idx >> 2, c = idx & 3;
            uint32_t doff = (uint32_t)r * S80 + c * 16;
            size_t so = (size_t)r * 640 + kof + c * 16;
            cp16(st + AH_OFF + doff, Ah_src + so);
            cp16(st + AL_OFF + doff, Al_src + so);
        }
        #pragma unroll
        for (int i = 0; i < 4; i++) {
            int idx = tid + i * 256;
            int r = idx >> 2, c = idx & 3;
            uint32_t doff = (uint32_t)r * S80 + c * 16;
            size_t so = (size_t)r * 640 + kof + c * 16;
            cp16(st + BH_OFF + doff, Bh_src + so);
            cp16(st + BL_OFF + doff, Bl_src + so);
        }
        cp_commit();
    };

    float acc[4][8][4];
    #pragma unroll
    for (int i = 0; i < 4; i++)
        #pragma unroll
        for (int j = 0; j < 8; j++)
            #pragma unroll
            for (int k = 0; k < 4; k++) acc[i][j][k] = 0.f;

    const int lg = lane >> 3, lj = lane & 7;
    const uint32_t a80 = (uint32_t)(lj + 8 * (lg & 1)) * S80 + (uint32_t)(lg >> 1) * 16;
    const uint32_t b80 = (uint32_t)(lj + 8 * (lg >> 1)) * S80 + (uint32_t)(lg & 1) * 16;

    load_stage(0, 0);
    load_stage(1, 1);

    for (int kc = 0; kc < 10; kc++) {
        const int s = kc % 3;
        if (kc + 2 < 10)      { load_stage((kc + 2) % 3, kc + 2); cp_wait<2>(); }
        else if (kc + 1 < 10) { cp_wait<1>(); }
        else                  { cp_wait<0>(); }
        __syncthreads();

        const uint32_t AHs = smb + s * STAGE_B + AH_OFF;
        const uint32_t ALs = smb + s * STAGE_B + AL_OFF;
        const uint32_t BHs = smb + s * STAGE_B + BH_OFF;
        const uint32_t BLs = smb + s * STAGE_B + BL_OFF;

        #pragma unroll
        for (int ks = 0; ks < 2; ks++) {
            const uint32_t kb = ks * 32;
            uint32_t bh[8][2], bl[8][2];
            #pragma unroll
            for (int h = 0; h < 4; h++) {
                uint32_t off = (uint32_t)(wn * 64 + h * 16) * S80 + kb + b80;
                uint32_t r[4];
                ldmx4(r, BHs + off);
                bh[h * 2 + 0][0] = r[0]; bh[h * 2 + 0][1] = r[1];
                bh[h * 2 + 1][0] = r[2]; bh[h * 2 + 1][1] = r[3];
                ldmx4(r, BLs + off);
                bl[h * 2 + 0][0] = r[0]; bl[h * 2 + 0][1] = r[1];
                bl[h * 2 + 1][0] = r[2]; bl[h * 2 + 1][1] = r[3];
            }
            #pragma unroll
            for (int mf = 0; mf < 4; mf++) {
                uint32_t off = (uint32_t)(wm * 64 + mf * 16) * S80 + kb + a80;
                uint32_t ah[4];
                ldmx4(ah, AHs + off);
                #pragma unroll
                for (int nf = 0; nf < 8; nf++) {
                    mma_f16(acc[mf][nf], ah, bh[nf]);
                    mma_f16(acc[mf][nf], ah, bl[nf]);
                }
            }
            #pragma unroll
            for (int mf = 0; mf < 4; mf++) {
                uint32_t off = (uint32_t)(wm * 64 + mf * 16) * S80 + kb + a80;
                uint32_t al[4];
                ldmx4(al, ALs + off);
                #pragma unroll
                for (int nf = 0; nf < 8; nf++) mma_f16(acc[mf][nf], al, bh[nf]);
            }
        }
        __syncthreads();
    }

    const int r0 = lane >> 2, c0 = (lane & 3) * 2;
    #pragma unroll
    for (int mf = 0; mf < 4; mf++) {
        int row = mbase + wm * 64 + mf * 16 + r0;
        #pragma unroll
        for (int nf = 0; nf < 8; nf++) {
            int col = jbase + wn * 64 + nf * 8 + c0;
            float* p = g_P + (size_t)row * NCAT + col;
            *(float2*)p                      = make_float2(acc[mf][nf][0], acc[mf][nf][1]);
            *(float2*)(p + (size_t)8 * NCAT) = make_float2(acc[mf][nf][2], acc[mf][nf][3]);
        }
    }
}

// ---------------- 3) combine -> packed fp16 h/l matcher layout ----------------
__global__ void combine_kernel(const float* __restrict__ b1, const float* __restrict__ b2,
                               const float* __restrict__ b3,
                               const float* __restrict__ qmask, const float* __restrict__ dmask) {
    int w = (blockIdx.x * blockDim.x + threadIdx.x) >> 5;
    int lane = threadIdx.x & 31;
    if (w >= (MD + MQ) * 3) return;
    int kidx = w % 3;
    int row  = w / 3;
    int prow, bb, pos, is_q;
    float mk;
    if (row < MD) { is_q = 0; prow = row; bb = row / DLEN; pos = row % DLEN; mk = dmask[row]; }
    else {
        is_q = 1;
        int q = row - MD;
        prow = QROW0 + q; bb = q / QLEN; pos = q % QLEN; mk = qmask[q];
    }
    const int len = is_q ? QLEN : DLEN;
    const float* bias = (kidx == 0) ? b1 : (kidx == 1 ? b2 : b3);
    const float* P0 = g_P + (size_t)prow * NCAT;
    int c = lane * 4;
    float4 v;
    if (kidx == 0) {
        v = *(const float4*)(P0 + c);
    } else if (kidx == 1) {
        float4 a = *(const float4*)(P0 + 128 + c);
        float4 b = *(const float4*)(P0 + NCAT + 256 + c);
        v = make_float4(a.x + b.x, a.y + b.y, a.z + b.z, a.w + b.w);
    } else {
        float4 a = *(const float4*)(P0 + 384 + c);
        float4 b = *(const float4*)(P0 + NCAT + 512 + c);
        float4 d = *(const float4*)(P0 + 2 * NCAT + 640 + c);
        v = make_float4(a.x + b.x + d.x, a.y + b.y + d.y, a.z + b.z + d.z, a.w + b.w + d.w);
    }
    float4 bv = *(const float4*)(bias + c);
    v.x = fmaxf(v.x + bv.x, 0.f);  v.y = fmaxf(v.y + bv.y, 0.f);
    v.z = fmaxf(v.z + bv.z, 0.f);  v.w = fmaxf(v.w + bv.w, 0.f);
    float ss = v.x * v.x + v.y * v.y + v.z * v.z + v.w * v.w;
    #pragma unroll
    for (int off = 16; off > 0; off >>= 1)
        ss += __shfl_xor_sync(0xffffffffu, ss, off);
    float sc = mk / (sqrtf(ss) + 1e-13f);
    if (pos >= len - kidx) sc = 0.f;
    v.x *= sc; v.y *= sc; v.z *= sc; v.w *= sc;

    float vv[4] = {v.x, v.y, v.z, v.w};
    __half h4[4], l4[4];
    #pragma unroll
    for (int i = 0; i < 4; i++) {
        h4[i] = __float2half(vv[i]);
        l4[i] = __float2half(vv[i] - __half2float(h4[i]));
    }

    int ch = lane >> 3, e8 = lane & 7;
    if (!is_q) {
        size_t blk = (((size_t)kidx * 32 + bb) * 4 + ch) * 1024 + pos;
        *(uint2*)(g_DH + blk * 64 + e8 * 8) = *(const uint2*)h4;
        *(uint2*)(g_DL + blk * 64 + e8 * 8) = *(const uint2*)l4;
    } else {
        size_t blk = (((size_t)kidx * 32 + bb) * 4 + ch) * 32 + pos;
        *(uint2*)(g_QH + blk * 64 + e8 * 8) = *(const uint2*)h4;
        *(uint2*)(g_QL + blk * 64 + e8 * 8) = *(const uint2*)l4;
    }
}

// ---------------- 4) tensor matcher (partial over D quarters, f32x2 binning) ----------------
// bins 1..20 split into lo (1-10) and hi (11-20) chains, packed in f32x2 lanes.
// lo: d = s-0.95, g=exp(-50 d^2), t=exp(-10d)*e^-.5 ; hi: dh=d+1, g=exp(-50 dh^2), t_hi=t*e^-10
// recurrence per step (both lanes): h += g ; g *= t ; t *= e^-1.
// single-sim scalar version used by merge for the exact zero-sim term.
__device__ __forceinline__ void bins_single(float s, float* out21) {
    float d1 = s - 1.0f;
    out21[0] = (fabsf(d1) < 0.012f) ? __expf(-500000.f * d1 * d1) : 0.f;
    float d = s - 0.95f;
    float dh = d + 1.0f;
    float gl = __expf(-50.f * d * d);
    float gh = __expf(-50.f * dh * dh);
    float tl = __expf(-10.f * d) * EXP_M05;
    float th = tl * EXP_M10;
    uint64_t g2 = pk2(gl, gh), t2 = pk2(tl, th);
    const uint64_t cc = pk2(EXP_M1, EXP_M1);
    #pragma unroll
    for (int j = 0; j < 10; j++) {
        float a, b;
        upk2(a, b, g2);
        out21[1 + j]  = a;
        out21[11 + j] = b;
        MUL2(g2, g2, t2);
        MUL2(t2, t2, cc);
    }
}

#define MQT_SZ   10240                     // 4 chunks x 32 rows x 80
#define MD_HALF  10240                     // 2 chunks x 64 rows x 80 (one array, one k-half)
#define MD_STG   (2 * MD_HALF)             // h + l per stage = 20480
#define SMEM_M   (2 * MQT_SZ + 2 * MD_STG) // 61440

__global__ void __launch_bounds__(256, 2) matcher_kernel() {
    extern __shared__ char sm[];
    __shared__ float H[8][16][21];

    const int b    = blockIdx.x;
    const int pair = blockIdx.y;
    const int part = blockIdx.z;           // D quarter
    const int qk   = pair / 3, dk = pair % 3;
    const int tid = threadIdx.x, wid = tid >> 5, lane = tid & 31;
    const int mh = wid & 1, nh = wid >> 1;
    (void)qk; (void)dk;

    const uint32_t smb = smem_u32(sm);
    const uint32_t QHs = smb, QLs = smb + MQT_SZ;
    const uint32_t DST = smb + 2 * MQT_SZ;

    const char* qh_g = g_QH + ((size_t)qk * 32 + b) * 8192;
    const char* ql_g = g_QL + ((size_t)qk * 32 + b) * 8192;
    const char* dh_g = g_DH + ((size_t)dk * 32 + b) * 262144;
    const char* dl_g = g_DL + ((size_t)dk * 32 + b) * 262144;

    auto load_step = [&](int s, int step) {
        int dt = part * 4 + (step >> 1);
        int kh = step & 1;
        const uint32_t st = DST + s * MD_STG;
        #pragma unroll
        for (int i = 0; i < 2; i++) {
            int idx = tid + i * 256;
            int chl = idx >> 8, rem = idx & 255;
            int rr = rem >> 2, c = rem & 3;
            int ch = kh * 2 + chl;
            size_t go = ((size_t)ch * 1024 + (size_t)dt * 64 + rr) * 64 + c * 16;
            uint32_t doff = (uint32_t)chl * 5120 + (uint32_t)rr * 80 + c * 16;
            cp16(st + doff, dh_g + go);
            cp16(st + MD_HALF + doff, dl_g + go);
        }
        cp_commit();
    };

    #pragma unroll
    for (int i = 0; i < 2; i++) {
        int idx = tid + i * 256;
        int ch = idx >> 7, rem = idx & 127;
        int rr = rem >> 2, c = rem & 3;
        size_t go = ((size_t)ch * 32 + rr) * 64 + c * 16;
        uint32_t doff = (uint32_t)ch * (32 * S80) + (uint32_t)rr * S80 + c * 16;
        cp16(QHs + doff, qh_g + go);
        cp16(QLs + doff, ql_g + go);
    }
    load_step(0, 0);

    const int lg = lane >> 3, lj = lane & 7;
    const uint32_t a80 = (uint32_t)(lj + 8 * (lg & 1)) * S80 + (uint32_t)(lg >> 1) * 16;
    const uint32_t b80 = (uint32_t)(lj + 8 * (lg >> 1)) * S80 + (uint32_t)(lg & 1) * 16;
    const uint32_t qa_h = QHs + (uint32_t)(mh * 16) * S80 + a80;
    const uint32_t qa_l = QLs + (uint32_t)(mh * 16) * S80 + a80;

    // packed histograms: h2[r][j] lanes = (bin 1+j, bin 11+j); h0[r] = bin 0
    uint64_t h2[2][10];
    float h0[2] = {0.f, 0.f};
    const uint64_t zz = pk2(0.f, 0.f);
    #pragma unroll
    for (int r = 0; r < 2; r++)
        #pragma unroll
        for (int j = 0; j < 10; j++) h2[r][j] = zz;

    const uint64_t cc = pk2(EXP_M1, EXP_M1);

    auto bin_sim = [&](int r, float s) {
        float d1 = s - 1.0f;
        if (fabsf(d1) < 0.012f)
            h0[r] += __expf(-500000.f * d1 * d1);
        float d = s - 0.95f;
        float dh = d + 1.0f;
        float gl = __expf(-50.f * d * d);
        float gh = __expf(-50.f * dh * dh);
        float tl = __expf(-10.f * d) * EXP_M05;
        float th = tl * EXP_M10;
        uint64_t g2 = pk2(gl, gh), t2 = pk2(tl, th);
        #pragma unroll
        for (int j = 0; j < 10; j++) {
            ADD2(h2[r][j], h2[r][j], g2);
            MUL2(g2, g2, t2);
            MUL2(t2, t2, cc);
        }
    };

    float acc[2][4];

    for (int step = 0; step < 8; step++) {
        const int s = step & 1;
        if (step + 1 < 8) { load_step(s ^ 1, step + 1); cp_wait<1>(); }
        else              { cp_wait<0>(); }
        __syncthreads();

        const int kh = step & 1;
        if (kh == 0) {
            #pragma unroll
            for (int t = 0; t < 2; t++)
                #pragma unroll
                for (int k = 0; k < 4; k++) acc[t][k] = 0.f;
        }

        const uint32_t Dh = DST + s * MD_STG + (uint32_t)(nh * 16) * S80 + b80;
        const uint32_t Dl = Dh + MD_HALF;

        #pragma unroll
        for (int kcl = 0; kcl < 2; kcl++) {
            const int kc = kh * 2 + kcl;
            #pragma unroll
            for (int ks = 0; ks < 2; ks++) {
                uint32_t ah[4], al[4], bh[4], bl[4];
                ldmx4(ah, qa_h + kc * 2560 + ks * 32);
                ldmx4(al, qa_l + kc * 2560 + ks * 32);
                ldmx4(bh, Dh + kcl * 5120 + ks * 32);
                ldmx4(bl, Dl + kcl * 5120 + ks * 32);
                mma_f16(acc[0], ah, bh);  mma_f16(acc[1], ah, bh + 2);
                mma_f16(acc[0], al, bh);  mma_f16(acc[1], al, bh + 2);
                mma_f16(acc[0], ah, bl);  mma_f16(acc[1], ah, bl + 2);
            }
        }

        if (kh == 1) {
            #pragma unroll
            for (int t = 0; t < 2; t++) {
                bin_sim(0, acc[t][0]);
                bin_sim(0, acc[t][1]);
                bin_sim(1, acc[t][2]);
                bin_sim(1, acc[t][3]);
            }
        }
        __syncthreads();
    }

    // unpack to 21 scalars, reduce across the 4 lanes sharing a q-row
    float histf[2][21];
    #pragma unroll
    for (int r = 0; r < 2; r++) {
        histf[r][0] = h0[r];
        #pragma unroll
        for (int j = 0; j < 10; j++) {
            float a, bv;
            upk2(a, bv, h2[r][j]);
            histf[r][1 + j]  = a;
            histf[r][11 + j] = bv;
        }
    }
    #pragma unroll
    for (int r = 0; r < 2; r++)
        #pragma unroll
        for (int j = 0; j < 21; j++) {
            float v = histf[r][j];
            v += __shfl_xor_sync(0xffffffffu, v, 1);
            v += __shfl_xor_sync(0xffffffffu, v, 2);
            histf[r][j] = v;
        }
    if ((lane & 3) == 0) {
        int lr = lane >> 2;
        #pragma unroll
        for (int j = 0; j < 21; j++) {
            H[wid][lr][j]     = histf[0][j];
            H[wid][lr + 8][j] = histf[1][j];
        }
    }
    __syncthreads();

    if (tid < 32) {
        int q = tid;
        int qmh = q >> 4, local = q & 15;
        float* dst = g_HISTP + ((((size_t)pair * 32 + b) * 4 + part) * 32 + q) * 21;
        #pragma unroll
        for (int j = 0; j < 21; j++) {
            float tot = 0.f;
            #pragma unroll
            for (int n = 0; n < 4; n++) tot += H[2 * n + qmh][local][j];
            dst[j] = tot;
        }
    }
}

// ---------------- 5) merge partials -> logits ----------------
__global__ void merge_kernel(const float* __restrict__ qmasks) {
    __shared__ float KW[32][21];
    const int b = blockIdx.x, pair = blockIdx.y;
    const int qk = pair / 3, dk = pair % 3;
    const int tid = threadIdx.x;
    if (tid < 32) {
        int q = tid;
        float g0[21];
        bins_single(0.f, g0);                          // same code path as matcher binning
        float w = (q < QLEN - qk) ? qmasks[b * QLEN + q] : 0.f;
        const float* src = g_HISTP + (((size_t)pair * 32 + b) * 4 * 32 + q) * 21;
        #pragma unroll
        for (int j = 0; j < 21; j++) {
            float tot = src[j] + src[672 + j] + src[2 * 672 + j] + src[3 * 672 + j]
                      - (float)dk * g0[j];
            KW[q][j] = __logf(fmaxf(tot, 1e-10f)) * 0.01f * w;
        }
    }
    __syncthreads();
    if (tid < 21) {
        float s = 0.f;
        #pragma unroll
        for (int q = 0; q < 32; q++) s += KW[q][tid];
        g_LOGITS[b * 189 + pair * 21 + tid] = s;
    }
}

// ---------------- 6) score ----------------
__global__ void score_kernel(const float* __restrict__ dw, const float* __restrict__ db,
                             float* __restrict__ out, int out_size) {
    __shared__ float red[256];
    int b = blockIdx.x, tid = threadIdx.x;
    float v = (tid < 189) ? g_LOGITS[b * 189 + tid] * dw[tid] : 0.f;
    red[tid] = v;
    __syncthreads();
    for (int s = 128; s > 0; s >>= 1) {
        if (tid < s) red[tid] += red[tid + s];
        __syncthreads();
    }
    float score = red[0] + db[0];
    if (out_size >= B + B * 189) {
        if (tid == 0) out[b] = score;
        if (tid < 189) out[B + b * 189 + tid] = g_LOGITS[b * 189 + tid];
    } else if (out_size == B * 189) {
        if (tid < 189) out[b * 189 + tid] = g_LOGITS[b * 189 + tid];
    } else {
        if (tid == 0 && b < out_size) out[b] = score;
    }
}

// ---------------- launch ----------------
extern "C" void kernel_launch(void* const* d_in, const int* in_sizes, int n_in,
                              void* d_out, int out_size) {
    const int*   qids   = (const int*)d_in[0];
    const float* qmask  = (const float*)d_in[1];
    const int*   dids   = (const int*)d_in[2];
    const float* dmask  = (const float*)d_in[3];
    const float* emb    = (const float*)d_in[4];
    const float* w1     = (const float*)d_in[5];
    const float* b1     = (const float*)d_in[6];
    const float* w2     = (const float*)d_in[7];
    const float* b2     = (const float*)d_in[8];
    const float* w3     = (const float*)d_in[9];
    const float* b3     = (const float*)d_in[10];
    const float* dw     = (const float*)d_in[11];
    const float* db     = (const float*)d_in[12];
    float* out = (float*)d_out;

    cudaFuncSetAttribute(conv_mix_kernel, cudaFuncAttributeMaxDynamicSharedMemorySize, SMEM_DYN);
    cudaFuncSetAttribute(matcher_kernel, cudaFuncAttributeMaxDynamicSharedMemorySize, SMEM_M);

    prep_kernel<<<GATHER_BLOCKS + WCAT_BLOCKS, 256>>>(qids, dids, emb, w1, w2, w3);
    conv_mix_kernel<<<dim3(3, MTILES), 256, SMEM_DYN>>>();
    combine_kernel<<<((MD + MQ) * 3 * 32 + 255) / 256, 256>>>(b1, b2, b3, qmask, dmask);
    matcher_kernel<<<dim3(B, 9, 4), 256, SMEM_M>>>();
    merge_kernel<<<dim3(B, 9), 64>>>(qmask);
    score_kernel<<<B, 256>>>(dw, db, out, out_size);
}

// round 14
// speedup vs baseline: 1.7149x; 1.0173x over previous
#include <cuda_runtime.h>
#include <cuda_bf16.h>
#include <cuda_fp16.h>
#include <cstdint>

#define B      32
#define QLEN   32
#define DLEN   1024
#define EMB    300
#define CDIM   128
#define MD     (B*DLEN)
#define MQ     (B*QLEN)

#define QROW0   32896
#define NROWS   33924
#define KPAD    320
#define NCAT    768
#define MTILES  264

// ---------------- device scratch (zero-initialized) ----------------
__device__ __half g_Eh[(size_t)NROWS * KPAD];
__device__ __half g_El[(size_t)NROWS * KPAD];
__device__ __half g_Wh[NCAT * KPAD];
__device__ __half g_Wl[NCAT * KPAD];
__device__ float g_P[(size_t)NROWS * NCAT];
__device__ char g_DH[3ull * 32 * 4 * 1024 * 64];
__device__ char g_DL[3ull * 32 * 4 * 1024 * 64];
__device__ char g_QH[3ull * 32 * 4 * 32 * 64];
__device__ char g_QL[3ull * 32 * 4 * 32 * 64];
__device__ float g_HISTP[9ull * 32 * 4 * 32 * 21];
__device__ float g_LOGITS[B * 189];

__device__ __forceinline__ uint32_t smem_u32(const void* p) {
    uint32_t a;
    asm("{ .reg .u64 t; cvta.to.shared.u64 t, %1; cvt.u32.u64 %0, t; }" : "=r"(a) : "l"(p));
    return a;
}
__device__ __forceinline__ void ldmx4(uint32_t* r, uint32_t addr) {
    asm volatile("ldmatrix.sync.aligned.m8n8.x4.shared.b16 {%0,%1,%2,%3}, [%4];"
                 : "=r"(r[0]), "=r"(r[1]), "=r"(r[2]), "=r"(r[3]) : "r"(addr));
}
__device__ __forceinline__ void mma_f16(float* c, const uint32_t* a, const uint32_t* b) {
    asm volatile("mma.sync.aligned.m16n8k16.row.col.f32.f16.f16.f32 "
                 "{%0,%1,%2,%3}, {%4,%5,%6,%7}, {%8,%9}, {%0,%1,%2,%3};"
                 : "+f"(c[0]), "+f"(c[1]), "+f"(c[2]), "+f"(c[3])
                 : "r"(a[0]), "r"(a[1]), "r"(a[2]), "r"(a[3]), "r"(b[0]), "r"(b[1]));
}
__device__ __forceinline__ void cp16(uint32_t dst, const void* src) {
    asm volatile("cp.async.cg.shared.global [%0], [%1], 16;" :: "r"(dst), "l"(src));
}
__device__ __forceinline__ void cp_commit() {
    asm volatile("cp.async.commit_group;" ::: "memory");
}
template <int N>
__device__ __forceinline__ void cp_wait() {
    asm volatile("cp.async.wait_group %0;" :: "n"(N) : "memory");
}

// ---- packed f32x2 helpers ----
__device__ __forceinline__ uint64_t pk2(float x, float y) {
    uint64_t r;
    asm("mov.b64 %0, {%1, %2};" : "=l"(r) : "f"(x), "f"(y));
    return r;
}
__device__ __forceinline__ void upk2(float& x, float& y, uint64_t v) {
    asm("mov.b64 {%0, %1}, %2;" : "=f"(x), "=f"(y) : "l"(v));
}
#define MUL2(o, a, b) asm("mul.rn.f32x2 %0, %1, %2;" : "=l"(o) : "l"(a), "l"(b))
#define ADD2(o, a, b) asm("add.rn.f32x2 %0, %1, %2;" : "=l"(o) : "l"(a), "l"(b))

#define EXP_M10   4.5399929762e-05f
#define EXP_M05   0.60653065971f
#define EXP_M1    0.36787944117f

// ---------------- 1) fused gather + wcat ----------------
#define GATHER_BLOCKS  (((MD + MQ) * 32) / 256)
#define WCAT_ELEMS     (NCAT * KPAD)
#define WCAT_BLOCKS    (WCAT_ELEMS / 256)

__global__ void prep_kernel(const int* __restrict__ qids, const int* __restrict__ dids,
                            const float* __restrict__ emb,
                            const float* __restrict__ w1, const float* __restrict__ w2,
                            const float* __restrict__ w3) {
    if (blockIdx.x < GATHER_BLOCKS) {
        int w = (blockIdx.x * blockDim.x + threadIdx.x) >> 5;
        int lane = threadIdx.x & 31;
        if (w >= MD + MQ) return;
        int id, drow;
        if (w < MD) { id = dids[w]; drow = w; }
        else        { id = qids[w - MD]; drow = QROW0 + (w - MD); }
        const float* src = emb + (size_t)id * EMB;
        __half* dh = g_Eh + (size_t)drow * KPAD;
        __half* dl = g_El + (size_t)drow * KPAD;
        #pragma unroll
        for (int i = 0; i < 10; i++) {
            int c = lane + i * 32;
            float x = (c < EMB) ? src[c] : 0.f;
            __half h = __float2half(x);
            dh[c] = h;
            dl[c] = __float2half(x - __half2float(h));
        }
    } else {
        int idx = (blockIdx.x - GATHER_BLOCKS) * 256 + threadIdx.x;
        if (idx >= WCAT_ELEMS) return;
        int j = idx / KPAD, e = idx % KPAD;
        int g = j >> 7, c = j & 127;
        float v = 0.f;
        if (e < EMB) {
            if (g == 0)      v = w1[c * EMB + e];
            else if (g == 1) v = w2[(c * EMB + e) * 2 + 0];
            else if (g == 2) v = w2[(c * EMB + e) * 2 + 1];
            else             v = w3[(c * EMB + e) * 3 + (g - 3)];
        }
        __half h = __float2half(v);
        g_Wh[idx] = h;
        g_Wl[idx] = __float2half(v - __half2float(h));
    }
}

// ---------------- 2) conv GEMM (unchanged, at HMMA-issue floor) ----------------
#define S80   80
#define AH_OFF  0
#define AL_OFF  10240
#define BH_OFF  20480
#define BL_OFF  40960
#define STAGE_B 61440
#define SMEM_DYN (3 * STAGE_B)

__global__ void __launch_bounds__(256, 1) conv_mix_kernel() {
    extern __shared__ char sm[];
    const int mt = blockIdx.y, pass = blockIdx.x;
    const int mbase = (mt < 256) ? mt * 128 : QROW0 + (mt - 256) * 128;
    const int jbase = pass * 256;
    const int tid = threadIdx.x, wid = tid >> 5, lane = tid & 31;
    const int wm = wid & 1, wn = wid >> 1;

    const uint32_t smb = smem_u32(sm);
    const char* Ah_src = (const char*)(g_Eh + (size_t)mbase * KPAD);
    const char* Al_src = (const char*)(g_El + (size_t)mbase * KPAD);
    const char* Bh_src = (const char*)(g_Wh + (size_t)jbase * KPAD);
    const char* Bl_src = (const char*)(g_Wl + (size_t)jbase * KPAD);

    auto load_stage = [&](int s, int kc) {
        const uint32_t st = smb + s * STAGE_B;
        const int kof = kc * 64;
        #pragma unroll
        for (int i = 0; i < 2; i++) {
            int idx = tid + i * 256;
            int r = idx >> 2, c = idx & 3;
            uint32_t doff = (uint32_t)r * S80 + c * 16;
            size_t so = (size_t)r * 640 + kof + c * 16;
            cp16(st + AH_OFF + doff, Ah_src + so);
            cp16(st + AL_OFF + doff, Al_src + so);
        }
        #pragma unroll
        for (int i = 0; i < 4; i++) {
            int idx = tid + i * 256;
            int r = idx >> 2, c = idx & 3;
            uint32_t doff = (uint32_t)r * S80 + c * 16;
            size_t so = (size_t)r * 640 + kof + c * 16;
            cp16(st + BH_OFF + doff, Bh_src + so);
            cp16(st + BL_OFF + doff, Bl_src + so);
        }
        cp_commit();
    };

    float acc[4][8][4];
    #pragma unroll
    for (int i = 0; i < 4; i++)
        #pragma unroll
        for (int j = 0; j < 8; j++)
            #pragma unroll
            for (int k = 0; k < 4; k++) acc[i][j][k] = 0.f;

    const int lg = lane >> 3, lj = lane & 7;
    const uint32_t a80 = (uint32_t)(lj + 8 * (lg & 1)) * S80 + (uint32_t)(lg >> 1) * 16;
    const uint32_t b80 = (uint32_t)(lj + 8 * (lg >> 1)) * S80 + (uint32_t)(lg & 1) * 16;

    load_stage(0, 0);
    load_stage(1, 1);

    for (int kc = 0; kc < 10; kc++) {
        const int s = kc % 3;
        if (kc + 2 < 10)      { load_stage((kc + 2) % 3, kc + 2); cp_wait<2>(); }
        else if (kc + 1 < 10) { cp_wait<1>(); }
        else                  { cp_wait<0>(); }
        __syncthreads();

        const uint32_t AHs = smb + s * STAGE_B + AH_OFF;
        const uint32_t ALs = smb + s * STAGE_B + AL_OFF;
        const uint32_t BHs = smb + s * STAGE_B + BH_OFF;
        const uint32_t BLs = smb + s * STAGE_B + BL_OFF;

        #pragma unroll
        for (int ks = 0; ks < 2; ks++) {
            const uint32_t kb = ks * 32;
            uint32_t bh[8][2], bl[8][2];
            #pragma unroll
            for (int h = 0; h < 4; h++) {
                uint32_t off = (uint32_t)(wn * 64 + h * 16) * S80 + kb + b80;
                uint32_t r[4];
                ldmx4(r, BHs + off);
                bh[h * 2 + 0][0] = r[0]; bh[h * 2 + 0][1] = r[1];
                bh[h * 2 + 1][0] = r[2]; bh[h * 2 + 1][1] = r[3];
                ldmx4(r, BLs + off);
                bl[h * 2 + 0][0] = r[0]; bl[h * 2 + 0][1] = r[1];
                bl[h * 2 + 1][0] = r[2]; bl[h * 2 + 1][1] = r[3];
            }
            #pragma unroll
            for (int mf = 0; mf < 4; mf++) {
                uint32_t off = (uint32_t)(wm * 64 + mf * 16) * S80 + kb + a80;
                uint32_t ah[4];
                ldmx4(ah, AHs + off);
                #pragma unroll
                for (int nf = 0; nf < 8; nf++) {
                    mma_f16(acc[mf][nf], ah, bh[nf]);
                    mma_f16(acc[mf][nf], ah, bl[nf]);
                }
            }
            #pragma unroll
            for (int mf = 0; mf < 4; mf++) {
                uint32_t off = (uint32_t)(wm * 64 + mf * 16) * S80 + kb + a80;
                uint32_t al[4];
                ldmx4(al, ALs + off);
                #pragma unroll
                for (int nf = 0; nf < 8; nf++) mma_f16(acc[mf][nf], al, bh[nf]);
            }
        }
        __syncthreads();
    }

    const int r0 = lane >> 2, c0 = (lane & 3) * 2;
    #pragma unroll
    for (int mf = 0; mf < 4; mf++) {
        int row = mbase + wm * 64 + mf * 16 + r0;
        #pragma unroll
        for (int nf = 0; nf < 8; nf++) {
            int col = jbase + wn * 64 + nf * 8 + c0;
            float* p = g_P + (size_t)row * NCAT + col;
            *(float2*)p                      = make_float2(acc[mf][nf][0], acc[mf][nf][1]);
            *(float2*)(p + (size_t)8 * NCAT) = make_float2(acc[mf][nf][2], acc[mf][nf][3]);
        }
    }
}

// ---------------- 3) combine (unchanged) ----------------
__global__ void combine_kernel(const float* __restrict__ b1, const float* __restrict__ b2,
                               const float* __restrict__ b3,
                               const float* __restrict__ qmask, const float* __restrict__ dmask) {
    int w = (blockIdx.x * blockDim.x + threadIdx.x) >> 5;
    int lane = threadIdx.x & 31;
    if (w >= (MD + MQ) * 3) return;
    int kidx = w % 3;
    int row  = w / 3;
    int prow, bb, pos, is_q;
    float mk;
    if (row < MD) { is_q = 0; prow = row; bb = row / DLEN; pos = row % DLEN; mk = dmask[row]; }
    else {
        is_q = 1;
        int q = row - MD;
        prow = QROW0 + q; bb = q / QLEN; pos = q % QLEN; mk = qmask[q];
    }
    const int len = is_q ? QLEN : DLEN;
    const float* bias = (kidx == 0) ? b1 : (kidx == 1 ? b2 : b3);
    const float* P0 = g_P + (size_t)prow * NCAT;
    int c = lane * 4;
    float4 v;
    if (kidx == 0) {
        v = *(const float4*)(P0 + c);
    } else if (kidx == 1) {
        float4 a = *(const float4*)(P0 + 128 + c);
        float4 b = *(const float4*)(P0 + NCAT + 256 + c);
        v = make_float4(a.x + b.x, a.y + b.y, a.z + b.z, a.w + b.w);
    } else {
        float4 a = *(const float4*)(P0 + 384 + c);
        float4 b = *(const float4*)(P0 + NCAT + 512 + c);
        float4 d = *(const float4*)(P0 + 2 * NCAT + 640 + c);
        v = make_float4(a.x + b.x + d.x, a.y + b.y + d.y, a.z + b.z + d.z, a.w + b.w + d.w);
    }
    float4 bv = *(const float4*)(bias + c);
    v.x = fmaxf(v.x + bv.x, 0.f);  v.y = fmaxf(v.y + bv.y, 0.f);
    v.z = fmaxf(v.z + bv.z, 0.f);  v.w = fmaxf(v.w + bv.w, 0.f);
    float ss = v.x * v.x + v.y * v.y + v.z * v.z + v.w * v.w;
    #pragma unroll
    for (int off = 16; off > 0; off >>= 1)
        ss += __shfl_xor_sync(0xffffffffu, ss, off);
    float sc = mk / (sqrtf(ss) + 1e-13f);
    if (pos >= len - kidx) sc = 0.f;
    v.x *= sc; v.y *= sc; v.z *= sc; v.w *= sc;

    float vv[4] = {v.x, v.y, v.z, v.w};
    __half h4[4], l4[4];
    #pragma unroll
    for (int i = 0; i < 4; i++) {
        h4[i] = __float2half(vv[i]);
        l4[i] = __float2half(vv[i] - __half2float(h4[i]));
    }

    int ch = lane >> 3, e8 = lane & 7;
    if (!is_q) {
        size_t blk = (((size_t)kidx * 32 + bb) * 4 + ch) * 1024 + pos;
        *(uint2*)(g_DH + blk * 64 + e8 * 8) = *(const uint2*)h4;
        *(uint2*)(g_DL + blk * 64 + e8 * 8) = *(const uint2*)l4;
    } else {
        size_t blk = (((size_t)kidx * 32 + bb) * 4 + ch) * 32 + pos;
        *(uint2*)(g_QH + blk * 64 + e8 * 8) = *(const uint2*)h4;
        *(uint2*)(g_QL + blk * 64 + e8 * 8) = *(const uint2*)l4;
    }
}

// ---------------- 4) tensor matcher: single-hist via pair-exchange, 3 CTAs/SM ----------------
__device__ __forceinline__ void bins_single(float s, float* out21) {
    float d1 = s - 1.0f;
    out21[0] = (fabsf(d1) < 0.012f) ? __expf(-500000.f * d1 * d1) : 0.f;
    float d = s - 0.95f;
    float dh = d + 1.0f;
    float gl = __expf(-50.f * d * d);
    float gh = __expf(-50.f * dh * dh);
    float tl = __expf(-10.f * d) * EXP_M05;
    float th = tl * EXP_M10;
    uint64_t g2 = pk2(gl, gh), t2 = pk2(tl, th);
    const uint64_t cc = pk2(EXP_M1, EXP_M1);
    #pragma unroll
    for (int j = 0; j < 10; j++) {
        float a, b;
        upk2(a, b, g2);
        out21[1 + j]  = a;
        out21[11 + j] = b;
        MUL2(g2, g2, t2);
        MUL2(t2, t2, cc);
    }
}

#define MQT_SZ   10240
#define MD_HALF  10240
#define MD_STG   (2 * MD_HALF)
#define SMEM_M   (2 * MQT_SZ + 2 * MD_STG)   // 61440

__global__ void __launch_bounds__(256, 3) matcher_kernel() {
    extern __shared__ char sm[];
    __shared__ float H[8][16][21];

    const int b    = blockIdx.x;
    const int pair = blockIdx.y;
    const int part = blockIdx.z;
    const int qk   = pair / 3, dk = pair % 3;
    const int tid = threadIdx.x, wid = tid >> 5, lane = tid & 31;
    const int mh = wid & 1, nh = wid >> 1;
    (void)dk;

    const uint32_t smb = smem_u32(sm);
    const uint32_t QHs = smb, QLs = smb + MQT_SZ;
    const uint32_t DST = smb + 2 * MQT_SZ;

    const char* qh_g = g_QH + ((size_t)qk * 32 + b) * 8192;
    const char* ql_g = g_QL + ((size_t)qk * 32 + b) * 8192;
    const char* dh_g = g_DH + ((size_t)dk * 32 + b) * 262144;
    const char* dl_g = g_DL + ((size_t)dk * 32 + b) * 262144;

    auto load_step = [&](int s, int step) {
        int dt = part * 4 + (step >> 1);
        int kh = step & 1;
        const uint32_t st = DST + s * MD_STG;
        #pragma unroll
        for (int i = 0; i < 2; i++) {
            int idx = tid + i * 256;
            int chl = idx >> 8, rem = idx & 255;
            int rr = rem >> 2, c = rem & 3;
            int ch = kh * 2 + chl;
            size_t go = ((size_t)ch * 1024 + (size_t)dt * 64 + rr) * 64 + c * 16;
            uint32_t doff = (uint32_t)chl * 5120 + (uint32_t)rr * 80 + c * 16;
            cp16(st + doff, dh_g + go);
            cp16(st + MD_HALF + doff, dl_g + go);
        }
        cp_commit();
    };

    #pragma unroll
    for (int i = 0; i < 2; i++) {
        int idx = tid + i * 256;
        int ch = idx >> 7, rem = idx & 127;
        int rr = rem >> 2, c = rem & 3;
        size_t go = ((size_t)ch * 32 + rr) * 64 + c * 16;
        uint32_t doff = (uint32_t)ch * (32 * S80) + (uint32_t)rr * S80 + c * 16;
        cp16(QHs + doff, qh_g + go);
        cp16(QLs + doff, ql_g + go);
    }
    load_step(0, 0);

    const int lg = lane >> 3, lj = lane & 7;
    const uint32_t a80 = (uint32_t)(lj + 8 * (lg & 1)) * S80 + (uint32_t)(lg >> 1) * 16;
    const uint32_t b80 = (uint32_t)(lj + 8 * (lg >> 1)) * S80 + (uint32_t)(lg & 1) * 16;
    const uint32_t qa_h = QHs + (uint32_t)(mh * 16) * S80 + a80;
    const uint32_t qa_l = QLs + (uint32_t)(mh * 16) * S80 + a80;

    // SINGLE packed histogram per thread (row = (lane>>2) + 8*(lane&1))
    uint64_t h2[10];
    float h0 = 0.f;
    const uint64_t zz = pk2(0.f, 0.f);
    #pragma unroll
    for (int j = 0; j < 10; j++) h2[j] = zz;
    const uint64_t cc = pk2(EXP_M1, EXP_M1);

    auto bin_sim = [&](float s) {
        float d1 = s - 1.0f;
        if (fabsf(d1) < 0.012f)
            h0 += __expf(-500000.f * d1 * d1);
        float d = s - 0.95f;
        float dh = d + 1.0f;
        float gl = __expf(-50.f * d * d);
        float gh = __expf(-50.f * dh * dh);
        float tl = __expf(-10.f * d) * EXP_M05;
        float th = tl * EXP_M10;
        uint64_t g2 = pk2(gl, gh), t2 = pk2(tl, th);
        #pragma unroll
        for (int j = 0; j < 10; j++) {
            ADD2(h2[j], h2[j], g2);
            MUL2(g2, g2, t2);
            MUL2(t2, t2, cc);
        }
    };

    float acc[2][4];

    for (int step = 0; step < 8; step++) {
        const int s = step & 1;
        if (step + 1 < 8) { load_step(s ^ 1, step + 1); cp_wait<1>(); }
        else              { cp_wait<0>(); }
        __syncthreads();

        const int kh = step & 1;
        if (kh == 0) {
            #pragma unroll
            for (int t = 0; t < 2; t++)
                #pragma unroll
                for (int k = 0; k < 4; k++) acc[t][k] = 0.f;
        }

        const uint32_t Dh = DST + s * MD_STG + (uint32_t)(nh * 16) * S80 + b80;
        const uint32_t Dl = Dh + MD_HALF;

        #pragma unroll
        for (int kcl = 0; kcl < 2; kcl++) {
            const int kc = kh * 2 + kcl;
            #pragma unroll
            for (int ks = 0; ks < 2; ks++) {
                uint32_t ah[4], al[4], bh[4], bl[4];
                ldmx4(ah, qa_h + kc * 2560 + ks * 32);
                ldmx4(al, qa_l + kc * 2560 + ks * 32);
                ldmx4(bh, Dh + kcl * 5120 + ks * 32);
                ldmx4(bl, Dl + kcl * 5120 + ks * 32);
                mma_f16(acc[0], ah, bh);  mma_f16(acc[1], ah, bh + 2);
                mma_f16(acc[0], al, bh);  mma_f16(acc[1], al, bh + 2);
                mma_f16(acc[0], ah, bl);  mma_f16(acc[1], ah, bl + 2);
            }
        }

        if (kh == 1) {
            // pair-exchange: even lane of each pair keeps row r sims, odd keeps row r+8
            float a8[8] = { acc[0][0], acc[0][1], acc[1][0], acc[1][1],
                            acc[0][2], acc[0][3], acc[1][2], acc[1][3] };
            #pragma unroll
            for (int k = 0; k < 4; k++) {
                float send = (lane & 1) ? a8[k] : a8[k + 4];
                float got  = __shfl_xor_sync(0xffffffffu, send, 1);
                float own  = (lane & 1) ? a8[k + 4] : a8[k];
                bin_sim(own);
                bin_sim(got);
            }
        }
        __syncthreads();
    }

    // unpack, reduce across lane^2 (the 2 lanes sharing a row)
    float histf[21];
    histf[0] = h0;
    #pragma unroll
    for (int j = 0; j < 10; j++) {
        float a, bv;
        upk2(a, bv, h2[j]);
        histf[1 + j]  = a;
        histf[11 + j] = bv;
    }
    #pragma unroll
    for (int j = 0; j < 21; j++)
        histf[j] += __shfl_xor_sync(0xffffffffu, histf[j], 2);

    if ((lane & 2) == 0) {
        int row16 = (lane >> 2) + 8 * (lane & 1);
        #pragma unroll
        for (int j = 0; j < 21; j++)
            H[wid][row16][j] = histf[j];
    }
    __syncthreads();

    if (tid < 32) {
        int q = tid;
        int qmh = q >> 4, local = q & 15;
        float* dst = g_HISTP + ((((size_t)pair * 32 + b) * 4 + part) * 32 + q) * 21;
        #pragma unroll
        for (int j = 0; j < 21; j++) {
            float tot = 0.f;
            #pragma unroll
            for (int n = 0; n < 4; n++) tot += H[2 * n + qmh][local][j];
            dst[j] = tot;
        }
    }
}

// ---------------- 5) merge partials -> logits ----------------
__global__ void merge_kernel(const float* __restrict__ qmasks) {
    __shared__ float KW[32][21];
    const int b = blockIdx.x, pair = blockIdx.y;
    const int qk = pair / 3, dk = pair % 3;
    const int tid = threadIdx.x;
    if (tid < 32) {
        int q = tid;
        float g0[21];
        bins_single(0.f, g0);
        float w = (q < QLEN - qk) ? qmasks[b * QLEN + q] : 0.f;
        const float* src = g_HISTP + (((size_t)pair * 32 + b) * 4 * 32 + q) * 21;
        #pragma unroll
        for (int j = 0; j < 21; j++) {
            float tot = src[j] + src[672 + j] + src[2 * 672 + j] + src[3 * 672 + j]
                      - (float)dk * g0[j];
            KW[q][j] = __logf(fmaxf(tot, 1e-10f)) * 0.01f * w;
        }
    }
    __syncthreads();
    if (tid < 21) {
        float s = 0.f;
        #pragma unroll
        for (int q = 0; q < 32; q++) s += KW[q][tid];
        g_LOGITS[b * 189 + pair * 21 + tid] = s;
    }
}

// ---------------- 6) score ----------------
__global__ void score_kernel(const float* __restrict__ dw, const float* __restrict__ db,
                             float* __restrict__ out, int out_size) {
    __shared__ float red[256];
    int b = blockIdx.x, tid = threadIdx.x;
    float v = (tid < 189) ? g_LOGITS[b * 189 + tid] * dw[tid] : 0.f;
    red[tid] = v;
    __syncthreads();
    for (int s = 128; s > 0; s >>= 1) {
        if (tid < s) red[tid] += red[tid + s];
        __syncthreads();
    }
    float score = red[0] + db[0];
    if (out_size >= B + B * 189) {
        if (tid == 0) out[b] = score;
        if (tid < 189) out[B + b * 189 + tid] = g_LOGITS[b * 189 + tid];
    } else if (out_size == B * 189) {
        if (tid < 189) out[b * 189 + tid] = g_LOGITS[b * 189 + tid];
    } else {
        if (tid == 0 && b < out_size) out[b] = score;
    }
}

// ---------------- launch ----------------
extern "C" void kernel_launch(void* const* d_in, const int* in_sizes, int n_in,
                              void* d_out, int out_size) {
    const int*   qids   = (const int*)d_in[0];
    const float* qmask  = (const float*)d_in[1];
    const int*   dids   = (const int*)d_in[2];
    const float* dmask  = (const float*)d_in[3];
    const float* emb    = (const float*)d_in[4];
    const float* w1     = (const float*)d_in[5];
    const float* b1     = (const float*)d_in[6];
    const float* w2     = (const float*)d_in[7];
    const float* b2     = (const float*)d_in[8];
    const float* w3     = (const float*)d_in[9];
    const float* b3     = (const float*)d_in[10];
    const float* dw     = (const float*)d_in[11];
    const float* db     = (const float*)d_in[12];
    float* out = (float*)d_out;

    cudaFuncSetAttribute(conv_mix_kernel, cudaFuncAttributeMaxDynamicSharedMemorySize, SMEM_DYN);
    cudaFuncSetAttribute(matcher_kernel, cudaFuncAttributeMaxDynamicSharedMemorySize, SMEM_M);

    prep_kernel<<<GATHER_BLOCKS + WCAT_BLOCKS, 256>>>(qids, dids, emb, w1, w2, w3);
    conv_mix_kernel<<<dim3(3, MTILES), 256, SMEM_DYN>>>();
    combine_kernel<<<((MD + MQ) * 3 * 32 + 255) / 256, 256>>>(b1, b2, b3, qmask, dmask);
    matcher_kernel<<<dim3(B, 9, 4), 256, SMEM_M>>>();
    merge_kernel<<<dim3(B, 9), 64>>>(qmask);
    score_kernel<<<B, 256>>>(dw, db, out, out_size);
}

// round 15
// speedup vs baseline: 1.7282x; 1.0077x over previous
#include <cuda_runtime.h>
#include <cuda_bf16.h>
#include <cuda_fp16.h>
#include <cstdint>

#define B      32
#define QLEN   32
#define DLEN   1024
#define EMB    300
#define CDIM   128
#define MD     (B*DLEN)
#define MQ     (B*QLEN)

#define QROW0   32896
#define NROWS   33924
#define KPAD    320
#define NCAT    768
#define MTILES  264

// ---------------- device scratch (zero-initialized) ----------------
__device__ __half g_Eh[(size_t)NROWS * KPAD];
__device__ __half g_El[(size_t)NROWS * KPAD];
__device__ __half g_Wh[NCAT * KPAD];
__device__ __half g_Wl[NCAT * KPAD];
__device__ float g_P[(size_t)NROWS * NCAT];
__device__ char g_DH[3ull * 32 * 4 * 1024 * 64];
__device__ char g_DL[3ull * 32 * 4 * 1024 * 64];
__device__ char g_QH[3ull * 32 * 4 * 32 * 64];
__device__ char g_QL[3ull * 32 * 4 * 32 * 64];
__device__ float g_HISTP[9ull * 32 * 4 * 32 * 21];

__device__ __forceinline__ uint32_t smem_u32(const void* p) {
    uint32_t a;
    asm("{ .reg .u64 t; cvta.to.shared.u64 t, %1; cvt.u32.u64 %0, t; }" : "=r"(a) : "l"(p));
    return a;
}
__device__ __forceinline__ void ldmx4(uint32_t* r, uint32_t addr) {
    asm volatile("ldmatrix.sync.aligned.m8n8.x4.shared.b16 {%0,%1,%2,%3}, [%4];"
                 : "=r"(r[0]), "=r"(r[1]), "=r"(r[2]), "=r"(r[3]) : "r"(addr));
}
__device__ __forceinline__ void mma_f16(float* c, const uint32_t* a, const uint32_t* b) {
    asm volatile("mma.sync.aligned.m16n8k16.row.col.f32.f16.f16.f32 "
                 "{%0,%1,%2,%3}, {%4,%5,%6,%7}, {%8,%9}, {%0,%1,%2,%3};"
                 : "+f"(c[0]), "+f"(c[1]), "+f"(c[2]), "+f"(c[3])
                 : "r"(a[0]), "r"(a[1]), "r"(a[2]), "r"(a[3]), "r"(b[0]), "r"(b[1]));
}
__device__ __forceinline__ void cp16(uint32_t dst, const void* src) {
    asm volatile("cp.async.cg.shared.global [%0], [%1], 16;" :: "r"(dst), "l"(src));
}
__device__ __forceinline__ void cp_commit() {
    asm volatile("cp.async.commit_group;" ::: "memory");
}
template <int N>
__device__ __forceinline__ void cp_wait() {
    asm volatile("cp.async.wait_group %0;" :: "n"(N) : "memory");
}

// ---- packed f32x2 helpers ----
__device__ __forceinline__ uint64_t pk2(float x, float y) {
    uint64_t r;
    asm("mov.b64 %0, {%1, %2};" : "=l"(r) : "f"(x), "f"(y));
    return r;
}
__device__ __forceinline__ void upk2(float& x, float& y, uint64_t v) {
    asm("mov.b64 {%0, %1}, %2;" : "=f"(x), "=f"(y) : "l"(v));
}
#define MUL2(o, a, b) asm("mul.rn.f32x2 %0, %1, %2;" : "=l"(o) : "l"(a), "l"(b))
#define ADD2(o, a, b) asm("add.rn.f32x2 %0, %1, %2;" : "=l"(o) : "l"(a), "l"(b))

#define EXP_M10   4.5399929762e-05f
#define EXP_M05   0.60653065971f
#define EXP_M1    0.36787944117f

// ---------------- 1) fused gather + wcat ----------------
#define GATHER_BLOCKS  (((MD + MQ) * 32) / 256)
#define WCAT_ELEMS     (NCAT * KPAD)
#define WCAT_BLOCKS    (WCAT_ELEMS / 256)

__global__ void prep_kernel(const int* __restrict__ qids, const int* __restrict__ dids,
                            const float* __restrict__ emb,
                            const float* __restrict__ w1, const float* __restrict__ w2,
                            const float* __restrict__ w3) {
    if (blockIdx.x < GATHER_BLOCKS) {
        int w = (blockIdx.x * blockDim.x + threadIdx.x) >> 5;
        int lane = threadIdx.x & 31;
        if (w >= MD + MQ) return;
        int id, drow;
        if (w < MD) { id = dids[w]; drow = w; }
        else        { id = qids[w - MD]; drow = QROW0 + (w - MD); }
        const float* src = emb + (size_t)id * EMB;
        __half* dh = g_Eh + (size_t)drow * KPAD;
        __half* dl = g_El + (size_t)drow * KPAD;
        #pragma unroll
        for (int i = 0; i < 10; i++) {
            int c = lane + i * 32;
            float x = (c < EMB) ? src[c] : 0.f;
            __half h = __float2half(x);
            dh[c] = h;
            dl[c] = __float2half(x - __half2float(h));
        }
    } else {
        int idx = (blockIdx.x - GATHER_BLOCKS) * 256 + threadIdx.x;
        if (idx >= WCAT_ELEMS) return;
        int j = idx / KPAD, e = idx % KPAD;
        int g = j >> 7, c = j & 127;
        float v = 0.f;
        if (e < EMB) {
            if (g == 0)      v = w1[c * EMB + e];
            else if (g == 1) v = w2[(c * EMB + e) * 2 + 0];
            else if (g == 2) v = w2[(c * EMB + e) * 2 + 1];
            else             v = w3[(c * EMB + e) * 3 + (g - 3)];
        }
        __half h = __float2half(v);
        g_Wh[idx] = h;
        g_Wl[idx] = __float2half(v - __half2float(h));
    }
}

// ---------------- 2) conv GEMM (tail-K step skipped: K 304-320 is all zeros) ----------------
#define S80   80
#define AH_OFF  0
#define AL_OFF  10240
#define BH_OFF  20480
#define BL_OFF  40960
#define STAGE_B 61440
#define SMEM_DYN (3 * STAGE_B)

__global__ void __launch_bounds__(256, 1) conv_mix_kernel() {
    extern __shared__ char sm[];
    const int mt = blockIdx.y, pass = blockIdx.x;
    const int mbase = (mt < 256) ? mt * 128 : QROW0 + (mt - 256) * 128;
    const int jbase = pass * 256;
    const int tid = threadIdx.x, wid = tid >> 5, lane = tid & 31;
    const int wm = wid & 1, wn = wid >> 1;

    const uint32_t smb = smem_u32(sm);
    const char* Ah_src = (const char*)(g_Eh + (size_t)mbase * KPAD);
    const char* Al_src = (const char*)(g_El + (size_t)mbase * KPAD);
    const char* Bh_src = (const char*)(g_Wh + (size_t)jbase * KPAD);
    const char* Bl_src = (const char*)(g_Wl + (size_t)jbase * KPAD);

    auto load_stage = [&](int s, int kc) {
        const uint32_t st = smb + s * STAGE_B;
        const int kof = kc * 64;
        #pragma unroll
        for (int i = 0; i < 2; i++) {
            int idx = tid + i * 256;
            int r = idx >> 2, c = idx & 3;
            uint32_t doff = (uint32_t)r * S80 + c * 16;
            size_t so = (size_t)r * 640 + kof + c * 16;
            cp16(st + AH_OFF + doff, Ah_src + so);
            cp16(st + AL_OFF + doff, Al_src + so);
        }
        #pragma unroll
        for (int i = 0; i < 4; i++) {
            int idx = tid + i * 256;
            int r = idx >> 2, c = idx & 3;
            uint32_t doff = (uint32_t)r * S80 + c * 16;
            size_t so = (size_t)r * 640 + kof + c * 16;
            cp16(st + BH_OFF + doff, Bh_src + so);
            cp16(st + BL_OFF + doff, Bl_src + so);
        }
        cp_commit();
    };

    float acc[4][8][4];
    #pragma unroll
    for (int i = 0; i < 4; i++)
        #pragma unroll
        for (int j = 0; j < 8; j++)
            #pragma unroll
            for (int k = 0; k < 4; k++) acc[i][j][k] = 0.f;

    const int lg = lane >> 3, lj = lane & 7;
    const uint32_t a80 = (uint32_t)(lj + 8 * (lg & 1)) * S80 + (uint32_t)(lg >> 1) * 16;
    const uint32_t b80 = (uint32_t)(lj + 8 * (lg >> 1)) * S80 + (uint32_t)(lg & 1) * 16;

    load_stage(0, 0);
    load_stage(1, 1);

    for (int kc = 0; kc < 10; kc++) {
        const int s = kc % 3;
        if (kc + 2 < 10)      { load_stage((kc + 2) % 3, kc + 2); cp_wait<2>(); }
        else if (kc + 1 < 10) { cp_wait<1>(); }
        else                  { cp_wait<0>(); }
        __syncthreads();

        const uint32_t AHs = smb + s * STAGE_B + AH_OFF;
        const uint32_t ALs = smb + s * STAGE_B + AL_OFF;
        const uint32_t BHs = smb + s * STAGE_B + BH_OFF;
        const uint32_t BLs = smb + s * STAGE_B + BL_OFF;

        #pragma unroll
        for (int ks = 0; ks < 2; ks++) {
            // chunk 9, second k16 step covers K 304..320 = all zero padding -> skip
            if (ks == 1 && kc == 9) break;
            const uint32_t kb = ks * 32;
            uint32_t bh[8][2], bl[8][2];
            #pragma unroll
            for (int h = 0; h < 4; h++) {
                uint32_t off = (uint32_t)(wn * 64 + h * 16) * S80 + kb + b80;
                uint32_t r[4];
                ldmx4(r, BHs + off);
                bh[h * 2 + 0][0] = r[0]; bh[h * 2 + 0][1] = r[1];
                bh[h * 2 + 1][0] = r[2]; bh[h * 2 + 1][1] = r[3];
                ldmx4(r, BLs + off);
                bl[h * 2 + 0][0] = r[0]; bl[h * 2 + 0][1] = r[1];
                bl[h * 2 + 1][0] = r[2]; bl[h * 2 + 1][1] = r[3];
            }
            #pragma unroll
            for (int mf = 0; mf < 4; mf++) {
                uint32_t off = (uint32_t)(wm * 64 + mf * 16) * S80 + kb + a80;
                uint32_t ah[4];
                ldmx4(ah, AHs + off);
                #pragma unroll
                for (int nf = 0; nf < 8; nf++) {
                    mma_f16(acc[mf][nf], ah, bh[nf]);
                    mma_f16(acc[mf][nf], ah, bl[nf]);
                }
            }
            #pragma unroll
            for (int mf = 0; mf < 4; mf++) {
                uint32_t off = (uint32_t)(wm * 64 + mf * 16) * S80 + kb + a80;
                uint32_t al[4];
                ldmx4(al, ALs + off);
                #pragma unroll
                for (int nf = 0; nf < 8; nf++) mma_f16(acc[mf][nf], al, bh[nf]);
            }
        }
        __syncthreads();
    }

    const int r0 = lane >> 2, c0 = (lane & 3) * 2;
    #pragma unroll
    for (int mf = 0; mf < 4; mf++) {
        int row = mbase + wm * 64 + mf * 16 + r0;
        #pragma unroll
        for (int nf = 0; nf < 8; nf++) {
            int col = jbase + wn * 64 + nf * 8 + c0;
            float* p = g_P + (size_t)row * NCAT + col;
            *(float2*)p                      = make_float2(acc[mf][nf][0], acc[mf][nf][1]);
            *(float2*)(p + (size_t)8 * NCAT) = make_float2(acc[mf][nf][2], acc[mf][nf][3]);
        }
    }
}

// ---------------- 3) combine: 2 items per warp ----------------
__global__ void combine_kernel(const float* __restrict__ b1, const float* __restrict__ b2,
                               const float* __restrict__ b3,
                               const float* __restrict__ qmask, const float* __restrict__ dmask) {
    const int w0 = (((blockIdx.x * blockDim.x + threadIdx.x) >> 5) << 1);
    const int lane = threadIdx.x & 31;
    #pragma unroll
    for (int u = 0; u < 2; u++) {
        int w = w0 + u;
        if (w >= (MD + MQ) * 3) break;
        int kidx = w % 3;
        int row  = w / 3;
        int prow, bb, pos, is_q;
        float mk;
        if (row < MD) { is_q = 0; prow = row; bb = row / DLEN; pos = row % DLEN; mk = dmask[row]; }
        else {
            is_q = 1;
            int q = row - MD;
            prow = QROW0 + q; bb = q / QLEN; pos = q % QLEN; mk = qmask[q];
        }
        const int len = is_q ? QLEN : DLEN;
        const float* bias = (kidx == 0) ? b1 : (kidx == 1 ? b2 : b3);
        const float* P0 = g_P + (size_t)prow * NCAT;
        int c = lane * 4;
        float4 v;
        if (kidx == 0) {
            v = *(const float4*)(P0 + c);
        } else if (kidx == 1) {
            float4 a = *(const float4*)(P0 + 128 + c);
            float4 b = *(const float4*)(P0 + NCAT + 256 + c);
            v = make_float4(a.x + b.x, a.y + b.y, a.z + b.z, a.w + b.w);
        } else {
            float4 a = *(const float4*)(P0 + 384 + c);
            float4 b = *(const float4*)(P0 + NCAT + 512 + c);
            float4 d = *(const float4*)(P0 + 2 * NCAT + 640 + c);
            v = make_float4(a.x + b.x + d.x, a.y + b.y + d.y, a.z + b.z + d.z, a.w + b.w + d.w);
        }
        float4 bv = *(const float4*)(bias + c);
        v.x = fmaxf(v.x + bv.x, 0.f);  v.y = fmaxf(v.y + bv.y, 0.f);
        v.z = fmaxf(v.z + bv.z, 0.f);  v.w = fmaxf(v.w + bv.w, 0.f);
        float ss = v.x * v.x + v.y * v.y + v.z * v.z + v.w * v.w;
        #pragma unroll
        for (int off = 16; off > 0; off >>= 1)
            ss += __shfl_xor_sync(0xffffffffu, ss, off);
        float sc = mk / (sqrtf(ss) + 1e-13f);
        if (pos >= len - kidx) sc = 0.f;
        v.x *= sc; v.y *= sc; v.z *= sc; v.w *= sc;

        float vv[4] = {v.x, v.y, v.z, v.w};
        __half h4[4], l4[4];
        #pragma unroll
        for (int i = 0; i < 4; i++) {
            h4[i] = __float2half(vv[i]);
            l4[i] = __float2half(vv[i] - __half2float(h4[i]));
        }

        int ch = lane >> 3, e8 = lane & 7;
        if (!is_q) {
            size_t blk = (((size_t)kidx * 32 + bb) * 4 + ch) * 1024 + pos;
            *(uint2*)(g_DH + blk * 64 + e8 * 8) = *(const uint2*)h4;
            *(uint2*)(g_DL + blk * 64 + e8 * 8) = *(const uint2*)l4;
        } else {
            size_t blk = (((size_t)kidx * 32 + bb) * 4 + ch) * 32 + pos;
            *(uint2*)(g_QH + blk * 64 + e8 * 8) = *(const uint2*)h4;
            *(uint2*)(g_QL + blk * 64 + e8 * 8) = *(const uint2*)l4;
        }
    }
}

// ---------------- 4) tensor matcher (unchanged from R14) ----------------
__device__ __forceinline__ void bins_single(float s, float* out21) {
    float d1 = s - 1.0f;
    out21[0] = (fabsf(d1) < 0.012f) ? __expf(-500000.f * d1 * d1) : 0.f;
    float d = s - 0.95f;
    float dh = d + 1.0f;
    float gl = __expf(-50.f * d * d);
    float gh = __expf(-50.f * dh * dh);
    float tl = __expf(-10.f * d) * EXP_M05;
    float th = tl * EXP_M10;
    uint64_t g2 = pk2(gl, gh), t2 = pk2(tl, th);
    const uint64_t cc = pk2(EXP_M1, EXP_M1);
    #pragma unroll
    for (int j = 0; j < 10; j++) {
        float a, b;
        upk2(a, b, g2);
        out21[1 + j]  = a;
        out21[11 + j] = b;
        MUL2(g2, g2, t2);
        MUL2(t2, t2, cc);
    }
}

#define MQT_SZ   10240
#define MD_HALF  10240
#define MD_STG   (2 * MD_HALF)
#define SMEM_M   (2 * MQT_SZ + 2 * MD_STG)   // 61440

__global__ void __launch_bounds__(256, 3) matcher_kernel() {
    extern __shared__ char sm[];
    __shared__ float H[8][16][21];

    const int b    = blockIdx.x;
    const int pair = blockIdx.y;
    const int part = blockIdx.z;
    const int qk   = pair / 3, dk = pair % 3;
    const int tid = threadIdx.x, wid = tid >> 5, lane = tid & 31;
    const int mh = wid & 1, nh = wid >> 1;

    const uint32_t smb = smem_u32(sm);
    const uint32_t QHs = smb, QLs = smb + MQT_SZ;
    const uint32_t DST = smb + 2 * MQT_SZ;

    const char* qh_g = g_QH + ((size_t)qk * 32 + b) * 8192;
    const char* ql_g = g_QL + ((size_t)qk * 32 + b) * 8192;
    const char* dh_g = g_DH + ((size_t)dk * 32 + b) * 262144;
    const char* dl_g = g_DL + ((size_t)dk * 32 + b) * 262144;

    auto load_step = [&](int s, int step) {
        int dt = part * 4 + (step >> 1);
        int kh = step & 1;
        const uint32_t st = DST + s * MD_STG;
        #pragma unroll
        for (int i = 0; i < 2; i++) {
            int idx = tid + i * 256;
            int chl = idx >> 8, rem = idx & 255;
            int rr = rem >> 2, c = rem & 3;
            int ch = kh * 2 + chl;
            size_t go = ((size_t)ch * 1024 + (size_t)dt * 64 + rr) * 64 + c * 16;
            uint32_t doff = (uint32_t)chl * 5120 + (uint32_t)rr * 80 + c * 16;
            cp16(st + doff, dh_g + go);
            cp16(st + MD_HALF + doff, dl_g + go);
        }
        cp_commit();
    };

    #pragma unroll
    for (int i = 0; i < 2; i++) {
        int idx = tid + i * 256;
        int ch = idx >> 7, rem = idx & 127;
        int rr = rem >> 2, c = rem & 3;
        size_t go = ((size_t)ch * 32 + rr) * 64 + c * 16;
        uint32_t doff = (uint32_t)ch * (32 * S80) + (uint32_t)rr * S80 + c * 16;
        cp16(QHs + doff, qh_g + go);
        cp16(QLs + doff, ql_g + go);
    }
    load_step(0, 0);

    const int lg = lane >> 3, lj = lane & 7;
    const uint32_t a80 = (uint32_t)(lj + 8 * (lg & 1)) * S80 + (uint32_t)(lg >> 1) * 16;
    const uint32_t b80 = (uint32_t)(lj + 8 * (lg >> 1)) * S80 + (uint32_t)(lg & 1) * 16;
    const uint32_t qa_h = QHs + (uint32_t)(mh * 16) * S80 + a80;
    const uint32_t qa_l = QLs + (uint32_t)(mh * 16) * S80 + a80;

    uint64_t h2[10];
    float h0 = 0.f;
    const uint64_t zz = pk2(0.f, 0.f);
    #pragma unroll
    for (int j = 0; j < 10; j++) h2[j] = zz;
    const uint64_t cc = pk2(EXP_M1, EXP_M1);

    auto bin_sim = [&](float s) {
        float d1 = s - 1.0f;
        if (fabsf(d1) < 0.012f)
            h0 += __expf(-500000.f * d1 * d1);
        float d = s - 0.95f;
        float dh = d + 1.0f;
        float gl = __expf(-50.f * d * d);
        float gh = __expf(-50.f * dh * dh);
        float tl = __expf(-10.f * d) * EXP_M05;
        float th = tl * EXP_M10;
        uint64_t g2 = pk2(gl, gh), t2 = pk2(tl, th);
        #pragma unroll
        for (int j = 0; j < 10; j++) {
            ADD2(h2[j], h2[j], g2);
            MUL2(g2, g2, t2);
            MUL2(t2, t2, cc);
        }
    };

    float acc[2][4];

    for (int step = 0; step < 8; step++) {
        const int s = step & 1;
        if (step + 1 < 8) { load_step(s ^ 1, step + 1); cp_wait<1>(); }
        else              { cp_wait<0>(); }
        __syncthreads();

        const int kh = step & 1;
        if (kh == 0) {
            #pragma unroll
            for (int t = 0; t < 2; t++)
                #pragma unroll
                for (int k = 0; k < 4; k++) acc[t][k] = 0.f;
        }

        const uint32_t Dh = DST + s * MD_STG + (uint32_t)(nh * 16) * S80 + b80;
        const uint32_t Dl = Dh + MD_HALF;

        #pragma unroll
        for (int kcl = 0; kcl < 2; kcl++) {
            const int kc = kh * 2 + kcl;
            #pragma unroll
            for (int ks = 0; ks < 2; ks++) {
                uint32_t ah[4], al[4], bh[4], bl[4];
                ldmx4(ah, qa_h + kc * 2560 + ks * 32);
                ldmx4(al, qa_l + kc * 2560 + ks * 32);
                ldmx4(bh, Dh + kcl * 5120 + ks * 32);
                ldmx4(bl, Dl + kcl * 5120 + ks * 32);
                mma_f16(acc[0], ah, bh);  mma_f16(acc[1], ah, bh + 2);
                mma_f16(acc[0], al, bh);  mma_f16(acc[1], al, bh + 2);
                mma_f16(acc[0], ah, bl);  mma_f16(acc[1], ah, bl + 2);
            }
        }

        if (kh == 1) {
            float a8[8] = { acc[0][0], acc[0][1], acc[1][0], acc[1][1],
                            acc[0][2], acc[0][3], acc[1][2], acc[1][3] };
            #pragma unroll
            for (int k = 0; k < 4; k++) {
                float send = (lane & 1) ? a8[k] : a8[k + 4];
                float got  = __shfl_xor_sync(0xffffffffu, send, 1);
                float own  = (lane & 1) ? a8[k + 4] : a8[k];
                bin_sim(own);
                bin_sim(got);
            }
        }
        __syncthreads();
    }

    float histf[21];
    histf[0] = h0;
    #pragma unroll
    for (int j = 0; j < 10; j++) {
        float a, bv;
        upk2(a, bv, h2[j]);
        histf[1 + j]  = a;
        histf[11 + j] = bv;
    }
    #pragma unroll
    for (int j = 0; j < 21; j++)
        histf[j] += __shfl_xor_sync(0xffffffffu, histf[j], 2);

    if ((lane & 2) == 0) {
        int row16 = (lane >> 2) + 8 * (lane & 1);
        #pragma unroll
        for (int j = 0; j < 21; j++)
            H[wid][row16][j] = histf[j];
    }
    __syncthreads();

    if (tid < 32) {
        int q = tid;
        int qmh = q >> 4, local = q & 15;
        float* dst = g_HISTP + ((((size_t)pair * 32 + b) * 4 + part) * 32 + q) * 21;
        #pragma unroll
        for (int j = 0; j < 21; j++) {
            float tot = 0.f;
            #pragma unroll
            for (int n = 0; n < 4; n++) tot += H[2 * n + qmh][local][j];
            dst[j] = tot;
        }
    }
}

// ---------------- 5) fused merge + score ----------------
__global__ void finish_kernel(const float* __restrict__ qmasks,
                              const float* __restrict__ dw, const float* __restrict__ db,
                              float* __restrict__ out, int out_size) {
    __shared__ float lg[192];
    __shared__ float red[256];
    const int b = blockIdx.x, t = threadIdx.x;

    if (t < 189) {
        int pair = t / 21, jj = t % 21;
        int qk = pair / 3, dk = pair % 3;
        float g0[21];
        bins_single(0.f, g0);
        float g0j = (float)dk * g0[jj];
        const float* base = g_HISTP + ((size_t)pair * 32 + b) * 4 * 32 * 21 + jj;
        float acc = 0.f;
        for (int q = 0; q < 32; q++) {
            float w = (q < QLEN - qk) ? qmasks[b * QLEN + q] : 0.f;
            const float* src = base + q * 21;
            float tot = src[0] + src[672] + src[1344] + src[2016] - g0j;
            acc += __logf(fmaxf(tot, 1e-10f)) * 0.01f * w;
        }
        lg[t] = acc;
    }
    __syncthreads();

    float v = (t < 189) ? lg[t] * dw[t] : 0.f;
    red[t] = v;
    __syncthreads();
    for (int s = 128; s > 0; s >>= 1) {
        if (t < s) red[t] += red[t + s];
        __syncthreads();
    }
    float score = red[0] + db[0];

    if (out_size >= B + B * 189) {
        if (t == 0) out[b] = score;
        if (t < 189) out[B + b * 189 + t] = lg[t];
    } else if (out_size == B * 189) {
        if (t < 189) out[b * 189 + t] = lg[t];
    } else {
        if (t == 0 && b < out_size) out[b] = score;
    }
}

// ---------------- launch ----------------
extern "C" void kernel_launch(void* const* d_in, const int* in_sizes, int n_in,
                              void* d_out, int out_size) {
    const int*   qids   = (const int*)d_in[0];
    const float* qmask  = (const float*)d_in[1];
    const int*   dids   = (const int*)d_in[2];
    const float* dmask  = (const float*)d_in[3];
    const float* emb    = (const float*)d_in[4];
    const float* w1     = (const float*)d_in[5];
    const float* b1     = (const float*)d_in[6];
    const float* w2     = (const float*)d_in[7];
    const float* b2     = (const float*)d_in[8];
    const float* w3     = (const float*)d_in[9];
    const float* b3     = (const float*)d_in[10];
    const float* dw     = (const float*)d_in[11];
    const float* db     = (const float*)d_in[12];
    float* out = (float*)d_out;

    cudaFuncSetAttribute(conv_mix_kernel, cudaFuncAttributeMaxDynamicSharedMemorySize, SMEM_DYN);
    cudaFuncSetAttribute(matcher_kernel, cudaFuncAttributeMaxDynamicSharedMemorySize, SMEM_M);

    prep_kernel<<<GATHER_BLOCKS + WCAT_BLOCKS, 256>>>(qids, dids, emb, w1, w2, w3);
    conv_mix_kernel<<<dim3(3, MTILES), 256, SMEM_DYN>>>();
    {
        int items = (MD + MQ) * 3;
        int warps = (items + 1) / 2;
        combine_kernel<<<(warps * 32 + 255) / 256, 256>>>(b1, b2, b3, qmask, dmask);
    }
    matcher_kernel<<<dim3(B, 9, 4), 256, SMEM_M>>>();
    finish_kernel<<<B, 256>>>(qmask, dw, db, out, out_size);
}

// round 16
// speedup vs baseline: 1.7439x; 1.0091x over previous
#include <cuda_runtime.h>
#include <cuda_bf16.h>
#include <cuda_fp16.h>
#include <cstdint>

#define B      32
#define QLEN   32
#define DLEN   1024
#define EMB    300
#define CDIM   128
#define MD     (B*DLEN)
#define MQ     (B*QLEN)

#define QROW0   32896
#define NROWS   33924
#define KPAD    320
#define NCAT    768
#define MTILES  264

// ---------------- device scratch (zero-initialized) ----------------
__device__ __half g_Eh[(size_t)NROWS * KPAD];
__device__ __half g_El[(size_t)NROWS * KPAD];
__device__ __half g_Wh[NCAT * KPAD];
__device__ __half g_Wl[NCAT * KPAD];
__device__ float g_P[(size_t)NROWS * NCAT];
__device__ char g_DH[3ull * 32 * 4 * 1024 * 64];
__device__ char g_DL[3ull * 32 * 4 * 1024 * 64];
__device__ char g_QH[3ull * 32 * 4 * 32 * 64];
__device__ char g_QL[3ull * 32 * 4 * 32 * 64];
__device__ float g_HISTP[9ull * 32 * 4 * 32 * 21];

__device__ __forceinline__ uint32_t smem_u32(const void* p) {
    uint32_t a;
    asm("{ .reg .u64 t; cvta.to.shared.u64 t, %1; cvt.u32.u64 %0, t; }" : "=r"(a) : "l"(p));
    return a;
}
__device__ __forceinline__ void ldmx4(uint32_t* r, uint32_t addr) {
    asm volatile("ldmatrix.sync.aligned.m8n8.x4.shared.b16 {%0,%1,%2,%3}, [%4];"
                 : "=r"(r[0]), "=r"(r[1]), "=r"(r[2]), "=r"(r[3]) : "r"(addr));
}
__device__ __forceinline__ void mma_f16(float* c, const uint32_t* a, const uint32_t* b) {
    asm volatile("mma.sync.aligned.m16n8k16.row.col.f32.f16.f16.f32 "
                 "{%0,%1,%2,%3}, {%4,%5,%6,%7}, {%8,%9}, {%0,%1,%2,%3};"
                 : "+f"(c[0]), "+f"(c[1]), "+f"(c[2]), "+f"(c[3])
                 : "r"(a[0]), "r"(a[1]), "r"(a[2]), "r"(a[3]), "r"(b[0]), "r"(b[1]));
}
__device__ __forceinline__ void cp16(uint32_t dst, const void* src) {
    asm volatile("cp.async.cg.shared.global [%0], [%1], 16;" :: "r"(dst), "l"(src));
}
__device__ __forceinline__ void cp_commit() {
    asm volatile("cp.async.commit_group;" ::: "memory");
}
template <int N>
__device__ __forceinline__ void cp_wait() {
    asm volatile("cp.async.wait_group %0;" :: "n"(N) : "memory");
}

// ---- packed f32x2 helpers ----
__device__ __forceinline__ uint64_t pk2(float x, float y) {
    uint64_t r;
    asm("mov.b64 %0, {%1, %2};" : "=l"(r) : "f"(x), "f"(y));
    return r;
}
__device__ __forceinline__ void upk2(float& x, float& y, uint64_t v) {
    asm("mov.b64 {%0, %1}, %2;" : "=f"(x), "=f"(y) : "l"(v));
}
#define MUL2(o, a, b) asm("mul.rn.f32x2 %0, %1, %2;" : "=l"(o) : "l"(a), "l"(b))
#define ADD2(o, a, b) asm("add.rn.f32x2 %0, %1, %2;" : "=l"(o) : "l"(a), "l"(b))

#define EXP_M10   4.5399929762e-05f
#define EXP_M05   0.60653065971f
#define EXP_M1    0.36787944117f

// ---------------- 1) fused gather + wcat ----------------
#define GATHER_BLOCKS  (((MD + MQ) * 32) / 256)
#define WCAT_ELEMS     (NCAT * KPAD)
#define WCAT_BLOCKS    (WCAT_ELEMS / 256)

__global__ void prep_kernel(const int* __restrict__ qids, const int* __restrict__ dids,
                            const float* __restrict__ emb,
                            const float* __restrict__ w1, const float* __restrict__ w2,
                            const float* __restrict__ w3) {
    if (blockIdx.x < GATHER_BLOCKS) {
        int w = (blockIdx.x * blockDim.x + threadIdx.x) >> 5;
        int lane = threadIdx.x & 31;
        if (w >= MD + MQ) return;
        int id, drow;
        if (w < MD) { id = dids[w]; drow = w; }
        else        { id = qids[w - MD]; drow = QROW0 + (w - MD); }
        const float* src = emb + (size_t)id * EMB;
        __half* dh = g_Eh + (size_t)drow * KPAD;
        __half* dl = g_El + (size_t)drow * KPAD;
        #pragma unroll
        for (int i = 0; i < 10; i++) {
            int c = lane + i * 32;
            float x = (c < EMB) ? src[c] : 0.f;
            __half h = __float2half(x);
            dh[c] = h;
            dl[c] = __float2half(x - __half2float(h));
        }
    } else {
        int idx = (blockIdx.x - GATHER_BLOCKS) * 256 + threadIdx.x;
        if (idx >= WCAT_ELEMS) return;
        int j = idx / KPAD, e = idx % KPAD;
        int g = j >> 7, c = j & 127;
        float v = 0.f;
        if (e < EMB) {
            if (g == 0)      v = w1[c * EMB + e];
            else if (g == 1) v = w2[(c * EMB + e) * 2 + 0];
            else if (g == 2) v = w2[(c * EMB + e) * 2 + 1];
            else             v = w3[(c * EMB + e) * 3 + (g - 3)];
        }
        __half h = __float2half(v);
        g_Wh[idx] = h;
        g_Wl[idx] = __float2half(v - __half2float(h));
    }
}

// ---------------- 2) conv GEMM: peeled tail (K 304-320 zero padding skipped) ----------------
#define S80   80
#define AH_OFF  0
#define AL_OFF  10240
#define BH_OFF  20480
#define BL_OFF  40960
#define STAGE_B 61440
#define SMEM_DYN (3 * STAGE_B)

__global__ void __launch_bounds__(256, 1) conv_mix_kernel() {
    extern __shared__ char sm[];
    const int mt = blockIdx.y, pass = blockIdx.x;
    const int mbase = (mt < 256) ? mt * 128 : QROW0 + (mt - 256) * 128;
    const int jbase = pass * 256;
    const int tid = threadIdx.x, wid = tid >> 5, lane = tid & 31;
    const int wm = wid & 1, wn = wid >> 1;

    const uint32_t smb = smem_u32(sm);
    const char* Ah_src = (const char*)(g_Eh + (size_t)mbase * KPAD);
    const char* Al_src = (const char*)(g_El + (size_t)mbase * KPAD);
    const char* Bh_src = (const char*)(g_Wh + (size_t)jbase * KPAD);
    const char* Bl_src = (const char*)(g_Wl + (size_t)jbase * KPAD);

    auto load_stage = [&](int s, int kc) {
        const uint32_t st = smb + s * STAGE_B;
        const int kof = kc * 64;
        #pragma unroll
        for (int i = 0; i < 2; i++) {
            int idx = tid + i * 256;
            int r = idx >> 2, c = idx & 3;
            uint32_t doff = (uint32_t)r * S80 + c * 16;
            size_t so = (size_t)r * 640 + kof + c * 16;
            cp16(st + AH_OFF + doff, Ah_src + so);
            cp16(st + AL_OFF + doff, Al_src + so);
        }
        #pragma unroll
        for (int i = 0; i < 4; i++) {
            int idx = tid + i * 256;
            int r = idx >> 2, c = idx & 3;
            uint32_t doff = (uint32_t)r * S80 + c * 16;
            size_t so = (size_t)r * 640 + kof + c * 16;
            cp16(st + BH_OFF + doff, Bh_src + so);
            cp16(st + BL_OFF + doff, Bl_src + so);
        }
        cp_commit();
    };

    float acc[4][8][4];
    #pragma unroll
    for (int i = 0; i < 4; i++)
        #pragma unroll
        for (int j = 0; j < 8; j++)
            #pragma unroll
            for (int k = 0; k < 4; k++) acc[i][j][k] = 0.f;

    const int lg = lane >> 3, lj = lane & 7;
    const uint32_t a80 = (uint32_t)(lj + 8 * (lg & 1)) * S80 + (uint32_t)(lg >> 1) * 16;
    const uint32_t b80 = (uint32_t)(lj + 8 * (lg >> 1)) * S80 + (uint32_t)(lg & 1) * 16;

    // one k16 step at smem stage s, k-offset kb bytes
    auto do_step = [&](uint32_t stg, uint32_t kb) {
        const uint32_t AHs = smb + stg * STAGE_B + AH_OFF;
        const uint32_t ALs = smb + stg * STAGE_B + AL_OFF;
        const uint32_t BHs = smb + stg * STAGE_B + BH_OFF;
        const uint32_t BLs = smb + stg * STAGE_B + BL_OFF;
        uint32_t bh[8][2], bl[8][2];
        #pragma unroll
        for (int h = 0; h < 4; h++) {
            uint32_t off = (uint32_t)(wn * 64 + h * 16) * S80 + kb + b80;
            uint32_t r[4];
            ldmx4(r, BHs + off);
            bh[h * 2 + 0][0] = r[0]; bh[h * 2 + 0][1] = r[1];
            bh[h * 2 + 1][0] = r[2]; bh[h * 2 + 1][1] = r[3];
            ldmx4(r, BLs + off);
            bl[h * 2 + 0][0] = r[0]; bl[h * 2 + 0][1] = r[1];
            bl[h * 2 + 1][0] = r[2]; bl[h * 2 + 1][1] = r[3];
        }
        #pragma unroll
        for (int mf = 0; mf < 4; mf++) {
            uint32_t off = (uint32_t)(wm * 64 + mf * 16) * S80 + kb + a80;
            uint32_t ah[4];
            ldmx4(ah, AHs + off);
            #pragma unroll
            for (int nf = 0; nf < 8; nf++) {
                mma_f16(acc[mf][nf], ah, bh[nf]);
                mma_f16(acc[mf][nf], ah, bl[nf]);
            }
        }
        #pragma unroll
        for (int mf = 0; mf < 4; mf++) {
            uint32_t off = (uint32_t)(wm * 64 + mf * 16) * S80 + kb + a80;
            uint32_t al[4];
            ldmx4(al, ALs + off);
            #pragma unroll
            for (int nf = 0; nf < 8; nf++) mma_f16(acc[mf][nf], al, bh[nf]);
        }
    };

    load_stage(0, 0);
    load_stage(1, 1);

    // kc = 0..7: steady state with prefetch
    for (int kc = 0; kc < 8; kc++) {
        const int s = kc % 3;
        load_stage((kc + 2) % 3, kc + 2);
        cp_wait<2>();
        __syncthreads();
        do_step(s, 0);
        do_step(s, 32);
        __syncthreads();
    }
    // kc = 8: no prefetch
    {
        cp_wait<1>();
        __syncthreads();
        do_step(8 % 3, 0);
        do_step(8 % 3, 32);
        __syncthreads();
    }
    // kc = 9: only first k16 step (K 304-320 is zero padding)
    {
        cp_wait<0>();
        __syncthreads();
        do_step(9 % 3, 0);
    }

    const int r0 = lane >> 2, c0 = (lane & 3) * 2;
    #pragma unroll
    for (int mf = 0; mf < 4; mf++) {
        int row = mbase + wm * 64 + mf * 16 + r0;
        #pragma unroll
        for (int nf = 0; nf < 8; nf++) {
            int col = jbase + wn * 64 + nf * 8 + c0;
            float* p = g_P + (size_t)row * NCAT + col;
            *(float2*)p                      = make_float2(acc[mf][nf][0], acc[mf][nf][1]);
            *(float2*)(p + (size_t)8 * NCAT) = make_float2(acc[mf][nf][2], acc[mf][nf][3]);
        }
    }
}

// ---------------- 3) combine: 2 items per warp ----------------
__global__ void combine_kernel(const float* __restrict__ b1, const float* __restrict__ b2,
                               const float* __restrict__ b3,
                               const float* __restrict__ qmask, const float* __restrict__ dmask) {
    const int w0 = (((blockIdx.x * blockDim.x + threadIdx.x) >> 5) << 1);
    const int lane = threadIdx.x & 31;
    #pragma unroll
    for (int u = 0; u < 2; u++) {
        int w = w0 + u;
        if (w >= (MD + MQ) * 3) break;
        int kidx = w % 3;
        int row  = w / 3;
        int prow, bb, pos, is_q;
        float mk;
        if (row < MD) { is_q = 0; prow = row; bb = row / DLEN; pos = row % DLEN; mk = dmask[row]; }
        else {
            is_q = 1;
            int q = row - MD;
            prow = QROW0 + q; bb = q / QLEN; pos = q % QLEN; mk = qmask[q];
        }
        const int len = is_q ? QLEN : DLEN;
        const float* bias = (kidx == 0) ? b1 : (kidx == 1 ? b2 : b3);
        const float* P0 = g_P + (size_t)prow * NCAT;
        int c = lane * 4;
        float4 v;
        if (kidx == 0) {
            v = *(const float4*)(P0 + c);
        } else if (kidx == 1) {
            float4 a = *(const float4*)(P0 + 128 + c);
            float4 b = *(const float4*)(P0 + NCAT + 256 + c);
            v = make_float4(a.x + b.x, a.y + b.y, a.z + b.z, a.w + b.w);
        } else {
            float4 a = *(const float4*)(P0 + 384 + c);
            float4 b = *(const float4*)(P0 + NCAT + 512 + c);
            float4 d = *(const float4*)(P0 + 2 * NCAT + 640 + c);
            v = make_float4(a.x + b.x + d.x, a.y + b.y + d.y, a.z + b.z + d.z, a.w + b.w + d.w);
        }
        float4 bv = *(const float4*)(bias + c);
        v.x = fmaxf(v.x + bv.x, 0.f);  v.y = fmaxf(v.y + bv.y, 0.f);
        v.z = fmaxf(v.z + bv.z, 0.f);  v.w = fmaxf(v.w + bv.w, 0.f);
        float ss = v.x * v.x + v.y * v.y + v.z * v.z + v.w * v.w;
        #pragma unroll
        for (int off = 16; off > 0; off >>= 1)
            ss += __shfl_xor_sync(0xffffffffu, ss, off);
        float sc = mk / (sqrtf(ss) + 1e-13f);
        if (pos >= len - kidx) sc = 0.f;
        v.x *= sc; v.y *= sc; v.z *= sc; v.w *= sc;

        float vv[4] = {v.x, v.y, v.z, v.w};
        __half h4[4], l4[4];
        #pragma unroll
        for (int i = 0; i < 4; i++) {
            h4[i] = __float2half(vv[i]);
            l4[i] = __float2half(vv[i] - __half2float(h4[i]));
        }

        int ch = lane >> 3, e8 = lane & 7;
        if (!is_q) {
            size_t blk = (((size_t)kidx * 32 + bb) * 4 + ch) * 1024 + pos;
            *(uint2*)(g_DH + blk * 64 + e8 * 8) = *(const uint2*)h4;
            *(uint2*)(g_DL + blk * 64 + e8 * 8) = *(const uint2*)l4;
        } else {
            size_t blk = (((size_t)kidx * 32 + bb) * 4 + ch) * 32 + pos;
            *(uint2*)(g_QH + blk * 64 + e8 * 8) = *(const uint2*)h4;
            *(uint2*)(g_QL + blk * 64 + e8 * 8) = *(const uint2*)l4;
        }
    }
}

// ---------------- 4) tensor matcher (2-way interleaved binning) ----------------
__device__ __forceinline__ void bins_single(float s, float* out21) {
    float d1 = s - 1.0f;
    out21[0] = (fabsf(d1) < 0.012f) ? __expf(-500000.f * d1 * d1) : 0.f;
    float d = s - 0.95f;
    float dh = d + 1.0f;
    float gl = __expf(-50.f * d * d);
    float gh = __expf(-50.f * dh * dh);
    float tl = __expf(-10.f * d) * EXP_M05;
    float th = tl * EXP_M10;
    uint64_t g2 = pk2(gl, gh), t2 = pk2(tl, th);
    const uint64_t cc = pk2(EXP_M1, EXP_M1);
    #pragma unroll
    for (int j = 0; j < 10; j++) {
        float a, b;
        upk2(a, b, g2);
        out21[1 + j]  = a;
        out21[11 + j] = b;
        MUL2(g2, g2, t2);
        MUL2(t2, t2, cc);
    }
}

#define MQT_SZ   10240
#define MD_HALF  10240
#define MD_STG   (2 * MD_HALF)
#define SMEM_M   (2 * MQT_SZ + 2 * MD_STG)   // 61440

__global__ void __launch_bounds__(256, 3) matcher_kernel() {
    extern __shared__ char sm[];
    __shared__ float H[8][16][21];

    const int b    = blockIdx.x;
    const int pair = blockIdx.y;
    const int part = blockIdx.z;
    const int qk   = pair / 3, dk = pair % 3;
    const int tid = threadIdx.x, wid = tid >> 5, lane = tid & 31;
    const int mh = wid & 1, nh = wid >> 1;

    const uint32_t smb = smem_u32(sm);
    const uint32_t QHs = smb, QLs = smb + MQT_SZ;
    const uint32_t DST = smb + 2 * MQT_SZ;

    const char* qh_g = g_QH + ((size_t)qk * 32 + b) * 8192;
    const char* ql_g = g_QL + ((size_t)qk * 32 + b) * 8192;
    const char* dh_g = g_DH + ((size_t)dk * 32 + b) * 262144;
    const char* dl_g = g_DL + ((size_t)dk * 32 + b) * 262144;

    auto load_step = [&](int s, int step) {
        int dt = part * 4 + (step >> 1);
        int kh = step & 1;
        const uint32_t st = DST + s * MD_STG;
        #pragma unroll
        for (int i = 0; i < 2; i++) {
            int idx = tid + i * 256;
            int chl = idx >> 8, rem = idx & 255;
            int rr = rem >> 2, c = rem & 3;
            int ch = kh * 2 + chl;
            size_t go = ((size_t)ch * 1024 + (size_t)dt * 64 + rr) * 64 + c * 16;
            uint32_t doff = (uint32_t)chl * 5120 + (uint32_t)rr * 80 + c * 16;
            cp16(st + doff, dh_g + go);
            cp16(st + MD_HALF + doff, dl_g + go);
        }
        cp_commit();
    };

    #pragma unroll
    for (int i = 0; i < 2; i++) {
        int idx = tid + i * 256;
        int ch = idx >> 7, rem = idx & 127;
        int rr = rem >> 2, c = rem & 3;
        size_t go = ((size_t)ch * 32 + rr) * 64 + c * 16;
        uint32_t doff = (uint32_t)ch * (32 * S80) + (uint32_t)rr * S80 + c * 16;
        cp16(QHs + doff, qh_g + go);
        cp16(QLs + doff, ql_g + go);
    }
    load_step(0, 0);

    const int lg = lane >> 3, lj = lane & 7;
    const uint32_t a80 = (uint32_t)(lj + 8 * (lg & 1)) * S80 + (uint32_t)(lg >> 1) * 16;
    const uint32_t b80 = (uint32_t)(lj + 8 * (lg >> 1)) * S80 + (uint32_t)(lg & 1) * 16;
    const uint32_t qa_h = QHs + (uint32_t)(mh * 16) * S80 + a80;
    const uint32_t qa_l = QLs + (uint32_t)(mh * 16) * S80 + a80;

    uint64_t h2[10];
    float h0 = 0.f;
    const uint64_t zz = pk2(0.f, 0.f);
    #pragma unroll
    for (int j = 0; j < 10; j++) h2[j] = zz;
    const uint64_t cc = pk2(EXP_M1, EXP_M1);

    // two independent sims binned with interleaved chains (2x ILP on serial recurrence)
    auto bin_sim2 = [&](float sa, float sb) {
        float d1a = sa - 1.0f, d1b = sb - 1.0f;
        if (fabsf(d1a) < 0.012f) h0 += __expf(-500000.f * d1a * d1a);
        if (fabsf(d1b) < 0.012f) h0 += __expf(-500000.f * d1b * d1b);
        float da = sa - 0.95f, db = sb - 0.95f;
        float dha = da + 1.0f, dhb = db + 1.0f;
        float gla = __expf(-50.f * da * da),  glb = __expf(-50.f * db * db);
        float gha = __expf(-50.f * dha * dha), ghb = __expf(-50.f * dhb * dhb);
        float tla = __expf(-10.f * da) * EXP_M05, tlb = __expf(-10.f * db) * EXP_M05;
        uint64_t ga = pk2(gla, gha), ta = pk2(tla, tla * EXP_M10);
        uint64_t gb = pk2(glb, ghb), tb = pk2(tlb, tlb * EXP_M10);
        #pragma unroll
        for (int j = 0; j < 10; j++) {
            uint64_t gs;
            ADD2(gs, ga, gb);
            ADD2(h2[j], h2[j], gs);
            MUL2(ga, ga, ta);
            MUL2(gb, gb, tb);
            MUL2(ta, ta, cc);
            MUL2(tb, tb, cc);
        }
    };

    float acc[2][4];

    for (int step = 0; step < 8; step++) {
        const int s = step & 1;
        if (step + 1 < 8) { load_step(s ^ 1, step + 1); cp_wait<1>(); }
        else              { cp_wait<0>(); }
        __syncthreads();

        const int kh = step & 1;
        if (kh == 0) {
            #pragma unroll
            for (int t = 0; t < 2; t++)
                #pragma unroll
                for (int k = 0; k < 4; k++) acc[t][k] = 0.f;
        }

        const uint32_t Dh = DST + s * MD_STG + (uint32_t)(nh * 16) * S80 + b80;
        const uint32_t Dl = Dh + MD_HALF;

        #pragma unroll
        for (int kcl = 0; kcl < 2; kcl++) {
            const int kc = kh * 2 + kcl;
            #pragma unroll
            for (int ks = 0; ks < 2; ks++) {
                uint32_t ah[4], al[4], bh[4], bl[4];
                ldmx4(ah, qa_h + kc * 2560 + ks * 32);
                ldmx4(al, qa_l + kc * 2560 + ks * 32);
                ldmx4(bh, Dh + kcl * 5120 + ks * 32);
                ldmx4(bl, Dl + kcl * 5120 + ks * 32);
                mma_f16(acc[0], ah, bh);  mma_f16(acc[1], ah, bh + 2);
                mma_f16(acc[0], al, bh);  mma_f16(acc[1], al, bh + 2);
                mma_f16(acc[0], ah, bl);  mma_f16(acc[1], ah, bl + 2);
            }
        }

        if (kh == 1) {
            float a8[8] = { acc[0][0], acc[0][1], acc[1][0], acc[1][1],
                            acc[0][2], acc[0][3], acc[1][2], acc[1][3] };
            #pragma unroll
            for (int k = 0; k < 4; k++) {
                float send = (lane & 1) ? a8[k] : a8[k + 4];
                float got  = __shfl_xor_sync(0xffffffffu, send, 1);
                float own  = (lane & 1) ? a8[k + 4] : a8[k];
                bin_sim2(own, got);
            }
        }
        __syncthreads();
    }

    float histf[21];
    histf[0] = h0;
    #pragma unroll
    for (int j = 0; j < 10; j++) {
        float a, bv;
        upk2(a, bv, h2[j]);
        histf[1 + j]  = a;
        histf[11 + j] = bv;
    }
    #pragma unroll
    for (int j = 0; j < 21; j++)
        histf[j] += __shfl_xor_sync(0xffffffffu, histf[j], 2);

    if ((lane & 2) == 0) {
        int row16 = (lane >> 2) + 8 * (lane & 1);
        #pragma unroll
        for (int j = 0; j < 21; j++)
            H[wid][row16][j] = histf[j];
    }
    __syncthreads();

    if (tid < 32) {
        int q = tid;
        int qmh = q >> 4, local = q & 15;
        float* dst = g_HISTP + ((((size_t)pair * 32 + b) * 4 + part) * 32 + q) * 21;
        #pragma unroll
        for (int j = 0; j < 21; j++) {
            float tot = 0.f;
            #pragma unroll
            for (int n = 0; n < 4; n++) tot += H[2 * n + qmh][local][j];
            dst[j] = tot;
        }
    }
}

// ---------------- 5) fused merge + score ----------------
__global__ void finish_kernel(const float* __restrict__ qmasks,
                              const float* __restrict__ dw, const float* __restrict__ db,
                              float* __restrict__ out, int out_size) {
    __shared__ float lg[192];
    __shared__ float red[256];
    const int b = blockIdx.x, t = threadIdx.x;

    if (t < 189) {
        int pair = t / 21, jj = t % 21;
        int qk = pair / 3, dk = pair % 3;
        float g0[21];
        bins_single(0.f, g0);
        float g0j = (float)dk * g0[jj];
        const float* base = g_HISTP + ((size_t)pair * 32 + b) * 4 * 32 * 21 + jj;
        float acc = 0.f;
        for (int q = 0; q < 32; q++) {
            float w = (q < QLEN - qk) ? qmasks[b * QLEN + q] : 0.f;
            const float* src = base + q * 21;
            float tot = src[0] + src[672] + src[1344] + src[2016] - g0j;
            acc += __logf(fmaxf(tot, 1e-10f)) * 0.01f * w;
        }
        lg[t] = acc;
    }
    __syncthreads();

    float v = (t < 189) ? lg[t] * dw[t] : 0.f;
    red[t] = v;
    __syncthreads();
    for (int s = 128; s > 0; s >>= 1) {
        if (t < s) red[t] += red[t + s];
        __syncthreads();
    }
    float score = red[0] + db[0];

    if (out_size >= B + B * 189) {
        if (t == 0) out[b] = score;
        if (t < 189) out[B + b * 189 + t] = lg[t];
    } else if (out_size == B * 189) {
        if (t < 189) out[b * 189 + t] = lg[t];
    } else {
        if (t == 0 && b < out_size) out[b] = score;
    }
}

// ---------------- launch ----------------
extern "C" void kernel_launch(void* const* d_in, const int* in_sizes, int n_in,
                              void* d_out, int out_size) {
    const int*   qids   = (const int*)d_in[0];
    const float* qmask  = (const float*)d_in[1];
    const int*   dids   = (const int*)d_in[2];
    const float* dmask  = (const float*)d_in[3];
    const float* emb    = (const float*)d_in[4];
    const float* w1     = (const float*)d_in[5];
    const float* b1     = (const float*)d_in[6];
    const float* w2     = (const float*)d_in[7];
    const float* b2     = (const float*)d_in[8];
    const float* w3     = (const float*)d_in[9];
    const float* b3     = (const float*)d_in[10];
    const float* dw     = (const float*)d_in[11];
    const float* db     = (const float*)d_in[12];
    float* out = (float*)d_out;

    cudaFuncSetAttribute(conv_mix_kernel, cudaFuncAttributeMaxDynamicSharedMemorySize, SMEM_DYN);
    cudaFuncSetAttribute(matcher_kernel, cudaFuncAttributeMaxDynamicSharedMemorySize, SMEM_M);

    prep_kernel<<<GATHER_BLOCKS + WCAT_BLOCKS, 256>>>(qids, dids, emb, w1, w2, w3);
    conv_mix_kernel<<<dim3(3, MTILES), 256, SMEM_DYN>>>();
    {
        int items = (MD + MQ) * 3;
        int warps = (items + 1) / 2;
        combine_kernel<<<(warps * 32 + 255) / 256, 256>>>(b1, b2, b3, qmask, dmask);
    }
    matcher_kernel<<<dim3(B, 9, 4), 256, SMEM_M>>>();
    finish_kernel<<<B, 256>>>(qmask, dw, db, out, out_size);
}